// round 11
// baseline (speedup 1.0000x reference)
#include <cuda_runtime.h>

typedef unsigned long long u64;

#define Qn   64
#define LQ   20
#define DSET 12
#define DTn  24
#define LD   50
#define Hn   256
#define G3   768
#define HSTR 260
#define NB_DOC 52
#define NB_TRM 40
#define NBLK 144
#define NTHR 512

// ---------------- device scratch ----------------
__device__ float g_gi_q[LQ * Qn * G3];
__device__ float g_gi_c[LD * DTn * G3];
__device__ float g_gi_a[LD * DTn * G3];
__device__ float4 g_wt_c[64 * G3];     // k-major Wih
__device__ float4 g_wt_a[64 * G3];
__device__ float4 g_wt_q[64 * G3];
__device__ float4 g_wthh_c[64 * G3];   // k-major Whh (uniform-LDG weights for recurrence)
__device__ float4 g_wthh_a[64 * G3];
__device__ float4 g_wthh_q[64 * G3];
__device__ float g_hq[2][Qn * Hn];
__device__ float g_hc[2][DTn * Hn];
__device__ float g_ha[2][DTn * Hn];
__device__ float g_attc[DTn * Hn];
__device__ float g_scores[Qn * DTn];
__device__ unsigned g_f_p0c[NB_DOC * 32];
__device__ unsigned g_f_p0a[NB_DOC * 32];
__device__ unsigned g_f_p0t[NB_TRM * 32];
__device__ unsigned g_f_rc[32 * 32];
__device__ unsigned g_f_ra[32 * 32];
__device__ unsigned g_f_rt[32 * 32];
__device__ unsigned g_f_all[NBLK * 32];

// ---------------- helpers ----------------
__device__ __forceinline__ float sigm(float x) { return 1.0f / (1.0f + __expf(-x)); }
__device__ __forceinline__ u64 pk(float lo, float hi) {
    u64 r; asm("mov.b64 %0, {%1,%2};" : "=l"(r) : "f"(lo), "f"(hi)); return r;
}
__device__ __forceinline__ float uns(u64 v) {
    float lo, hi; asm("mov.b64 {%0,%1}, %2;" : "=f"(lo), "=f"(hi) : "l"(v));
    return lo + hi;
}
__device__ __forceinline__ void ffma2(u64& d, u64 a, u64 b) {
    asm("fma.rn.f32x2 %0, %1, %2, %0;" : "+l"(d) : "l"(a), "l"(b));
}
__device__ __forceinline__ unsigned sptr(const void* p) {
    return (unsigned)__cvta_generic_to_shared(p);
}
__device__ __forceinline__ void lds2(u64& a, u64& b, unsigned addr) {
    asm volatile("ld.shared.v2.u64 {%0,%1}, [%2];" : "=l"(a), "=l"(b) : "r"(addr));
}
__device__ __forceinline__ void ldg2(u64& a, u64& b, const float* p) {
    asm volatile("ld.global.nc.v2.u64 {%0,%1}, [%2];" : "=l"(a), "=l"(b) : "l"(p));
}
__device__ __forceinline__ void barh(int h) {
    asm volatile("bar.sync %0, %1;" :: "r"(1 + h), "r"(256) : "memory");
}

// ---- flag barrier ----
__device__ __forceinline__ void bar_arrive(unsigned* fl, int idx, unsigned gen) {
    __syncthreads();
    if (threadIdx.x == 0)
        asm volatile("st.release.gpu.global.u32 [%0], %1;"
                     :: "l"(fl + idx * 32), "r"(gen) : "memory");
}
__device__ __forceinline__ void bar_wait(unsigned* fl, int n, unsigned gen) {
    if (threadIdx.x < (unsigned)n) {
        unsigned cur;
        do {
            asm volatile("ld.acquire.gpu.global.u32 %0, [%1];"
                         : "=r"(cur) : "l"(fl + threadIdx.x * 32) : "memory");
        } while (cur < gen);
    }
    __syncthreads();
}
__device__ __forceinline__ unsigned rd_base(unsigned* fl, int idx) {
    return *(volatile unsigned*)(fl + idx * 32);
}

// ---------------- W transpose: W[768][256] -> Wt[64][768] float4 ----------------
__device__ void transpose_w(int gid, const float* __restrict__ W, float4* __restrict__ Wt,
                            float* sbuf)
{
    int tid = threadIdx.x;
    int r0 = gid * 24;
    for (int i = tid; i < 24 * 256; i += NTHR) {
        int rl = i >> 8, j = i & 255;
        sbuf[rl * 260 + j] = __ldg(W + (size_t)(r0 + rl) * Hn + j);
    }
    __syncthreads();
    for (int i = tid; i < 24 * 64; i += NTHR) {
        int rl = i % 24, kk = i / 24;
        float4 v = *(float4*)(sbuf + rl * 260 + (kk << 2));
        Wt[kk * G3 + r0 + rl] = v;
    }
    __syncthreads();
}

// ---------------- phase 0 (one 256-thread half = one virtual block) ----------------
__device__ void phase0_gemm(int vgid, int nv, int half, int R, int mode,
                            const int* __restrict__ tokA, const int* __restrict__ tokB,
                            const float* __restrict__ emb, const float4* __restrict__ Wt,
                            const float* __restrict__ bias, float* __restrict__ gi,
                            float* xs)
{
    int th = threadIdx.x & 255;
    int rpb = (R + nv - 1) / nv;
    int r0 = vgid * rpb;
    int r1 = min(R, r0 + rpb);
    unsigned xsa = sptr(xs);
    float b0 = __ldg(bias + th), b1 = __ldg(bias + th + 256), b2 = __ldg(bias + th + 512);

    for (int rt = r0; rt < r1; rt += 8) {
        int nr = min(8, r1 - rt);
        barh(half);
        for (int idx = th; idx < (nr << 8); idx += 256) {
            int rl = idx >> 8, j = idx & 255;
            int r = rt + rl;
            int tok;
            if (mode == 0) {
                int t = r >> 6, q = r & 63;
                tok = tokA[q * LQ + t];
            } else {
                int t = r / DTn, dt = r - t * DTn;
                tok = (dt < DSET) ? tokA[dt * LD + t] : tokB[(dt - DSET) * LD + t];
            }
            xs[(rl << 8) + j] = __ldg(emb + (size_t)tok * Hn + j);
        }
        barh(half);

        u64 acc[3][8];
        #pragma unroll
        for (int rl = 0; rl < 8; rl++) {
            acc[0][rl] = pk(b0, 0.0f);
            acc[1][rl] = pk(b1, 0.0f);
            acc[2][rl] = pk(b2, 0.0f);
        }
        #pragma unroll 2
        for (int jj = 0; jj < 64; jj++) {
            const float* wp = (const float*)(Wt + jj * G3 + th);
            u64 w0a, w0b, w1a, w1b, w2a, w2b;
            ldg2(w0a, w0b, wp);
            ldg2(w1a, w1b, wp + 1024);
            ldg2(w2a, w2b, wp + 2048);
            unsigned xo = xsa + (jj << 4);
            #pragma unroll
            for (int rlb = 0; rlb < 2; rlb++) {
                u64 x01[4], x23[4];
                #pragma unroll
                for (int rl = 0; rl < 4; rl++)
                    lds2(x01[rl], x23[rl], xo + ((rlb * 4 + rl) << 10));
                #pragma unroll
                for (int rl = 0; rl < 4; rl++) {
                    int ri = rlb * 4 + rl;
                    ffma2(acc[0][ri], w0a, x01[rl]); ffma2(acc[0][ri], w0b, x23[rl]);
                    ffma2(acc[1][ri], w1a, x01[rl]); ffma2(acc[1][ri], w1b, x23[rl]);
                    ffma2(acc[2][ri], w2a, x01[rl]); ffma2(acc[2][ri], w2b, x23[rl]);
                }
            }
        }
        for (int rl = 0; rl < nr; rl++) {
            float* gr = gi + (size_t)(rt + rl) * G3 + th;
            gr[0]   = uns(acc[0][rl]);
            gr[256] = uns(acc[1][rl]);
            gr[512] = uns(acc[2][rl]);
        }
    }
}

// ---------------- doc recurrence: 16 warps, k-quarter split, uniform-LDG weights ----------------
__device__ void run_doc(int cb, const float4* __restrict__ wthh, const float* __restrict__ bhh,
                        const float* __restrict__ gi, float* hb0, float* hb1,
                        unsigned* fl, unsigned fbase, float* red, float* hst)
{
    int tid = threadIdx.x;
    int cbase = cb << 3;
    int wid = tid >> 5, lane = tid & 31;
    int kq = wid >> 2, wl = wid & 3;
    int c0 = wl * 2, c1 = c0 + 1;
    int j0 = cbase + c0, j1 = cbase + c1;
    bool fin = (kq == 0) && (lane < DTn);
    float br0 = 0.f, bz0 = 0.f, bn0 = 0.f, br1 = 0.f, bz1 = 0.f, bn1 = 0.f;
    if (kq == 0) {
        br0 = __ldg(bhh + j0); bz0 = __ldg(bhh + Hn + j0); bn0 = __ldg(bhh + 2 * Hn + j0);
        br1 = __ldg(bhh + j1); bz1 = __ldg(bhh + Hn + j1); bn1 = __ldg(bhh + 2 * Hn + j1);
    }
    const float4* wt = wthh + (size_t)(kq * 16) * G3;   // this warp's k-quarter
    unsigned kofs = (unsigned)kq * 256;
    unsigned hA = sptr(hst) + (unsigned)lane * (HSTR * 4) + kofs;
    float* myred = red + (wl * 32 + lane) * 7;
    float* hb[2] = { hb0, hb1 };

    for (int t = 0; t < LD; t++) {
        const float4* hg = (const float4*)hb[t & 1];
        float* hn_ = hb[(t & 1) ^ 1];
        #pragma unroll
        for (int i = 0; i < 3; i++) {
            int idx = tid + (i << 9);          // < 1536 float4
            int row = idx >> 6, col = idx & 63;
            float4 v = __ldcg(hg + idx);
            *(float4*)(hst + row * HSTR + (col << 2)) = v;
        }
        float g_r0 = 0.f, g_z0 = 0.f, g_n0 = 0.f, g_r1 = 0.f, g_z1 = 0.f, g_n1 = 0.f;
        if (fin) {
            const float* gib = gi + ((size_t)t * DTn + lane) * G3;
            g_r0 = __ldg(gib + j0); g_z0 = __ldg(gib + Hn + j0); g_n0 = __ldg(gib + 2 * Hn + j0);
            g_r1 = __ldg(gib + j1); g_z1 = __ldg(gib + Hn + j1); g_n1 = __ldg(gib + 2 * Hn + j1);
        }
        __syncthreads();
        u64 ar0 = pk(br0, 0.f), az0 = pk(bz0, 0.f), an0 = pk(bn0, 0.f);
        u64 ar1 = pk(br1, 0.f), az1 = pk(bz1, 0.f), an1 = pk(bn1, 0.f);
        #pragma unroll 4
        for (int jj = 0; jj < 16; jj++) {
            const float* wj = (const float*)(wt + (size_t)jj * G3);
            u64 h01, h23, wa, wb;
            lds2(h01, h23, hA + (jj << 4));
            ldg2(wa, wb, wj + (j0 << 2));
            ffma2(ar0, wa, h01); ffma2(ar0, wb, h23);
            ldg2(wa, wb, wj + (j1 << 2));
            ffma2(ar1, wa, h01); ffma2(ar1, wb, h23);
            ldg2(wa, wb, wj + ((256 + j0) << 2));
            ffma2(az0, wa, h01); ffma2(az0, wb, h23);
            ldg2(wa, wb, wj + ((256 + j1) << 2));
            ffma2(az1, wa, h01); ffma2(az1, wb, h23);
            ldg2(wa, wb, wj + ((512 + j0) << 2));
            ffma2(an0, wa, h01); ffma2(an0, wb, h23);
            ldg2(wa, wb, wj + ((512 + j1) << 2));
            ffma2(an1, wa, h01); ffma2(an1, wb, h23);
        }
        if (kq > 0) {
            float* rp = myred + (kq - 1) * (128 * 7);
            rp[0] = uns(ar0); rp[1] = uns(ar1);
            rp[2] = uns(az0); rp[3] = uns(az1);
            rp[4] = uns(an0); rp[5] = uns(an1);
        }
        __syncthreads();
        if (fin) {
            float sr0 = uns(ar0), sr1 = uns(ar1);
            float sz0 = uns(az0), sz1 = uns(az1);
            float sn0 = uns(an0), sn1 = uns(an1);
            #pragma unroll
            for (int p = 0; p < 3; p++) {
                float* rp = myred + p * (128 * 7);
                sr0 += rp[0]; sr1 += rp[1];
                sz0 += rp[2]; sz1 += rp[3];
                sn0 += rp[4]; sn1 += rp[5];
            }
            float r0 = sigm(g_r0 + sr0);
            float r1 = sigm(g_r1 + sr1);
            float z0 = sigm(g_z0 + sz0);
            float z1 = sigm(g_z1 + sz1);
            float n0 = tanhf(g_n0 + r0 * sn0);
            float n1 = tanhf(g_n1 + r1 * sn1);
            float ho0 = hst[lane * HSTR + j0];
            float ho1 = hst[lane * HSTR + j1];
            hn_[(lane << 8) + j0] = (1.0f - z0) * n0 + z0 * ho0;
            hn_[(lane << 8) + j1] = (1.0f - z1) * n1 + z1 * ho1;
        }
        bar_arrive(fl, cb, fbase + t + 1);
        bar_wait(fl, 32, fbase + t + 1);
    }
}

// ---------------- term recurrence: 16 warps, k-quarter split, uniform-LDG weights ----------------
__device__ void run_term(int cb, const float4* __restrict__ wthh, const float* __restrict__ bhh,
                         unsigned* fl, unsigned fbase, float* red, float* hst)
{
    int tid = threadIdx.x;
    int cbase = cb << 3;
    int wid = tid >> 5, lane = tid & 31;
    int kq = wid >> 2, wl = wid & 3;
    int c0 = wl * 2, c1 = c0 + 1;
    int j0 = cbase + c0, j1 = cbase + c1;
    float br0 = 0.f, bz0 = 0.f, bn0 = 0.f, br1 = 0.f, bz1 = 0.f, bn1 = 0.f;
    if (kq == 0) {
        br0 = __ldg(bhh + j0); bz0 = __ldg(bhh + Hn + j0); bn0 = __ldg(bhh + 2 * Hn + j0);
        br1 = __ldg(bhh + j1); bz1 = __ldg(bhh + Hn + j1); bn1 = __ldg(bhh + 2 * Hn + j1);
    }
    const float4* wt = wthh + (size_t)(kq * 16) * G3;
    unsigned kofs = (unsigned)kq * 256;
    unsigned h0A = sptr(hst) + (unsigned)lane * (HSTR * 4) + kofs;
    unsigned h1A = sptr(hst) + (unsigned)(lane + 32) * (HSTR * 4) + kofs;
    float* myred = red + (wl * 32 + lane) * 13;

    for (int t = 0; t < LQ; t++) {
        const float4* hg = (const float4*)g_hq[t & 1];
        float* hn_ = g_hq[(t & 1) ^ 1];
        #pragma unroll
        for (int i = 0; i < 8; i++) {
            int idx = tid + (i << 9);          // < 4096 float4
            int row = idx >> 6, col = idx & 63;
            float4 v = __ldcg(hg + idx);
            *(float4*)(hst + row * HSTR + (col << 2)) = v;
        }
        int q0 = lane, q1 = lane + 32;
        float gr00 = 0.f, gz00 = 0.f, gn00 = 0.f, gr01 = 0.f, gz01 = 0.f, gn01 = 0.f;
        float gr10 = 0.f, gz10 = 0.f, gn10 = 0.f, gr11 = 0.f, gz11 = 0.f, gn11 = 0.f;
        if (kq == 0) {
            const float* gA = g_gi_q + ((size_t)t * Qn + q0) * G3;
            const float* gB = g_gi_q + ((size_t)t * Qn + q1) * G3;
            gr00 = __ldg(gA + j0); gz00 = __ldg(gA + Hn + j0); gn00 = __ldg(gA + 2 * Hn + j0);
            gr01 = __ldg(gA + j1); gz01 = __ldg(gA + Hn + j1); gn01 = __ldg(gA + 2 * Hn + j1);
            gr10 = __ldg(gB + j0); gz10 = __ldg(gB + Hn + j0); gn10 = __ldg(gB + 2 * Hn + j0);
            gr11 = __ldg(gB + j1); gz11 = __ldg(gB + Hn + j1); gn11 = __ldg(gB + 2 * Hn + j1);
        }
        __syncthreads();
        u64 ar00 = pk(br0, 0.f), az00 = pk(bz0, 0.f), an00 = pk(bn0, 0.f);
        u64 ar01 = pk(br1, 0.f), az01 = pk(bz1, 0.f), an01 = pk(bn1, 0.f);
        u64 ar10 = pk(br0, 0.f), az10 = pk(bz0, 0.f), an10 = pk(bn0, 0.f);
        u64 ar11 = pk(br1, 0.f), az11 = pk(bz1, 0.f), an11 = pk(bn1, 0.f);
        #pragma unroll 4
        for (int jj = 0; jj < 16; jj++) {
            const float* wj = (const float*)(wt + (size_t)jj * G3);
            u64 h0a, h0b, h1a, h1b, wa, wb;
            lds2(h0a, h0b, h0A + (jj << 4));
            lds2(h1a, h1b, h1A + (jj << 4));
            ldg2(wa, wb, wj + (j0 << 2));
            ffma2(ar00, wa, h0a); ffma2(ar00, wb, h0b);
            ffma2(ar10, wa, h1a); ffma2(ar10, wb, h1b);
            ldg2(wa, wb, wj + (j1 << 2));
            ffma2(ar01, wa, h0a); ffma2(ar01, wb, h0b);
            ffma2(ar11, wa, h1a); ffma2(ar11, wb, h1b);
            ldg2(wa, wb, wj + ((256 + j0) << 2));
            ffma2(az00, wa, h0a); ffma2(az00, wb, h0b);
            ffma2(az10, wa, h1a); ffma2(az10, wb, h1b);
            ldg2(wa, wb, wj + ((256 + j1) << 2));
            ffma2(az01, wa, h0a); ffma2(az01, wb, h0b);
            ffma2(az11, wa, h1a); ffma2(az11, wb, h1b);
            ldg2(wa, wb, wj + ((512 + j0) << 2));
            ffma2(an00, wa, h0a); ffma2(an00, wb, h0b);
            ffma2(an10, wa, h1a); ffma2(an10, wb, h1b);
            ldg2(wa, wb, wj + ((512 + j1) << 2));
            ffma2(an01, wa, h0a); ffma2(an01, wb, h0b);
            ffma2(an11, wa, h1a); ffma2(an11, wb, h1b);
        }
        if (kq > 0) {
            float* rp = myred + (kq - 1) * (128 * 13);
            rp[0]  = uns(ar00); rp[1]  = uns(ar01);
            rp[2]  = uns(az00); rp[3]  = uns(az01);
            rp[4]  = uns(an00); rp[5]  = uns(an01);
            rp[6]  = uns(ar10); rp[7]  = uns(ar11);
            rp[8]  = uns(az10); rp[9]  = uns(az11);
            rp[10] = uns(an10); rp[11] = uns(an11);
        }
        __syncthreads();
        if (kq == 0) {
            float s[12];
            s[0] = uns(ar00); s[1] = uns(ar01); s[2] = uns(az00); s[3] = uns(az01);
            s[4] = uns(an00); s[5] = uns(an01); s[6] = uns(ar10); s[7] = uns(ar11);
            s[8] = uns(az10); s[9] = uns(az11); s[10] = uns(an10); s[11] = uns(an11);
            #pragma unroll
            for (int p = 0; p < 3; p++) {
                float* rp = myred + p * (128 * 13);
                #pragma unroll
                for (int v = 0; v < 12; v++) s[v] += rp[v];
            }
            float r, z, n, ho;
            r = sigm(gr00 + s[0]);
            z = sigm(gz00 + s[2]);
            n = tanhf(gn00 + r * s[4]);
            ho = hst[q0 * HSTR + j0];
            hn_[(q0 << 8) + j0] = (1.0f - z) * n + z * ho;
            r = sigm(gr01 + s[1]);
            z = sigm(gz01 + s[3]);
            n = tanhf(gn01 + r * s[5]);
            ho = hst[q0 * HSTR + j1];
            hn_[(q0 << 8) + j1] = (1.0f - z) * n + z * ho;
            r = sigm(gr10 + s[6]);
            z = sigm(gz10 + s[8]);
            n = tanhf(gn10 + r * s[10]);
            ho = hst[q1 * HSTR + j0];
            hn_[(q1 << 8) + j0] = (1.0f - z) * n + z * ho;
            r = sigm(gr11 + s[7]);
            z = sigm(gz11 + s[9]);
            n = tanhf(gn11 + r * s[11]);
            ho = hst[q1 * HSTR + j1];
            hn_[(q1 << 8) + j1] = (1.0f - z) * n + z * ho;
        }
        bar_arrive(fl, cb, fbase + t + 1);
        bar_wait(fl, 32, fbase + t + 1);
    }
}

// ---------------- persistent kernel ----------------
__global__ void __launch_bounds__(NTHR, 1)
fmn_kernel(const int* __restrict__ q_tok, const int* __restrict__ p_tok, const int* __restrict__ n_tok,
           const float* __restrict__ term_emb, const float* __restrict__ term_Wih,
           const float* __restrict__ term_Whh, const float* __restrict__ term_bih,
           const float* __restrict__ term_bhh,
           const float* __restrict__ doc_emb,
           const float* __restrict__ dc_Wih, const float* __restrict__ dc_Whh,
           const float* __restrict__ dc_bih, const float* __restrict__ dc_bhh,
           const float* __restrict__ da_Wih, const float* __restrict__ da_Whh,
           const float* __restrict__ da_bih, const float* __restrict__ da_bhh,
           const float* __restrict__ pos_table, const float* __restrict__ posd_W,
           const float* __restrict__ posd_b,
           const float* __restrict__ qy_Wih, const float* __restrict__ qy_Whh,
           const float* __restrict__ qy_bih, const float* __restrict__ qy_bhh,
           float* __restrict__ out)
{
    __shared__ float ws[24 * 256];
    __shared__ float red[3 * 128 * 13];
    extern __shared__ float dyn[];
    int bid = blockIdx.x;
    int tid = threadIdx.x;
    int half = tid >> 8;
    unsigned ball = rd_base(g_f_all, bid);

    if (bid < 32) {
        int gid = bid;
        unsigned bp0 = rd_base(g_f_p0c, gid);
        unsigned brr = rd_base(g_f_rc, gid);
        if (gid == 0)
            for (int i = tid; i < DTn * Hn; i += NTHR) g_hc[0][i] = 0.0f;
        transpose_w(gid, dc_Wih, g_wt_c, dyn);
        transpose_w(gid, dc_Whh, g_wthh_c, dyn);
        bar_arrive(g_f_p0c, gid, bp0 + 1); bar_wait(g_f_p0c, NB_DOC, bp0 + 1);
        phase0_gemm(gid * 2 + half, NB_DOC * 2, half, LD * DTn, 1, p_tok, n_tok,
                    doc_emb, g_wt_c, dc_bih, g_gi_c, dyn + half * 2048);
        bar_arrive(g_f_p0c, gid, bp0 + 2); bar_wait(g_f_p0c, NB_DOC, bp0 + 2);
        run_doc(gid, g_wthh_c, dc_bhh, g_gi_c, g_hc[0], g_hc[1], g_f_rc, brr, red, dyn);
    } else if (bid < 64) {
        int gid = bid - 32;
        unsigned bp0 = rd_base(g_f_p0a, gid);
        unsigned brr = rd_base(g_f_ra, gid);
        if (gid == 0)
            for (int i = tid; i < DTn * Hn; i += NTHR) g_ha[0][i] = 0.0f;
        transpose_w(gid, da_Wih, g_wt_a, dyn);
        transpose_w(gid, da_Whh, g_wthh_a, dyn);
        bar_arrive(g_f_p0a, gid, bp0 + 1); bar_wait(g_f_p0a, NB_DOC, bp0 + 1);
        phase0_gemm(gid * 2 + half, NB_DOC * 2, half, LD * DTn, 1, p_tok, n_tok,
                    doc_emb, g_wt_a, da_bih, g_gi_a, dyn + half * 2048);
        bar_arrive(g_f_p0a, gid, bp0 + 2); bar_wait(g_f_p0a, NB_DOC, bp0 + 2);
        run_doc(gid, g_wthh_a, da_bhh, g_gi_a, g_ha[0], g_ha[1], g_f_ra, brr, red, dyn);
    } else if (bid < 96) {
        int gid = bid - 64;
        unsigned bp0 = rd_base(g_f_p0t, gid);
        unsigned brr = rd_base(g_f_rt, gid);
        if (gid == 0)
            for (int i = tid; i < Qn * Hn; i += NTHR) g_hq[0][i] = 0.0f;
        transpose_w(gid, term_Wih, g_wt_q, dyn);
        transpose_w(gid, term_Whh, g_wthh_q, dyn);
        bar_arrive(g_f_p0t, gid, bp0 + 1); bar_wait(g_f_p0t, NB_TRM, bp0 + 1);
        phase0_gemm(gid * 2 + half, NB_TRM * 2, half, LQ * Qn, 0, q_tok, (const int*)0,
                    term_emb, g_wt_q, term_bih, g_gi_q, dyn + half * 2048);
        bar_arrive(g_f_p0t, gid, bp0 + 2); bar_wait(g_f_p0t, NB_TRM, bp0 + 2);
        run_term(gid, g_wthh_q, term_bhh, g_f_rt, brr, red, dyn);
    } else if (bid < 116) {
        int gid = bid - 96 + 32;
        unsigned bp0 = rd_base(g_f_p0c, gid);
        bar_arrive(g_f_p0c, gid, bp0 + 1); bar_wait(g_f_p0c, NB_DOC, bp0 + 1);
        phase0_gemm(gid * 2 + half, NB_DOC * 2, half, LD * DTn, 1, p_tok, n_tok,
                    doc_emb, g_wt_c, dc_bih, g_gi_c, dyn + half * 2048);
        bar_arrive(g_f_p0c, gid, bp0 + 2);
    } else if (bid < 136) {
        int gid = bid - 116 + 32;
        unsigned bp0 = rd_base(g_f_p0a, gid);
        bar_arrive(g_f_p0a, gid, bp0 + 1); bar_wait(g_f_p0a, NB_DOC, bp0 + 1);
        phase0_gemm(gid * 2 + half, NB_DOC * 2, half, LD * DTn, 1, p_tok, n_tok,
                    doc_emb, g_wt_a, da_bih, g_gi_a, dyn + half * 2048);
        bar_arrive(g_f_p0a, gid, bp0 + 2);
    } else {
        int gid = bid - 136 + 32;
        unsigned bp0 = rd_base(g_f_p0t, gid);
        bar_arrive(g_f_p0t, gid, bp0 + 1); bar_wait(g_f_p0t, NB_TRM, bp0 + 1);
        phase0_gemm(gid * 2 + half, NB_TRM * 2, half, LQ * Qn, 0, q_tok, (const int*)0,
                    term_emb, g_wt_q, term_bih, g_gi_q, dyn + half * 2048);
        bar_arrive(g_f_p0t, gid, bp0 + 2);
    }

    bar_arrive(g_f_all, bid, ball + 1); bar_wait(g_f_all, NBLK, ball + 1);

    // ---- phase A: position dense (blocks 0..23) ----
    if (bid < DTn) {
        float* hrow = ws;
        if (tid < 256) hrow[tid] = __ldcg(&g_hc[0][bid * Hn + tid]);
        __syncthreads();
        if (tid < 256) {
            int dset = bid % DSET;
            float pe0 = __ldg(&pos_table[dset * 4 + 0]);
            float pe1 = __ldg(&pos_table[dset * 4 + 1]);
            float pe2 = __ldg(&pos_table[dset * 4 + 2]);
            float pe3 = __ldg(&pos_table[dset * 4 + 3]);
            int j = tid;
            const float* wrow = posd_W + (size_t)j * (Hn + 4);
            unsigned xsa = sptr(hrow);
            u64 acc = pk(0.0f, 0.0f);
            #pragma unroll 4
            for (int ii = 0; ii < 64; ii++) {
                u64 w01, w23, x01, x23;
                ldg2(w01, w23, wrow + (ii << 2));
                lds2(x01, x23, xsa + (ii << 4));
                ffma2(acc, w01, x01);
                ffma2(acc, w23, x23);
            }
            float a = uns(acc);
            a = fmaf(pe0, __ldg(wrow + 256), a);
            a = fmaf(pe1, __ldg(wrow + 257), a);
            a = fmaf(pe2, __ldg(wrow + 258), a);
            a = fmaf(pe3, __ldg(wrow + 259), a);
            a += __ldg(&posd_b[j]);
            g_attc[bid * Hn + j] = a;
        }
    } else if (bid >= 32 && bid < 96) {
        // ---- phase B: attention scores ----
        int q = bid - 32;
        float* eq = ws;
        if (tid < 256) eq[tid] = __ldcg(&g_hq[0][q * Hn + tid]);
        __syncthreads();
        if (tid < DTn) {
            const float4* ap = (const float4*)(g_ha[0] + tid * Hn);
            const float4* e4 = (const float4*)eq;
            float acc = 0.0f;
            #pragma unroll 4
            for (int ii = 0; ii < 64; ii++) {
                float4 a4 = __ldcg(ap + ii);
                float4 x4 = e4[ii];
                acc = fmaf(a4.x, x4.x, acc);
                acc = fmaf(a4.y, x4.y, acc);
                acc = fmaf(a4.z, x4.z, acc);
                acc = fmaf(a4.w, x4.w, acc);
            }
            g_scores[q * DTn + tid] = acc;
        }
    }

    bar_arrive(g_f_all, bid, ball + 2); bar_wait(g_f_all, NBLK, ball + 2);

    // ---- phase C: softmax + memory read + final GRU (blocks 0..63) ----
    if (bid < Qn) {
        int q = bid;
        float* sv = ws;
        float* wv = ws + 32;
        float* qs = ws + 64;
        if (tid < DTn) sv[tid] = __ldcg(&g_scores[q * DTn + tid]);
        __syncthreads();
        if (tid < 2) {
            int off = tid * DSET;
            float mx = -1e30f;
            for (int d2 = 0; d2 < DSET; d2++) mx = fmaxf(mx, sv[off + d2]);
            float s = 0.0f;
            for (int d2 = 0; d2 < DSET; d2++) {
                float e = __expf(sv[off + d2] - mx);
                wv[off + d2] = e;
                s += e;
            }
            float inv = 1.0f / s;
            for (int d2 = 0; d2 < DSET; d2++) wv[off + d2] *= inv;
        }
        __syncthreads();
        if (tid < 256) {
            int j = tid;
            float val = __ldcg(&g_hq[0][q * Hn + j]);
            #pragma unroll
            for (int d2 = 0; d2 < DSET; d2++)
                val = fmaf(wv[d2], __ldcg(&g_attc[d2 * Hn + j]), val);
            #pragma unroll
            for (int d2 = 0; d2 < DSET; d2++)
                val = fmaf(wv[DSET + d2], __ldcg(&g_attc[(DSET + d2) * Hn + j]), val);
            qs[j] = val;
        }
        __syncthreads();
        if (tid < 256) {
            int j = tid;
            u64 dr = pk(0.0f, 0.0f), dz = pk(0.0f, 0.0f), dn = pk(0.0f, 0.0f);
            unsigned qsa = sptr(qs);
            const float* wr = qy_Wih + (size_t)j * Hn;
            const float* wz = qy_Wih + (size_t)(Hn + j) * Hn;
            const float* wn = qy_Wih + (size_t)(2 * Hn + j) * Hn;
            #pragma unroll 4
            for (int ii = 0; ii < 64; ii++) {
                u64 x01, x23, w01, w23;
                lds2(x01, x23, qsa + (ii << 4));
                ldg2(w01, w23, wr + (ii << 2));
                ffma2(dr, w01, x01); ffma2(dr, w23, x23);
                ldg2(w01, w23, wz + (ii << 2));
                ffma2(dz, w01, x01); ffma2(dz, w23, x23);
                ldg2(w01, w23, wn + (ii << 2));
                ffma2(dn, w01, x01); ffma2(dn, w23, x23);
            }
            float r = sigm(uns(dr) + __ldg(&qy_bih[j]) + __ldg(&qy_bhh[j]));
            float z = sigm(uns(dz) + __ldg(&qy_bih[Hn + j]) + __ldg(&qy_bhh[Hn + j]));
            float n = tanhf(uns(dn) + __ldg(&qy_bih[2 * Hn + j]) + r * __ldg(&qy_bhh[2 * Hn + j]));
            out[q * Hn + j] = (1.0f - z) * n;
        }
    }
}

extern "C" void kernel_launch(void* const* d_in, const int* in_sizes, int n_in,
                              void* d_out, int out_size) {
    const int*   q_tok    = (const int*)d_in[0];
    const int*   p_tok    = (const int*)d_in[1];
    const int*   n_tok    = (const int*)d_in[2];
    const float* term_emb = (const float*)d_in[3];
    const float* term_Wih = (const float*)d_in[4];
    const float* term_Whh = (const float*)d_in[5];
    const float* term_bih = (const float*)d_in[6];
    const float* term_bhh = (const float*)d_in[7];
    const float* doc_emb  = (const float*)d_in[8];
    const float* dc_Wih   = (const float*)d_in[9];
    const float* dc_Whh   = (const float*)d_in[10];
    const float* dc_bih   = (const float*)d_in[11];
    const float* dc_bhh   = (const float*)d_in[12];
    const float* da_Wih   = (const float*)d_in[13];
    const float* da_Whh   = (const float*)d_in[14];
    const float* da_bih   = (const float*)d_in[15];
    const float* da_bhh   = (const float*)d_in[16];
    const float* pos_tab  = (const float*)d_in[17];
    const float* posd_W   = (const float*)d_in[18];
    const float* posd_b   = (const float*)d_in[19];
    const float* qy_Wih   = (const float*)d_in[20];
    const float* qy_Whh   = (const float*)d_in[21];
    const float* qy_bih   = (const float*)d_in[22];
    const float* qy_bhh   = (const float*)d_in[23];
    float* out = (float*)d_out;

    const int dyn_bytes = 64 * HSTR * 4;
    cudaFuncSetAttribute(fmn_kernel, cudaFuncAttributeMaxDynamicSharedMemorySize, dyn_bytes);
    fmn_kernel<<<NBLK, NTHR, dyn_bytes>>>(q_tok, p_tok, n_tok,
                            term_emb, term_Wih, term_Whh, term_bih, term_bhh,
                            doc_emb, dc_Wih, dc_Whh, dc_bih, dc_bhh,
                            da_Wih, da_Whh, da_bih, da_bhh,
                            pos_tab, posd_W, posd_b,
                            qy_Wih, qy_Whh, qy_bih, qy_bhh,
                            out);
}

// round 12
// speedup vs baseline: 1.0778x; 1.0778x over previous
#include <cuda_runtime.h>

typedef unsigned long long u64;

#define Qn   64
#define LQ   20
#define DSET 12
#define DTn  24
#define LD   50
#define Hn   256
#define G3   768
#define HSTR 260
#define NB_DOC 52
#define NB_TRM 40
#define NBLK 144
#define NTHR 512

// ---------------- device scratch ----------------
__device__ float g_gi_q[LQ * Qn * G3];
__device__ float g_gi_c[LD * DTn * G3];
__device__ float g_gi_a[LD * DTn * G3];
__device__ float4 g_wt_c[64 * G3];     // k-major Wih (phase0)
__device__ float4 g_wt_a[64 * G3];
__device__ float4 g_wt_q[64 * G3];
__device__ float g_hq[2][Qn * Hn];
__device__ float g_hc[2][DTn * Hn];
__device__ float g_ha[2][DTn * Hn];
__device__ float g_attc[DTn * Hn];
__device__ float g_scores[Qn * DTn];
__device__ unsigned g_f_p0c[NB_DOC * 32];
__device__ unsigned g_f_p0a[NB_DOC * 32];
__device__ unsigned g_f_p0t[NB_TRM * 32];
__device__ unsigned g_f_rc[32 * 32];
__device__ unsigned g_f_ra[32 * 32];
__device__ unsigned g_f_rt[32 * 32];
__device__ unsigned g_f_all[NBLK * 32];

// ---------------- helpers ----------------
__device__ __forceinline__ float sigm(float x) { return 1.0f / (1.0f + __expf(-x)); }
__device__ __forceinline__ u64 pk(float lo, float hi) {
    u64 r; asm("mov.b64 %0, {%1,%2};" : "=l"(r) : "f"(lo), "f"(hi)); return r;
}
__device__ __forceinline__ float uns(u64 v) {
    float lo, hi; asm("mov.b64 {%0,%1}, %2;" : "=f"(lo), "=f"(hi) : "l"(v));
    return lo + hi;
}
__device__ __forceinline__ void ffma2(u64& d, u64 a, u64 b) {
    asm("fma.rn.f32x2 %0, %1, %2, %0;" : "+l"(d) : "l"(a), "l"(b));
}
__device__ __forceinline__ unsigned sptr(const void* p) {
    return (unsigned)__cvta_generic_to_shared(p);
}
__device__ __forceinline__ void lds2(u64& a, u64& b, unsigned addr) {
    asm volatile("ld.shared.v2.u64 {%0,%1}, [%2];" : "=l"(a), "=l"(b) : "r"(addr));
}
__device__ __forceinline__ void ldg2(u64& a, u64& b, const float* p) {
    asm volatile("ld.global.nc.v2.u64 {%0,%1}, [%2];" : "=l"(a), "=l"(b) : "l"(p));
}
__device__ __forceinline__ void barh(int h) {
    asm volatile("bar.sync %0, %1;" :: "r"(1 + h), "r"(256) : "memory");
}

// ---- flag barrier ----
__device__ __forceinline__ void bar_arrive(unsigned* fl, int idx, unsigned gen) {
    __syncthreads();
    if (threadIdx.x == 0)
        asm volatile("st.release.gpu.global.u32 [%0], %1;"
                     :: "l"(fl + idx * 32), "r"(gen) : "memory");
}
__device__ __forceinline__ void bar_wait(unsigned* fl, int n, unsigned gen) {
    if (threadIdx.x < (unsigned)n) {
        unsigned cur;
        do {
            asm volatile("ld.acquire.gpu.global.u32 %0, [%1];"
                         : "=r"(cur) : "l"(fl + threadIdx.x * 32) : "memory");
        } while (cur < gen);
    }
    __syncthreads();
}
__device__ __forceinline__ unsigned rd_base(unsigned* fl, int idx) {
    return *(volatile unsigned*)(fl + idx * 32);
}

// ---------------- W transpose: W[768][256] -> Wt[64][768] float4 ----------------
__device__ void transpose_w(int gid, const float* __restrict__ W, float4* __restrict__ Wt,
                            float* sbuf)
{
    int tid = threadIdx.x;
    int r0 = gid * 24;
    for (int i = tid; i < 24 * 256; i += NTHR) {
        int rl = i >> 8, j = i & 255;
        sbuf[rl * 260 + j] = __ldg(W + (size_t)(r0 + rl) * Hn + j);
    }
    __syncthreads();
    for (int i = tid; i < 24 * 64; i += NTHR) {
        int rl = i % 24, kk = i / 24;
        float4 v = *(float4*)(sbuf + rl * 260 + (kk << 2));
        Wt[kk * G3 + r0 + rl] = v;
    }
    __syncthreads();
}

// ---------------- phase 0 (one 256-thread half = one virtual block) ----------------
__device__ void phase0_gemm(int vgid, int nv, int half, int R, int mode,
                            const int* __restrict__ tokA, const int* __restrict__ tokB,
                            const float* __restrict__ emb, const float4* __restrict__ Wt,
                            const float* __restrict__ bias, float* __restrict__ gi,
                            float* xs)
{
    int th = threadIdx.x & 255;
    int rpb = (R + nv - 1) / nv;
    int r0 = vgid * rpb;
    int r1 = min(R, r0 + rpb);
    unsigned xsa = sptr(xs);
    float b0 = __ldg(bias + th), b1 = __ldg(bias + th + 256), b2 = __ldg(bias + th + 512);

    for (int rt = r0; rt < r1; rt += 8) {
        int nr = min(8, r1 - rt);
        barh(half);
        for (int idx = th; idx < (nr << 8); idx += 256) {
            int rl = idx >> 8, j = idx & 255;
            int r = rt + rl;
            int tok;
            if (mode == 0) {
                int t = r >> 6, q = r & 63;
                tok = tokA[q * LQ + t];
            } else {
                int t = r / DTn, dt = r - t * DTn;
                tok = (dt < DSET) ? tokA[dt * LD + t] : tokB[(dt - DSET) * LD + t];
            }
            xs[(rl << 8) + j] = __ldg(emb + (size_t)tok * Hn + j);
        }
        barh(half);

        u64 acc[3][8];
        #pragma unroll
        for (int rl = 0; rl < 8; rl++) {
            acc[0][rl] = pk(b0, 0.0f);
            acc[1][rl] = pk(b1, 0.0f);
            acc[2][rl] = pk(b2, 0.0f);
        }
        #pragma unroll 2
        for (int jj = 0; jj < 64; jj++) {
            const float* wp = (const float*)(Wt + jj * G3 + th);
            u64 w0a, w0b, w1a, w1b, w2a, w2b;
            ldg2(w0a, w0b, wp);
            ldg2(w1a, w1b, wp + 1024);
            ldg2(w2a, w2b, wp + 2048);
            unsigned xo = xsa + (jj << 4);
            #pragma unroll
            for (int rlb = 0; rlb < 2; rlb++) {
                u64 x01[4], x23[4];
                #pragma unroll
                for (int rl = 0; rl < 4; rl++)
                    lds2(x01[rl], x23[rl], xo + ((rlb * 4 + rl) << 10));
                #pragma unroll
                for (int rl = 0; rl < 4; rl++) {
                    int ri = rlb * 4 + rl;
                    ffma2(acc[0][ri], w0a, x01[rl]); ffma2(acc[0][ri], w0b, x23[rl]);
                    ffma2(acc[1][ri], w1a, x01[rl]); ffma2(acc[1][ri], w1b, x23[rl]);
                    ffma2(acc[2][ri], w2a, x01[rl]); ffma2(acc[2][ri], w2b, x23[rl]);
                }
            }
        }
        for (int rl = 0; rl < nr; rl++) {
            float* gr = gi + (size_t)(rt + rl) * G3 + th;
            gr[0]   = uns(acc[0][rl]);
            gr[256] = uns(acc[1][rl]);
            gr[512] = uns(acc[2][rl]);
        }
    }
}

// ---------------- doc recurrence: weights in registers, dense LDS, shfl reduce ----------------
// warp: c = wid&7 (column), kq = wid>>3 (k-half of 128)
// lane: ko = lane&7 (16 k each), dgrp = lane>>3 (4 docs per batch, 6 batches)
__device__ void run_doc(int cb, const float* __restrict__ Whh, const float* __restrict__ bhh,
                        const float* __restrict__ gi, float* hb0, float* hb1,
                        unsigned* fl, unsigned fbase, float* red, float* hst)
{
    int tid = threadIdx.x;
    int cbase = cb << 3;
    int wid = tid >> 5, lane = tid & 31;
    int c = wid & 7, kq = wid >> 3;
    int ko = lane & 7, dgrp = lane >> 3;
    int j = cbase + c;
    int kbase = kq * 128 + ko * 16;

    u64 W[3][8];
    #pragma unroll
    for (int g = 0; g < 3; g++) {
        const float* wr = Whh + (size_t)(g * Hn + j) * Hn + kbase;
        #pragma unroll
        for (int i = 0; i < 4; i++)
            ldg2(W[g][i * 2], W[g][i * 2 + 1], wr + i * 4);
    }

    int fc = tid & 7, fd = tid >> 3;        // finalize role (tid<192)
    bool fin = (tid < 192);
    int fj = cbase + fc;
    float br = 0.f, bz = 0.f, bn = 0.f;
    if (fin) {
        br = __ldg(bhh + fj); bz = __ldg(bhh + Hn + fj); bn = __ldg(bhh + 2 * Hn + fj);
    }
    unsigned hbaseA = sptr(hst);
    int redw = ((kq << 3) + c) * 24;        // write base row (per warp)
    float* hb[2] = { hb0, hb1 };

    for (int t = 0; t < LD; t++) {
        const float4* hg = (const float4*)hb[t & 1];
        float* hn_ = hb[(t & 1) ^ 1];
        #pragma unroll
        for (int i = 0; i < 3; i++) {
            int idx = tid + (i << 9);          // < 1536 float4
            int row = idx >> 6, col = idx & 63;
            float4 v = __ldcg(hg + idx);
            *(float4*)(hst + row * HSTR + (col << 2)) = v;
        }
        float gr = 0.f, gz = 0.f, gn = 0.f;
        if (fin) {
            const float* gib = gi + ((size_t)t * DTn + fd) * G3;
            gr = __ldg(gib + fj); gz = __ldg(gib + Hn + fj); gn = __ldg(gib + 2 * Hn + fj);
        }
        __syncthreads();
        #pragma unroll
        for (int db = 0; db < 6; db++) {
            int d = db * 4 + dgrp;
            unsigned ha = hbaseA + ((unsigned)(d * HSTR + kbase) << 2);
            u64 h0, h1, h2, h3, h4, h5, h6, h7;
            lds2(h0, h1, ha);      lds2(h2, h3, ha + 16);
            lds2(h4, h5, ha + 32); lds2(h6, h7, ha + 48);
            u64 a0 = pk(0.f, 0.f), a1 = pk(0.f, 0.f), a2 = pk(0.f, 0.f);
            ffma2(a0, W[0][0], h0); ffma2(a0, W[0][1], h1); ffma2(a0, W[0][2], h2); ffma2(a0, W[0][3], h3);
            ffma2(a0, W[0][4], h4); ffma2(a0, W[0][5], h5); ffma2(a0, W[0][6], h6); ffma2(a0, W[0][7], h7);
            ffma2(a1, W[1][0], h0); ffma2(a1, W[1][1], h1); ffma2(a1, W[1][2], h2); ffma2(a1, W[1][3], h3);
            ffma2(a1, W[1][4], h4); ffma2(a1, W[1][5], h5); ffma2(a1, W[1][6], h6); ffma2(a1, W[1][7], h7);
            ffma2(a2, W[2][0], h0); ffma2(a2, W[2][1], h1); ffma2(a2, W[2][2], h2); ffma2(a2, W[2][3], h3);
            ffma2(a2, W[2][4], h4); ffma2(a2, W[2][5], h5); ffma2(a2, W[2][6], h6); ffma2(a2, W[2][7], h7);
            float s0 = uns(a0), s1 = uns(a1), s2 = uns(a2);
            #pragma unroll
            for (int m = 1; m < 8; m <<= 1) {
                s0 += __shfl_xor_sync(0xffffffffu, s0, m);
                s1 += __shfl_xor_sync(0xffffffffu, s1, m);
                s2 += __shfl_xor_sync(0xffffffffu, s2, m);
            }
            if (ko == 0) {
                float* rp = red + (redw + d) * 3;
                rp[0] = s0; rp[1] = s1; rp[2] = s2;
            }
        }
        __syncthreads();
        if (fin) {
            const float* r0 = red + (fc * 24 + fd) * 3;          // kq=0
            const float* r1 = red + ((64 + fc * 24 + fd) * 3) + 8; // placeholder avoided
            r1 = red + ((8 + fc) * 24 + fd) * 3;                  // kq=1
            float rr = sigm(gr + r0[0] + r1[0] + br);
            float zz = sigm(gz + r0[1] + r1[1] + bz);
            float nn = tanhf(gn + rr * (r0[2] + r1[2] + bn));
            float hold = hst[fd * HSTR + fj];
            hn_[(fd << 8) + fj] = (1.0f - zz) * nn + zz * hold;
        }
        bar_arrive(fl, cb, fbase + t + 1);
        bar_wait(fl, 32, fbase + t + 1);
    }
}

// ---------------- term recurrence: same scheme, 64 queries (16 batches) ----------------
__device__ void run_term(int cb, const float* __restrict__ Whh, const float* __restrict__ bhh,
                         unsigned* fl, unsigned fbase, float* red, float* hst)
{
    int tid = threadIdx.x;
    int cbase = cb << 3;
    int wid = tid >> 5, lane = tid & 31;
    int c = wid & 7, kq = wid >> 3;
    int ko = lane & 7, dgrp = lane >> 3;
    int j = cbase + c;
    int kbase = kq * 128 + ko * 16;

    u64 W[3][8];
    #pragma unroll
    for (int g = 0; g < 3; g++) {
        const float* wr = Whh + (size_t)(g * Hn + j) * Hn + kbase;
        #pragma unroll
        for (int i = 0; i < 4; i++)
            ldg2(W[g][i * 2], W[g][i * 2 + 1], wr + i * 4);
    }

    int fc = tid & 7, fq = tid >> 3;        // finalize: all 512 threads, fq<64
    int fj = cbase + fc;
    float br = __ldg(bhh + fj), bz = __ldg(bhh + Hn + fj), bn = __ldg(bhh + 2 * Hn + fj);
    unsigned hbaseA = sptr(hst);
    int redw = ((kq << 3) + c) * 64;

    for (int t = 0; t < LQ; t++) {
        const float4* hg = (const float4*)g_hq[t & 1];
        float* hn_ = g_hq[(t & 1) ^ 1];
        #pragma unroll
        for (int i = 0; i < 8; i++) {
            int idx = tid + (i << 9);          // < 4096 float4
            int row = idx >> 6, col = idx & 63;
            float4 v = __ldcg(hg + idx);
            *(float4*)(hst + row * HSTR + (col << 2)) = v;
        }
        const float* gib = g_gi_q + ((size_t)t * Qn + fq) * G3;
        float gr = __ldg(gib + fj), gz = __ldg(gib + Hn + fj), gn = __ldg(gib + 2 * Hn + fj);
        __syncthreads();
        #pragma unroll 4
        for (int db = 0; db < 16; db++) {
            int q = db * 4 + dgrp;
            unsigned ha = hbaseA + ((unsigned)(q * HSTR + kbase) << 2);
            u64 h0, h1, h2, h3, h4, h5, h6, h7;
            lds2(h0, h1, ha);      lds2(h2, h3, ha + 16);
            lds2(h4, h5, ha + 32); lds2(h6, h7, ha + 48);
            u64 a0 = pk(0.f, 0.f), a1 = pk(0.f, 0.f), a2 = pk(0.f, 0.f);
            ffma2(a0, W[0][0], h0); ffma2(a0, W[0][1], h1); ffma2(a0, W[0][2], h2); ffma2(a0, W[0][3], h3);
            ffma2(a0, W[0][4], h4); ffma2(a0, W[0][5], h5); ffma2(a0, W[0][6], h6); ffma2(a0, W[0][7], h7);
            ffma2(a1, W[1][0], h0); ffma2(a1, W[1][1], h1); ffma2(a1, W[1][2], h2); ffma2(a1, W[1][3], h3);
            ffma2(a1, W[1][4], h4); ffma2(a1, W[1][5], h5); ffma2(a1, W[1][6], h6); ffma2(a1, W[1][7], h7);
            ffma2(a2, W[2][0], h0); ffma2(a2, W[2][1], h1); ffma2(a2, W[2][2], h2); ffma2(a2, W[2][3], h3);
            ffma2(a2, W[2][4], h4); ffma2(a2, W[2][5], h5); ffma2(a2, W[2][6], h6); ffma2(a2, W[2][7], h7);
            float s0 = uns(a0), s1 = uns(a1), s2 = uns(a2);
            #pragma unroll
            for (int m = 1; m < 8; m <<= 1) {
                s0 += __shfl_xor_sync(0xffffffffu, s0, m);
                s1 += __shfl_xor_sync(0xffffffffu, s1, m);
                s2 += __shfl_xor_sync(0xffffffffu, s2, m);
            }
            if (ko == 0) {
                float* rp = red + (redw + q) * 3;
                rp[0] = s0; rp[1] = s1; rp[2] = s2;
            }
        }
        __syncthreads();
        {
            const float* r0 = red + (fc * 64 + fq) * 3;           // kq=0
            const float* r1 = red + ((8 + fc) * 64 + fq) * 3;     // kq=1
            float rr = sigm(gr + r0[0] + r1[0] + br);
            float zz = sigm(gz + r0[1] + r1[1] + bz);
            float nn = tanhf(gn + rr * (r0[2] + r1[2] + bn));
            float hold = hst[fq * HSTR + fj];
            hn_[(fq << 8) + fj] = (1.0f - zz) * nn + zz * hold;
        }
        bar_arrive(fl, cb, fbase + t + 1);
        bar_wait(fl, 32, fbase + t + 1);
    }
}

// ---------------- persistent kernel ----------------
__global__ void __launch_bounds__(NTHR, 1)
fmn_kernel(const int* __restrict__ q_tok, const int* __restrict__ p_tok, const int* __restrict__ n_tok,
           const float* __restrict__ term_emb, const float* __restrict__ term_Wih,
           const float* __restrict__ term_Whh, const float* __restrict__ term_bih,
           const float* __restrict__ term_bhh,
           const float* __restrict__ doc_emb,
           const float* __restrict__ dc_Wih, const float* __restrict__ dc_Whh,
           const float* __restrict__ dc_bih, const float* __restrict__ dc_bhh,
           const float* __restrict__ da_Wih, const float* __restrict__ da_Whh,
           const float* __restrict__ da_bih, const float* __restrict__ da_bhh,
           const float* __restrict__ pos_table, const float* __restrict__ posd_W,
           const float* __restrict__ posd_b,
           const float* __restrict__ qy_Wih, const float* __restrict__ qy_Whh,
           const float* __restrict__ qy_bih, const float* __restrict__ qy_bhh,
           float* __restrict__ out)
{
    __shared__ float ws[24 * 256];
    __shared__ float red[2 * 8 * 64 * 3];
    extern __shared__ float dyn[];
    int bid = blockIdx.x;
    int tid = threadIdx.x;
    int half = tid >> 8;
    unsigned ball = rd_base(g_f_all, bid);

    if (bid < 32) {
        int gid = bid;
        unsigned bp0 = rd_base(g_f_p0c, gid);
        unsigned brr = rd_base(g_f_rc, gid);
        if (gid == 0)
            for (int i = tid; i < DTn * Hn; i += NTHR) g_hc[0][i] = 0.0f;
        transpose_w(gid, dc_Wih, g_wt_c, dyn);
        bar_arrive(g_f_p0c, gid, bp0 + 1); bar_wait(g_f_p0c, NB_DOC, bp0 + 1);
        phase0_gemm(gid * 2 + half, NB_DOC * 2, half, LD * DTn, 1, p_tok, n_tok,
                    doc_emb, g_wt_c, dc_bih, g_gi_c, dyn + half * 2048);
        bar_arrive(g_f_p0c, gid, bp0 + 2); bar_wait(g_f_p0c, NB_DOC, bp0 + 2);
        run_doc(gid, dc_Whh, dc_bhh, g_gi_c, g_hc[0], g_hc[1], g_f_rc, brr, red, dyn);
    } else if (bid < 64) {
        int gid = bid - 32;
        unsigned bp0 = rd_base(g_f_p0a, gid);
        unsigned brr = rd_base(g_f_ra, gid);
        if (gid == 0)
            for (int i = tid; i < DTn * Hn; i += NTHR) g_ha[0][i] = 0.0f;
        transpose_w(gid, da_Wih, g_wt_a, dyn);
        bar_arrive(g_f_p0a, gid, bp0 + 1); bar_wait(g_f_p0a, NB_DOC, bp0 + 1);
        phase0_gemm(gid * 2 + half, NB_DOC * 2, half, LD * DTn, 1, p_tok, n_tok,
                    doc_emb, g_wt_a, da_bih, g_gi_a, dyn + half * 2048);
        bar_arrive(g_f_p0a, gid, bp0 + 2); bar_wait(g_f_p0a, NB_DOC, bp0 + 2);
        run_doc(gid, da_Whh, da_bhh, g_gi_a, g_ha[0], g_ha[1], g_f_ra, brr, red, dyn);
    } else if (bid < 96) {
        int gid = bid - 64;
        unsigned bp0 = rd_base(g_f_p0t, gid);
        unsigned brr = rd_base(g_f_rt, gid);
        if (gid == 0)
            for (int i = tid; i < Qn * Hn; i += NTHR) g_hq[0][i] = 0.0f;
        transpose_w(gid, term_Wih, g_wt_q, dyn);
        bar_arrive(g_f_p0t, gid, bp0 + 1); bar_wait(g_f_p0t, NB_TRM, bp0 + 1);
        phase0_gemm(gid * 2 + half, NB_TRM * 2, half, LQ * Qn, 0, q_tok, (const int*)0,
                    term_emb, g_wt_q, term_bih, g_gi_q, dyn + half * 2048);
        bar_arrive(g_f_p0t, gid, bp0 + 2); bar_wait(g_f_p0t, NB_TRM, bp0 + 2);
        run_term(gid, term_Whh, term_bhh, g_f_rt, brr, red, dyn);
    } else if (bid < 116) {
        int gid = bid - 96 + 32;
        unsigned bp0 = rd_base(g_f_p0c, gid);
        bar_arrive(g_f_p0c, gid, bp0 + 1); bar_wait(g_f_p0c, NB_DOC, bp0 + 1);
        phase0_gemm(gid * 2 + half, NB_DOC * 2, half, LD * DTn, 1, p_tok, n_tok,
                    doc_emb, g_wt_c, dc_bih, g_gi_c, dyn + half * 2048);
        bar_arrive(g_f_p0c, gid, bp0 + 2);
    } else if (bid < 136) {
        int gid = bid - 116 + 32;
        unsigned bp0 = rd_base(g_f_p0a, gid);
        bar_arrive(g_f_p0a, gid, bp0 + 1); bar_wait(g_f_p0a, NB_DOC, bp0 + 1);
        phase0_gemm(gid * 2 + half, NB_DOC * 2, half, LD * DTn, 1, p_tok, n_tok,
                    doc_emb, g_wt_a, da_bih, g_gi_a, dyn + half * 2048);
        bar_arrive(g_f_p0a, gid, bp0 + 2);
    } else {
        int gid = bid - 136 + 32;
        unsigned bp0 = rd_base(g_f_p0t, gid);
        bar_arrive(g_f_p0t, gid, bp0 + 1); bar_wait(g_f_p0t, NB_TRM, bp0 + 1);
        phase0_gemm(gid * 2 + half, NB_TRM * 2, half, LQ * Qn, 0, q_tok, (const int*)0,
                    term_emb, g_wt_q, term_bih, g_gi_q, dyn + half * 2048);
        bar_arrive(g_f_p0t, gid, bp0 + 2);
    }

    bar_arrive(g_f_all, bid, ball + 1); bar_wait(g_f_all, NBLK, ball + 1);

    // ---- phase A: position dense (blocks 0..23) ----
    if (bid < DTn) {
        float* hrow = ws;
        if (tid < 256) hrow[tid] = __ldcg(&g_hc[0][bid * Hn + tid]);
        __syncthreads();
        if (tid < 256) {
            int dset = bid % DSET;
            float pe0 = __ldg(&pos_table[dset * 4 + 0]);
            float pe1 = __ldg(&pos_table[dset * 4 + 1]);
            float pe2 = __ldg(&pos_table[dset * 4 + 2]);
            float pe3 = __ldg(&pos_table[dset * 4 + 3]);
            int j = tid;
            const float* wrow = posd_W + (size_t)j * (Hn + 4);
            unsigned xsa = sptr(hrow);
            u64 acc = pk(0.0f, 0.0f);
            #pragma unroll 4
            for (int ii = 0; ii < 64; ii++) {
                u64 w01, w23, x01, x23;
                ldg2(w01, w23, wrow + (ii << 2));
                lds2(x01, x23, xsa + (ii << 4));
                ffma2(acc, w01, x01);
                ffma2(acc, w23, x23);
            }
            float a = uns(acc);
            a = fmaf(pe0, __ldg(wrow + 256), a);
            a = fmaf(pe1, __ldg(wrow + 257), a);
            a = fmaf(pe2, __ldg(wrow + 258), a);
            a = fmaf(pe3, __ldg(wrow + 259), a);
            a += __ldg(&posd_b[j]);
            g_attc[bid * Hn + j] = a;
        }
    } else if (bid >= 32 && bid < 96) {
        // ---- phase B: attention scores ----
        int q = bid - 32;
        float* eq = ws;
        if (tid < 256) eq[tid] = __ldcg(&g_hq[0][q * Hn + tid]);
        __syncthreads();
        if (tid < DTn) {
            const float4* ap = (const float4*)(g_ha[0] + tid * Hn);
            const float4* e4 = (const float4*)eq;
            float acc = 0.0f;
            #pragma unroll 4
            for (int ii = 0; ii < 64; ii++) {
                float4 a4 = __ldcg(ap + ii);
                float4 x4 = e4[ii];
                acc = fmaf(a4.x, x4.x, acc);
                acc = fmaf(a4.y, x4.y, acc);
                acc = fmaf(a4.z, x4.z, acc);
                acc = fmaf(a4.w, x4.w, acc);
            }
            g_scores[q * DTn + tid] = acc;
        }
    }

    bar_arrive(g_f_all, bid, ball + 2); bar_wait(g_f_all, NBLK, ball + 2);

    // ---- phase C: softmax + memory read + final GRU (blocks 0..63) ----
    if (bid < Qn) {
        int q = bid;
        float* sv = ws;
        float* wv = ws + 32;
        float* qs = ws + 64;
        if (tid < DTn) sv[tid] = __ldcg(&g_scores[q * DTn + tid]);
        __syncthreads();
        if (tid < 2) {
            int off = tid * DSET;
            float mx = -1e30f;
            for (int d2 = 0; d2 < DSET; d2++) mx = fmaxf(mx, sv[off + d2]);
            float s = 0.0f;
            for (int d2 = 0; d2 < DSET; d2++) {
                float e = __expf(sv[off + d2] - mx);
                wv[off + d2] = e;
                s += e;
            }
            float inv = 1.0f / s;
            for (int d2 = 0; d2 < DSET; d2++) wv[off + d2] *= inv;
        }
        __syncthreads();
        if (tid < 256) {
            int j = tid;
            float val = __ldcg(&g_hq[0][q * Hn + j]);
            #pragma unroll
            for (int d2 = 0; d2 < DSET; d2++)
                val = fmaf(wv[d2], __ldcg(&g_attc[d2 * Hn + j]), val);
            #pragma unroll
            for (int d2 = 0; d2 < DSET; d2++)
                val = fmaf(wv[DSET + d2], __ldcg(&g_attc[(DSET + d2) * Hn + j]), val);
            qs[j] = val;
        }
        __syncthreads();
        if (tid < 256) {
            int j = tid;
            u64 dr = pk(0.0f, 0.0f), dz = pk(0.0f, 0.0f), dn = pk(0.0f, 0.0f);
            unsigned qsa = sptr(qs);
            const float* wr = qy_Wih + (size_t)j * Hn;
            const float* wz = qy_Wih + (size_t)(Hn + j) * Hn;
            const float* wn = qy_Wih + (size_t)(2 * Hn + j) * Hn;
            #pragma unroll 4
            for (int ii = 0; ii < 64; ii++) {
                u64 x01, x23, w01, w23;
                lds2(x01, x23, qsa + (ii << 4));
                ldg2(w01, w23, wr + (ii << 2));
                ffma2(dr, w01, x01); ffma2(dr, w23, x23);
                ldg2(w01, w23, wz + (ii << 2));
                ffma2(dz, w01, x01); ffma2(dz, w23, x23);
                ldg2(w01, w23, wn + (ii << 2));
                ffma2(dn, w01, x01); ffma2(dn, w23, x23);
            }
            float r = sigm(uns(dr) + __ldg(&qy_bih[j]) + __ldg(&qy_bhh[j]));
            float z = sigm(uns(dz) + __ldg(&qy_bih[Hn + j]) + __ldg(&qy_bhh[Hn + j]));
            float n = tanhf(uns(dn) + __ldg(&qy_bih[2 * Hn + j]) + r * __ldg(&qy_bhh[2 * Hn + j]));
            out[q * Hn + j] = (1.0f - z) * n;
        }
    }
}

extern "C" void kernel_launch(void* const* d_in, const int* in_sizes, int n_in,
                              void* d_out, int out_size) {
    const int*   q_tok    = (const int*)d_in[0];
    const int*   p_tok    = (const int*)d_in[1];
    const int*   n_tok    = (const int*)d_in[2];
    const float* term_emb = (const float*)d_in[3];
    const float* term_Wih = (const float*)d_in[4];
    const float* term_Whh = (const float*)d_in[5];
    const float* term_bih = (const float*)d_in[6];
    const float* term_bhh = (const float*)d_in[7];
    const float* doc_emb  = (const float*)d_in[8];
    const float* dc_Wih   = (const float*)d_in[9];
    const float* dc_Whh   = (const float*)d_in[10];
    const float* dc_bih   = (const float*)d_in[11];
    const float* dc_bhh   = (const float*)d_in[12];
    const float* da_Wih   = (const float*)d_in[13];
    const float* da_Whh   = (const float*)d_in[14];
    const float* da_bih   = (const float*)d_in[15];
    const float* da_bhh   = (const float*)d_in[16];
    const float* pos_tab  = (const float*)d_in[17];
    const float* posd_W   = (const float*)d_in[18];
    const float* posd_b   = (const float*)d_in[19];
    const float* qy_Wih   = (const float*)d_in[20];
    const float* qy_Whh   = (const float*)d_in[21];
    const float* qy_bih   = (const float*)d_in[22];
    const float* qy_bhh   = (const float*)d_in[23];
    float* out = (float*)d_out;

    const int dyn_bytes = 64 * HSTR * 4;
    cudaFuncSetAttribute(fmn_kernel, cudaFuncAttributeMaxDynamicSharedMemorySize, dyn_bytes);
    fmn_kernel<<<NBLK, NTHR, dyn_bytes>>>(q_tok, p_tok, n_tok,
                            term_emb, term_Wih, term_Whh, term_bih, term_bhh,
                            doc_emb, dc_Wih, dc_Whh, dc_bih, dc_bhh,
                            da_Wih, da_Whh, da_bih, da_bhh,
                            pos_tab, posd_W, posd_b,
                            qy_Wih, qy_Whh, qy_bih, qy_bhh,
                            out);
}

// round 13
// speedup vs baseline: 1.1024x; 1.0229x over previous
#include <cuda_runtime.h>

typedef unsigned long long u64;

#define Qn   64
#define LQ   20
#define DSET 12
#define DTn  24
#define LD   50
#define Hn   256
#define G3   768
#define HSTR 260
#define NB_DOC 52
#define NB_TRM 40
#define NBLK 144
#define NTHR 512

// ---------------- device scratch ----------------
__device__ float g_gi_q[LQ * Qn * G3];
__device__ float g_gi_c[LD * DTn * G3];
__device__ float g_gi_a[LD * DTn * G3];
__device__ float4 g_wt_c[64 * G3];     // k-major Wih (phase0)
__device__ float4 g_wt_a[64 * G3];
__device__ float4 g_wt_q[64 * G3];
__device__ float g_hq[2][Qn * Hn];
__device__ float g_hc[2][DTn * Hn];
__device__ float g_ha[2][DTn * Hn];
__device__ float g_attc[DTn * Hn];
__device__ float g_scores[Qn * DTn];
__device__ unsigned g_f_p0c[NB_DOC * 32];
__device__ unsigned g_f_p0a[NB_DOC * 32];
__device__ unsigned g_f_p0t[NB_TRM * 32];
__device__ unsigned g_f_rc[32 * 32];
__device__ unsigned g_f_ra[32 * 32];
__device__ unsigned g_f_rt[32 * 32];
__device__ unsigned g_f_all[NBLK * 32];

// ---------------- helpers ----------------
__device__ __forceinline__ float sigm(float x) { return 1.0f / (1.0f + __expf(-x)); }
__device__ __forceinline__ u64 pk(float lo, float hi) {
    u64 r; asm("mov.b64 %0, {%1,%2};" : "=l"(r) : "f"(lo), "f"(hi)); return r;
}
__device__ __forceinline__ float uns(u64 v) {
    float lo, hi; asm("mov.b64 {%0,%1}, %2;" : "=f"(lo), "=f"(hi) : "l"(v));
    return lo + hi;
}
__device__ __forceinline__ void ffma2(u64& d, u64 a, u64 b) {
    asm("fma.rn.f32x2 %0, %1, %2, %0;" : "+l"(d) : "l"(a), "l"(b));
}
__device__ __forceinline__ unsigned sptr(const void* p) {
    return (unsigned)__cvta_generic_to_shared(p);
}
__device__ __forceinline__ void lds2(u64& a, u64& b, unsigned addr) {
    asm volatile("ld.shared.v2.u64 {%0,%1}, [%2];" : "=l"(a), "=l"(b) : "r"(addr));
}
__device__ __forceinline__ void ldg2(u64& a, u64& b, const float* p) {
    asm volatile("ld.global.nc.v2.u64 {%0,%1}, [%2];" : "=l"(a), "=l"(b) : "l"(p));
}
__device__ __forceinline__ void barh(int h) {
    asm volatile("bar.sync %0, %1;" :: "r"(1 + h), "r"(256) : "memory");
}

// ---- flag barrier ----
__device__ __forceinline__ void bar_arrive(unsigned* fl, int idx, unsigned gen) {
    __syncthreads();
    if (threadIdx.x == 0)
        asm volatile("st.release.gpu.global.u32 [%0], %1;"
                     :: "l"(fl + idx * 32), "r"(gen) : "memory");
}
__device__ __forceinline__ void bar_wait(unsigned* fl, int n, unsigned gen) {
    if (threadIdx.x < (unsigned)n) {
        unsigned cur;
        do {
            asm volatile("ld.acquire.gpu.global.u32 %0, [%1];"
                         : "=r"(cur) : "l"(fl + threadIdx.x * 32) : "memory");
        } while (cur < gen);
    }
    __syncthreads();
}
__device__ __forceinline__ unsigned rd_base(unsigned* fl, int idx) {
    return *(volatile unsigned*)(fl + idx * 32);
}

// ---------------- W transpose: W[768][256] -> Wt[64][768] float4 ----------------
__device__ void transpose_w(int gid, const float* __restrict__ W, float4* __restrict__ Wt,
                            float* sbuf)
{
    int tid = threadIdx.x;
    int r0 = gid * 24;
    for (int i = tid; i < 24 * 256; i += NTHR) {
        int rl = i >> 8, j = i & 255;
        sbuf[rl * 260 + j] = __ldg(W + (size_t)(r0 + rl) * Hn + j);
    }
    __syncthreads();
    for (int i = tid; i < 24 * 64; i += NTHR) {
        int rl = i % 24, kk = i / 24;
        float4 v = *(float4*)(sbuf + rl * 260 + (kk << 2));
        Wt[kk * G3 + r0 + rl] = v;
    }
    __syncthreads();
}

// ---------------- phase 0 (one 256-thread half = one virtual block) ----------------
__device__ void phase0_gemm(int vgid, int nv, int half, int R, int mode,
                            const int* __restrict__ tokA, const int* __restrict__ tokB,
                            const float* __restrict__ emb, const float4* __restrict__ Wt,
                            const float* __restrict__ bias, float* __restrict__ gi,
                            float* xs)
{
    int th = threadIdx.x & 255;
    int rpb = (R + nv - 1) / nv;
    int r0 = vgid * rpb;
    int r1 = min(R, r0 + rpb);
    unsigned xsa = sptr(xs);
    float b0 = __ldg(bias + th), b1 = __ldg(bias + th + 256), b2 = __ldg(bias + th + 512);

    for (int rt = r0; rt < r1; rt += 8) {
        int nr = min(8, r1 - rt);
        barh(half);
        for (int idx = th; idx < (nr << 8); idx += 256) {
            int rl = idx >> 8, j = idx & 255;
            int r = rt + rl;
            int tok;
            if (mode == 0) {
                int t = r >> 6, q = r & 63;
                tok = tokA[q * LQ + t];
            } else {
                int t = r / DTn, dt = r - t * DTn;
                tok = (dt < DSET) ? tokA[dt * LD + t] : tokB[(dt - DSET) * LD + t];
            }
            xs[(rl << 8) + j] = __ldg(emb + (size_t)tok * Hn + j);
        }
        barh(half);

        u64 acc[3][8];
        #pragma unroll
        for (int rl = 0; rl < 8; rl++) {
            acc[0][rl] = pk(b0, 0.0f);
            acc[1][rl] = pk(b1, 0.0f);
            acc[2][rl] = pk(b2, 0.0f);
        }
        #pragma unroll 2
        for (int jj = 0; jj < 64; jj++) {
            const float* wp = (const float*)(Wt + jj * G3 + th);
            u64 w0a, w0b, w1a, w1b, w2a, w2b;
            ldg2(w0a, w0b, wp);
            ldg2(w1a, w1b, wp + 1024);
            ldg2(w2a, w2b, wp + 2048);
            unsigned xo = xsa + (jj << 4);
            #pragma unroll
            for (int rlb = 0; rlb < 2; rlb++) {
                u64 x01[4], x23[4];
                #pragma unroll
                for (int rl = 0; rl < 4; rl++)
                    lds2(x01[rl], x23[rl], xo + ((rlb * 4 + rl) << 10));
                #pragma unroll
                for (int rl = 0; rl < 4; rl++) {
                    int ri = rlb * 4 + rl;
                    ffma2(acc[0][ri], w0a, x01[rl]); ffma2(acc[0][ri], w0b, x23[rl]);
                    ffma2(acc[1][ri], w1a, x01[rl]); ffma2(acc[1][ri], w1b, x23[rl]);
                    ffma2(acc[2][ri], w2a, x01[rl]); ffma2(acc[2][ri], w2b, x23[rl]);
                }
            }
        }
        for (int rl = 0; rl < nr; rl++) {
            float* gr = gi + (size_t)(rt + rl) * G3 + th;
            gr[0]   = uns(acc[0][rl]);
            gr[256] = uns(acc[1][rl]);
            gr[512] = uns(acc[2][rl]);
        }
    }
}

// ---------------- doc recurrence: weights in registers, dense LDS, shfl reduce ----------------
// warp: c = wid&7 (column), kq = wid>>3 (k-half of 128)
// lane: ko = lane&7 (16 k each), dgrp = lane>>3 (4 docs per batch, 6 batches)
__device__ void run_doc(int cb, const float* __restrict__ Whh, const float* __restrict__ bhh,
                        const float* __restrict__ gi, float* hb0, float* hb1,
                        unsigned* fl, unsigned fbase, float* red, float* hst)
{
    int tid = threadIdx.x;
    int cbase = cb << 3;
    int wid = tid >> 5, lane = tid & 31;
    int c = wid & 7, kq = wid >> 3;
    int ko = lane & 7, dgrp = lane >> 3;
    int j = cbase + c;
    int kbase = kq * 128 + ko * 16;

    u64 W[3][8];
    #pragma unroll
    for (int g = 0; g < 3; g++) {
        const float* wr = Whh + (size_t)(g * Hn + j) * Hn + kbase;
        #pragma unroll
        for (int i = 0; i < 4; i++)
            ldg2(W[g][i * 2], W[g][i * 2 + 1], wr + i * 4);
    }

    int fc = tid & 7, fd = tid >> 3;        // finalize role (tid<192)
    bool fin = (tid < 192);
    int fj = cbase + fc;
    float br = 0.f, bz = 0.f, bn = 0.f;
    if (fin) {
        br = __ldg(bhh + fj); bz = __ldg(bhh + Hn + fj); bn = __ldg(bhh + 2 * Hn + fj);
    }
    unsigned hbaseA = sptr(hst);
    int redw = ((kq << 3) + c) * 24;        // write base row (per warp)
    float* hb[2] = { hb0, hb1 };

    for (int t = 0; t < LD; t++) {
        const float4* hg = (const float4*)hb[t & 1];
        float* hn_ = hb[(t & 1) ^ 1];
        #pragma unroll
        for (int i = 0; i < 3; i++) {
            int idx = tid + (i << 9);          // < 1536 float4
            int row = idx >> 6, col = idx & 63;
            float4 v = __ldcg(hg + idx);
            *(float4*)(hst + row * HSTR + (col << 2)) = v;
        }
        float gr = 0.f, gz = 0.f, gn = 0.f;
        if (fin) {
            const float* gib = gi + ((size_t)t * DTn + fd) * G3;
            gr = __ldg(gib + fj); gz = __ldg(gib + Hn + fj); gn = __ldg(gib + 2 * Hn + fj);
        }
        __syncthreads();
        #pragma unroll
        for (int db = 0; db < 6; db++) {
            int d = db * 4 + dgrp;
            unsigned ha = hbaseA + ((unsigned)(d * HSTR + kbase) << 2);
            u64 h0, h1, h2, h3, h4, h5, h6, h7;
            lds2(h0, h1, ha);      lds2(h2, h3, ha + 16);
            lds2(h4, h5, ha + 32); lds2(h6, h7, ha + 48);
            u64 a0 = pk(0.f, 0.f), a1 = pk(0.f, 0.f), a2 = pk(0.f, 0.f);
            ffma2(a0, W[0][0], h0); ffma2(a0, W[0][1], h1); ffma2(a0, W[0][2], h2); ffma2(a0, W[0][3], h3);
            ffma2(a0, W[0][4], h4); ffma2(a0, W[0][5], h5); ffma2(a0, W[0][6], h6); ffma2(a0, W[0][7], h7);
            ffma2(a1, W[1][0], h0); ffma2(a1, W[1][1], h1); ffma2(a1, W[1][2], h2); ffma2(a1, W[1][3], h3);
            ffma2(a1, W[1][4], h4); ffma2(a1, W[1][5], h5); ffma2(a1, W[1][6], h6); ffma2(a1, W[1][7], h7);
            ffma2(a2, W[2][0], h0); ffma2(a2, W[2][1], h1); ffma2(a2, W[2][2], h2); ffma2(a2, W[2][3], h3);
            ffma2(a2, W[2][4], h4); ffma2(a2, W[2][5], h5); ffma2(a2, W[2][6], h6); ffma2(a2, W[2][7], h7);
            float s0 = uns(a0), s1 = uns(a1), s2 = uns(a2);
            #pragma unroll
            for (int m = 1; m < 8; m <<= 1) {
                s0 += __shfl_xor_sync(0xffffffffu, s0, m);
                s1 += __shfl_xor_sync(0xffffffffu, s1, m);
                s2 += __shfl_xor_sync(0xffffffffu, s2, m);
            }
            if (ko == 0) {
                float* rp = red + (redw + d) * 3;
                rp[0] = s0; rp[1] = s1; rp[2] = s2;
            }
        }
        __syncthreads();
        if (fin) {
            const float* r0 = red + (fc * 24 + fd) * 3;          // kq=0
            const float* r1 = red + ((64 + fc * 24 + fd) * 3) + 8; // placeholder avoided
            r1 = red + ((8 + fc) * 24 + fd) * 3;                  // kq=1
            float rr = sigm(gr + r0[0] + r1[0] + br);
            float zz = sigm(gz + r0[1] + r1[1] + bz);
            float nn = tanhf(gn + rr * (r0[2] + r1[2] + bn));
            float hold = hst[fd * HSTR + fj];
            hn_[(fd << 8) + fj] = (1.0f - zz) * nn + zz * hold;
        }
        bar_arrive(fl, cb, fbase + t + 1);
        bar_wait(fl, 32, fbase + t + 1);
    }
}

// ---------------- term recurrence: same scheme, 64 queries (16 batches) ----------------
__device__ void run_term(int cb, const float* __restrict__ Whh, const float* __restrict__ bhh,
                         unsigned* fl, unsigned fbase, float* red, float* hst)
{
    int tid = threadIdx.x;
    int cbase = cb << 3;
    int wid = tid >> 5, lane = tid & 31;
    int c = wid & 7, kq = wid >> 3;
    int ko = lane & 7, dgrp = lane >> 3;
    int j = cbase + c;
    int kbase = kq * 128 + ko * 16;

    u64 W[3][8];
    #pragma unroll
    for (int g = 0; g < 3; g++) {
        const float* wr = Whh + (size_t)(g * Hn + j) * Hn + kbase;
        #pragma unroll
        for (int i = 0; i < 4; i++)
            ldg2(W[g][i * 2], W[g][i * 2 + 1], wr + i * 4);
    }

    int fc = tid & 7, fq = tid >> 3;        // finalize: all 512 threads, fq<64
    int fj = cbase + fc;
    float br = __ldg(bhh + fj), bz = __ldg(bhh + Hn + fj), bn = __ldg(bhh + 2 * Hn + fj);
    unsigned hbaseA = sptr(hst);
    int redw = ((kq << 3) + c) * 64;

    for (int t = 0; t < LQ; t++) {
        const float4* hg = (const float4*)g_hq[t & 1];
        float* hn_ = g_hq[(t & 1) ^ 1];
        #pragma unroll
        for (int i = 0; i < 8; i++) {
            int idx = tid + (i << 9);          // < 4096 float4
            int row = idx >> 6, col = idx & 63;
            float4 v = __ldcg(hg + idx);
            *(float4*)(hst + row * HSTR + (col << 2)) = v;
        }
        const float* gib = g_gi_q + ((size_t)t * Qn + fq) * G3;
        float gr = __ldg(gib + fj), gz = __ldg(gib + Hn + fj), gn = __ldg(gib + 2 * Hn + fj);
        __syncthreads();
        #pragma unroll 4
        for (int db = 0; db < 16; db++) {
            int q = db * 4 + dgrp;
            unsigned ha = hbaseA + ((unsigned)(q * HSTR + kbase) << 2);
            u64 h0, h1, h2, h3, h4, h5, h6, h7;
            lds2(h0, h1, ha);      lds2(h2, h3, ha + 16);
            lds2(h4, h5, ha + 32); lds2(h6, h7, ha + 48);
            u64 a0 = pk(0.f, 0.f), a1 = pk(0.f, 0.f), a2 = pk(0.f, 0.f);
            ffma2(a0, W[0][0], h0); ffma2(a0, W[0][1], h1); ffma2(a0, W[0][2], h2); ffma2(a0, W[0][3], h3);
            ffma2(a0, W[0][4], h4); ffma2(a0, W[0][5], h5); ffma2(a0, W[0][6], h6); ffma2(a0, W[0][7], h7);
            ffma2(a1, W[1][0], h0); ffma2(a1, W[1][1], h1); ffma2(a1, W[1][2], h2); ffma2(a1, W[1][3], h3);
            ffma2(a1, W[1][4], h4); ffma2(a1, W[1][5], h5); ffma2(a1, W[1][6], h6); ffma2(a1, W[1][7], h7);
            ffma2(a2, W[2][0], h0); ffma2(a2, W[2][1], h1); ffma2(a2, W[2][2], h2); ffma2(a2, W[2][3], h3);
            ffma2(a2, W[2][4], h4); ffma2(a2, W[2][5], h5); ffma2(a2, W[2][6], h6); ffma2(a2, W[2][7], h7);
            float s0 = uns(a0), s1 = uns(a1), s2 = uns(a2);
            #pragma unroll
            for (int m = 1; m < 8; m <<= 1) {
                s0 += __shfl_xor_sync(0xffffffffu, s0, m);
                s1 += __shfl_xor_sync(0xffffffffu, s1, m);
                s2 += __shfl_xor_sync(0xffffffffu, s2, m);
            }
            if (ko == 0) {
                float* rp = red + (redw + q) * 3;
                rp[0] = s0; rp[1] = s1; rp[2] = s2;
            }
        }
        __syncthreads();
        {
            const float* r0 = red + (fc * 64 + fq) * 3;           // kq=0
            const float* r1 = red + ((8 + fc) * 64 + fq) * 3;     // kq=1
            float rr = sigm(gr + r0[0] + r1[0] + br);
            float zz = sigm(gz + r0[1] + r1[1] + bz);
            float nn = tanhf(gn + rr * (r0[2] + r1[2] + bn));
            float hold = hst[fq * HSTR + fj];
            hn_[(fq << 8) + fj] = (1.0f - zz) * nn + zz * hold;
        }
        bar_arrive(fl, cb, fbase + t + 1);
        bar_wait(fl, 32, fbase + t + 1);
    }
}

// ---------------- persistent kernel ----------------
__global__ void __launch_bounds__(NTHR, 1)
fmn_kernel(const int* __restrict__ q_tok, const int* __restrict__ p_tok, const int* __restrict__ n_tok,
           const float* __restrict__ term_emb, const float* __restrict__ term_Wih,
           const float* __restrict__ term_Whh, const float* __restrict__ term_bih,
           const float* __restrict__ term_bhh,
           const float* __restrict__ doc_emb,
           const float* __restrict__ dc_Wih, const float* __restrict__ dc_Whh,
           const float* __restrict__ dc_bih, const float* __restrict__ dc_bhh,
           const float* __restrict__ da_Wih, const float* __restrict__ da_Whh,
           const float* __restrict__ da_bih, const float* __restrict__ da_bhh,
           const float* __restrict__ pos_table, const float* __restrict__ posd_W,
           const float* __restrict__ posd_b,
           const float* __restrict__ qy_Wih, const float* __restrict__ qy_Whh,
           const float* __restrict__ qy_bih, const float* __restrict__ qy_bhh,
           float* __restrict__ out)
{
    __shared__ float ws[24 * 256];
    __shared__ float red[2 * 8 * 64 * 3];
    extern __shared__ float dyn[];
    int bid = blockIdx.x;
    int tid = threadIdx.x;
    int half = tid >> 8;
    unsigned ball = rd_base(g_f_all, bid);

    if (bid < 32) {
        int gid = bid;
        unsigned bp0 = rd_base(g_f_p0c, gid);
        unsigned brr = rd_base(g_f_rc, gid);
        if (gid == 0)
            for (int i = tid; i < DTn * Hn; i += NTHR) g_hc[0][i] = 0.0f;
        transpose_w(gid, dc_Wih, g_wt_c, dyn);
        bar_arrive(g_f_p0c, gid, bp0 + 1); bar_wait(g_f_p0c, NB_DOC, bp0 + 1);
        phase0_gemm(gid * 2 + half, NB_DOC * 2, half, LD * DTn, 1, p_tok, n_tok,
                    doc_emb, g_wt_c, dc_bih, g_gi_c, dyn + half * 2048);
        bar_arrive(g_f_p0c, gid, bp0 + 2); bar_wait(g_f_p0c, NB_DOC, bp0 + 2);
        run_doc(gid, dc_Whh, dc_bhh, g_gi_c, g_hc[0], g_hc[1], g_f_rc, brr, red, dyn);
    } else if (bid < 64) {
        int gid = bid - 32;
        unsigned bp0 = rd_base(g_f_p0a, gid);
        unsigned brr = rd_base(g_f_ra, gid);
        if (gid == 0)
            for (int i = tid; i < DTn * Hn; i += NTHR) g_ha[0][i] = 0.0f;
        transpose_w(gid, da_Wih, g_wt_a, dyn);
        bar_arrive(g_f_p0a, gid, bp0 + 1); bar_wait(g_f_p0a, NB_DOC, bp0 + 1);
        phase0_gemm(gid * 2 + half, NB_DOC * 2, half, LD * DTn, 1, p_tok, n_tok,
                    doc_emb, g_wt_a, da_bih, g_gi_a, dyn + half * 2048);
        bar_arrive(g_f_p0a, gid, bp0 + 2); bar_wait(g_f_p0a, NB_DOC, bp0 + 2);
        run_doc(gid, da_Whh, da_bhh, g_gi_a, g_ha[0], g_ha[1], g_f_ra, brr, red, dyn);
    } else if (bid < 96) {
        int gid = bid - 64;
        unsigned bp0 = rd_base(g_f_p0t, gid);
        unsigned brr = rd_base(g_f_rt, gid);
        if (gid == 0)
            for (int i = tid; i < Qn * Hn; i += NTHR) g_hq[0][i] = 0.0f;
        transpose_w(gid, term_Wih, g_wt_q, dyn);
        bar_arrive(g_f_p0t, gid, bp0 + 1); bar_wait(g_f_p0t, NB_TRM, bp0 + 1);
        phase0_gemm(gid * 2 + half, NB_TRM * 2, half, LQ * Qn, 0, q_tok, (const int*)0,
                    term_emb, g_wt_q, term_bih, g_gi_q, dyn + half * 2048);
        bar_arrive(g_f_p0t, gid, bp0 + 2); bar_wait(g_f_p0t, NB_TRM, bp0 + 2);
        run_term(gid, term_Whh, term_bhh, g_f_rt, brr, red, dyn);
    } else if (bid < 116) {
        int gid = bid - 96 + 32;
        unsigned bp0 = rd_base(g_f_p0c, gid);
        bar_arrive(g_f_p0c, gid, bp0 + 1); bar_wait(g_f_p0c, NB_DOC, bp0 + 1);
        phase0_gemm(gid * 2 + half, NB_DOC * 2, half, LD * DTn, 1, p_tok, n_tok,
                    doc_emb, g_wt_c, dc_bih, g_gi_c, dyn + half * 2048);
        bar_arrive(g_f_p0c, gid, bp0 + 2);
    } else if (bid < 136) {
        int gid = bid - 116 + 32;
        unsigned bp0 = rd_base(g_f_p0a, gid);
        bar_arrive(g_f_p0a, gid, bp0 + 1); bar_wait(g_f_p0a, NB_DOC, bp0 + 1);
        phase0_gemm(gid * 2 + half, NB_DOC * 2, half, LD * DTn, 1, p_tok, n_tok,
                    doc_emb, g_wt_a, da_bih, g_gi_a, dyn + half * 2048);
        bar_arrive(g_f_p0a, gid, bp0 + 2);
    } else {
        int gid = bid - 136 + 32;
        unsigned bp0 = rd_base(g_f_p0t, gid);
        bar_arrive(g_f_p0t, gid, bp0 + 1); bar_wait(g_f_p0t, NB_TRM, bp0 + 1);
        phase0_gemm(gid * 2 + half, NB_TRM * 2, half, LQ * Qn, 0, q_tok, (const int*)0,
                    term_emb, g_wt_q, term_bih, g_gi_q, dyn + half * 2048);
        bar_arrive(g_f_p0t, gid, bp0 + 2);
    }

    bar_arrive(g_f_all, bid, ball + 1); bar_wait(g_f_all, NBLK, ball + 1);

    // ---- phase A: position dense (blocks 0..23) ----
    if (bid < DTn) {
        float* hrow = ws;
        if (tid < 256) hrow[tid] = __ldcg(&g_hc[0][bid * Hn + tid]);
        __syncthreads();
        if (tid < 256) {
            int dset = bid % DSET;
            float pe0 = __ldg(&pos_table[dset * 4 + 0]);
            float pe1 = __ldg(&pos_table[dset * 4 + 1]);
            float pe2 = __ldg(&pos_table[dset * 4 + 2]);
            float pe3 = __ldg(&pos_table[dset * 4 + 3]);
            int j = tid;
            const float* wrow = posd_W + (size_t)j * (Hn + 4);
            unsigned xsa = sptr(hrow);
            u64 acc = pk(0.0f, 0.0f);
            #pragma unroll 4
            for (int ii = 0; ii < 64; ii++) {
                u64 w01, w23, x01, x23;
                ldg2(w01, w23, wrow + (ii << 2));
                lds2(x01, x23, xsa + (ii << 4));
                ffma2(acc, w01, x01);
                ffma2(acc, w23, x23);
            }
            float a = uns(acc);
            a = fmaf(pe0, __ldg(wrow + 256), a);
            a = fmaf(pe1, __ldg(wrow + 257), a);
            a = fmaf(pe2, __ldg(wrow + 258), a);
            a = fmaf(pe3, __ldg(wrow + 259), a);
            a += __ldg(&posd_b[j]);
            g_attc[bid * Hn + j] = a;
        }
    } else if (bid >= 32 && bid < 96) {
        // ---- phase B: attention scores ----
        int q = bid - 32;
        float* eq = ws;
        if (tid < 256) eq[tid] = __ldcg(&g_hq[0][q * Hn + tid]);
        __syncthreads();
        if (tid < DTn) {
            const float4* ap = (const float4*)(g_ha[0] + tid * Hn);
            const float4* e4 = (const float4*)eq;
            float acc = 0.0f;
            #pragma unroll 4
            for (int ii = 0; ii < 64; ii++) {
                float4 a4 = __ldcg(ap + ii);
                float4 x4 = e4[ii];
                acc = fmaf(a4.x, x4.x, acc);
                acc = fmaf(a4.y, x4.y, acc);
                acc = fmaf(a4.z, x4.z, acc);
                acc = fmaf(a4.w, x4.w, acc);
            }
            g_scores[q * DTn + tid] = acc;
        }
    }

    bar_arrive(g_f_all, bid, ball + 2); bar_wait(g_f_all, NBLK, ball + 2);

    // ---- phase C: softmax + memory read + final GRU (blocks 0..63) ----
    if (bid < Qn) {
        int q = bid;
        float* sv = ws;
        float* wv = ws + 32;
        float* qs = ws + 64;
        if (tid < DTn) sv[tid] = __ldcg(&g_scores[q * DTn + tid]);
        __syncthreads();
        if (tid < 2) {
            int off = tid * DSET;
            float mx = -1e30f;
            for (int d2 = 0; d2 < DSET; d2++) mx = fmaxf(mx, sv[off + d2]);
            float s = 0.0f;
            for (int d2 = 0; d2 < DSET; d2++) {
                float e = __expf(sv[off + d2] - mx);
                wv[off + d2] = e;
                s += e;
            }
            float inv = 1.0f / s;
            for (int d2 = 0; d2 < DSET; d2++) wv[off + d2] *= inv;
        }
        __syncthreads();
        if (tid < 256) {
            int j = tid;
            float val = __ldcg(&g_hq[0][q * Hn + j]);
            #pragma unroll
            for (int d2 = 0; d2 < DSET; d2++)
                val = fmaf(wv[d2], __ldcg(&g_attc[d2 * Hn + j]), val);
            #pragma unroll
            for (int d2 = 0; d2 < DSET; d2++)
                val = fmaf(wv[DSET + d2], __ldcg(&g_attc[(DSET + d2) * Hn + j]), val);
            qs[j] = val;
        }
        __syncthreads();
        if (tid < 256) {
            int j = tid;
            u64 dr = pk(0.0f, 0.0f), dz = pk(0.0f, 0.0f), dn = pk(0.0f, 0.0f);
            unsigned qsa = sptr(qs);
            const float* wr = qy_Wih + (size_t)j * Hn;
            const float* wz = qy_Wih + (size_t)(Hn + j) * Hn;
            const float* wn = qy_Wih + (size_t)(2 * Hn + j) * Hn;
            #pragma unroll 4
            for (int ii = 0; ii < 64; ii++) {
                u64 x01, x23, w01, w23;
                lds2(x01, x23, qsa + (ii << 4));
                ldg2(w01, w23, wr + (ii << 2));
                ffma2(dr, w01, x01); ffma2(dr, w23, x23);
                ldg2(w01, w23, wz + (ii << 2));
                ffma2(dz, w01, x01); ffma2(dz, w23, x23);
                ldg2(w01, w23, wn + (ii << 2));
                ffma2(dn, w01, x01); ffma2(dn, w23, x23);
            }
            float r = sigm(uns(dr) + __ldg(&qy_bih[j]) + __ldg(&qy_bhh[j]));
            float z = sigm(uns(dz) + __ldg(&qy_bih[Hn + j]) + __ldg(&qy_bhh[Hn + j]));
            float n = tanhf(uns(dn) + __ldg(&qy_bih[2 * Hn + j]) + r * __ldg(&qy_bhh[2 * Hn + j]));
            out[q * Hn + j] = (1.0f - z) * n;
        }
    }
}

extern "C" void kernel_launch(void* const* d_in, const int* in_sizes, int n_in,
                              void* d_out, int out_size) {
    const int*   q_tok    = (const int*)d_in[0];
    const int*   p_tok    = (const int*)d_in[1];
    const int*   n_tok    = (const int*)d_in[2];
    const float* term_emb = (const float*)d_in[3];
    const float* term_Wih = (const float*)d_in[4];
    const float* term_Whh = (const float*)d_in[5];
    const float* term_bih = (const float*)d_in[6];
    const float* term_bhh = (const float*)d_in[7];
    const float* doc_emb  = (const float*)d_in[8];
    const float* dc_Wih   = (const float*)d_in[9];
    const float* dc_Whh   = (const float*)d_in[10];
    const float* dc_bih   = (const float*)d_in[11];
    const float* dc_bhh   = (const float*)d_in[12];
    const float* da_Wih   = (const float*)d_in[13];
    const float* da_Whh   = (const float*)d_in[14];
    const float* da_bih   = (const float*)d_in[15];
    const float* da_bhh   = (const float*)d_in[16];
    const float* pos_tab  = (const float*)d_in[17];
    const float* posd_W   = (const float*)d_in[18];
    const float* posd_b   = (const float*)d_in[19];
    const float* qy_Wih   = (const float*)d_in[20];
    const float* qy_Whh   = (const float*)d_in[21];
    const float* qy_bih   = (const float*)d_in[22];
    const float* qy_bhh   = (const float*)d_in[23];
    float* out = (float*)d_out;

    const int dyn_bytes = 64 * HSTR * 4;
    cudaFuncSetAttribute(fmn_kernel, cudaFuncAttributeMaxDynamicSharedMemorySize, dyn_bytes);
    fmn_kernel<<<NBLK, NTHR, dyn_bytes>>>(q_tok, p_tok, n_tok,
                            term_emb, term_Wih, term_Whh, term_bih, term_bhh,
                            doc_emb, dc_Wih, dc_Whh, dc_bih, dc_bhh,
                            da_Wih, da_Whh, da_bih, da_bhh,
                            pos_tab, posd_W, posd_b,
                            qy_Wih, qy_Whh, qy_bih, qy_bhh,
                            out);
}

// round 14
// speedup vs baseline: 1.1244x; 1.0199x over previous
#include <cuda_runtime.h>

typedef unsigned long long u64;

#define Qn   64
#define LQ   20
#define DSET 12
#define DTn  24
#define LD   50
#define Hn   256
#define G3   768
#define HSTR 260
#define NB_DC 64
#define NB_DA 64
#define NB_T  16
#define NBLK 144
#define NTHR 512

// ---------------- device scratch ----------------
__device__ float g_gi_q[LQ * Qn * G3];
__device__ float g_gi_c[LD * DTn * G3];
__device__ float g_gi_a[LD * DTn * G3];
__device__ float4 g_wt_c[64 * G3];     // k-major Wih (phase0)
__device__ float4 g_wt_a[64 * G3];
__device__ float4 g_wt_q[64 * G3];
__device__ float g_hq[2][Qn * Hn];
__device__ float g_hc[2][DTn * Hn];
__device__ float g_ha[2][DTn * Hn];
__device__ float g_attc[DTn * Hn];
__device__ float g_scores[Qn * DTn];
__device__ unsigned g_f_p0c[NB_DC * 32];
__device__ unsigned g_f_p0a[NB_DA * 32];
__device__ unsigned g_f_p0t[NB_T * 32];
__device__ unsigned g_f_rc[NB_DC * 32];
__device__ unsigned g_f_ra[NB_DA * 32];
__device__ unsigned g_f_rt[NB_T * 32];
__device__ unsigned g_f_all[NBLK * 32];

// ---------------- helpers ----------------
__device__ __forceinline__ float sigm(float x) { return 1.0f / (1.0f + __expf(-x)); }
__device__ __forceinline__ u64 pk(float lo, float hi) {
    u64 r; asm("mov.b64 %0, {%1,%2};" : "=l"(r) : "f"(lo), "f"(hi)); return r;
}
__device__ __forceinline__ float uns(u64 v) {
    float lo, hi; asm("mov.b64 {%0,%1}, %2;" : "=f"(lo), "=f"(hi) : "l"(v));
    return lo + hi;
}
__device__ __forceinline__ void ffma2(u64& d, u64 a, u64 b) {
    asm("fma.rn.f32x2 %0, %1, %2, %0;" : "+l"(d) : "l"(a), "l"(b));
}
__device__ __forceinline__ unsigned sptr(const void* p) {
    return (unsigned)__cvta_generic_to_shared(p);
}
__device__ __forceinline__ void lds2(u64& a, u64& b, unsigned addr) {
    asm volatile("ld.shared.v2.u64 {%0,%1}, [%2];" : "=l"(a), "=l"(b) : "r"(addr));
}
__device__ __forceinline__ void ldg2(u64& a, u64& b, const float* p) {
    asm volatile("ld.global.nc.v2.u64 {%0,%1}, [%2];" : "=l"(a), "=l"(b) : "l"(p));
}
__device__ __forceinline__ void barh(int h) {
    asm volatile("bar.sync %0, %1;" :: "r"(1 + h), "r"(256) : "memory");
}

// ---- flag barrier ----
__device__ __forceinline__ void bar_arrive(unsigned* fl, int idx, unsigned gen) {
    __syncthreads();
    if (threadIdx.x == 0)
        asm volatile("st.release.gpu.global.u32 [%0], %1;"
                     :: "l"(fl + idx * 32), "r"(gen) : "memory");
}
__device__ __forceinline__ void bar_wait(unsigned* fl, int n, unsigned gen) {
    if (threadIdx.x < (unsigned)n) {
        unsigned cur;
        do {
            asm volatile("ld.acquire.gpu.global.u32 %0, [%1];"
                         : "=r"(cur) : "l"(fl + threadIdx.x * 32) : "memory");
        } while (cur < gen);
    }
    __syncthreads();
}
__device__ __forceinline__ unsigned rd_base(unsigned* fl, int idx) {
    return *(volatile unsigned*)(fl + idx * 32);
}

// ---------------- W transpose: 24 rows of W[768][256] -> Wt[64][768] float4 ----------------
__device__ void transpose_w(int gid, const float* __restrict__ W, float4* __restrict__ Wt,
                            float* sbuf)
{
    int tid = threadIdx.x;
    int r0 = gid * 24;
    for (int i = tid; i < 24 * 256; i += NTHR) {
        int rl = i >> 8, j = i & 255;
        sbuf[rl * 260 + j] = __ldg(W + (size_t)(r0 + rl) * Hn + j);
    }
    __syncthreads();
    for (int i = tid; i < 24 * 64; i += NTHR) {
        int rl = i % 24, kk = i / 24;
        float4 v = *(float4*)(sbuf + rl * 260 + (kk << 2));
        Wt[kk * G3 + r0 + rl] = v;
    }
    __syncthreads();
}

// ---------------- phase 0 (one 256-thread half = one virtual block) ----------------
__device__ void phase0_gemm(int vgid, int nv, int half, int R, int mode,
                            const int* __restrict__ tokA, const int* __restrict__ tokB,
                            const float* __restrict__ emb, const float4* __restrict__ Wt,
                            const float* __restrict__ bias, float* __restrict__ gi,
                            float* xs)
{
    int th = threadIdx.x & 255;
    int rpb = (R + nv - 1) / nv;
    int r0 = vgid * rpb;
    int r1 = min(R, r0 + rpb);
    unsigned xsa = sptr(xs);
    float b0 = __ldg(bias + th), b1 = __ldg(bias + th + 256), b2 = __ldg(bias + th + 512);

    for (int rt = r0; rt < r1; rt += 8) {
        int nr = min(8, r1 - rt);
        barh(half);
        for (int idx = th; idx < (nr << 8); idx += 256) {
            int rl = idx >> 8, j = idx & 255;
            int r = rt + rl;
            int tok;
            if (mode == 0) {
                int t = r >> 6, q = r & 63;
                tok = tokA[q * LQ + t];
            } else {
                int t = r / DTn, dt = r - t * DTn;
                tok = (dt < DSET) ? tokA[dt * LD + t] : tokB[(dt - DSET) * LD + t];
            }
            xs[(rl << 8) + j] = __ldg(emb + (size_t)tok * Hn + j);
        }
        barh(half);

        u64 acc[3][8];
        #pragma unroll
        for (int rl = 0; rl < 8; rl++) {
            acc[0][rl] = pk(b0, 0.0f);
            acc[1][rl] = pk(b1, 0.0f);
            acc[2][rl] = pk(b2, 0.0f);
        }
        #pragma unroll 2
        for (int jj = 0; jj < 64; jj++) {
            const float* wp = (const float*)(Wt + jj * G3 + th);
            u64 w0a, w0b, w1a, w1b, w2a, w2b;
            ldg2(w0a, w0b, wp);
            ldg2(w1a, w1b, wp + 1024);
            ldg2(w2a, w2b, wp + 2048);
            unsigned xo = xsa + (jj << 4);
            #pragma unroll
            for (int rlb = 0; rlb < 2; rlb++) {
                u64 x01[4], x23[4];
                #pragma unroll
                for (int rl = 0; rl < 4; rl++)
                    lds2(x01[rl], x23[rl], xo + ((rlb * 4 + rl) << 10));
                #pragma unroll
                for (int rl = 0; rl < 4; rl++) {
                    int ri = rlb * 4 + rl;
                    ffma2(acc[0][ri], w0a, x01[rl]); ffma2(acc[0][ri], w0b, x23[rl]);
                    ffma2(acc[1][ri], w1a, x01[rl]); ffma2(acc[1][ri], w1b, x23[rl]);
                    ffma2(acc[2][ri], w2a, x01[rl]); ffma2(acc[2][ri], w2b, x23[rl]);
                }
            }
        }
        for (int rl = 0; rl < nr; rl++) {
            float* gr = gi + (size_t)(rt + rl) * G3 + th;
            gr[0]   = uns(acc[0][rl]);
            gr[256] = uns(acc[1][rl]);
            gr[512] = uns(acc[2][rl]);
        }
    }
}

// ---------------- doc recurrence: 64 blocks x 4 cols; warp = 2 cols x 32 k ----------------
// wl = wid&1 (col pair), kq = wid>>1 (k-eighth, 32 k each)
__device__ void run_doc(int cb, const float* __restrict__ Whh, const float* __restrict__ bhh,
                        const float* __restrict__ gi, float* hb0, float* hb1,
                        unsigned* fl, int nbar, unsigned fbase,
                        float* ws, float* red, float* hst)
{
    int tid = threadIdx.x;
    int cbase = cb << 2;                     // 4 cols per block
    // ws rows: [gate*4 + cc][256]
    for (int idx = tid; idx < 12 * 256; idx += NTHR) {
        int rl = idx >> 8, j = idx & 255;
        int gate = rl >> 2, cc = rl & 3;
        ws[idx] = __ldg(Whh + (size_t)(gate * Hn + cbase + cc) * Hn + j);
    }
    int wid = tid >> 5, lane = tid & 31;
    int wl = wid & 1, kq = wid >> 1;         // kq 0..7
    int c0 = wl * 2, c1 = c0 + 1;
    int j0 = cbase + c0, j1 = cbase + c1;
    bool fin = (kq == 0) && (lane < DTn);
    float br0 = 0.f, bz0 = 0.f, bn0 = 0.f, br1 = 0.f, bz1 = 0.f, bn1 = 0.f;
    if (kq == 0) {
        br0 = __ldg(bhh + j0); bz0 = __ldg(bhh + Hn + j0); bn0 = __ldg(bhh + 2 * Hn + j0);
        br1 = __ldg(bhh + j1); bz1 = __ldg(bhh + Hn + j1); bn1 = __ldg(bhh + 2 * Hn + j1);
    }
    unsigned wsa = sptr(ws);
    unsigned kofs = (unsigned)kq * 128;      // 32 floats
    unsigned wA[6];
    #pragma unroll
    for (int g = 0; g < 3; g++) {
        wA[g * 2 + 0] = wsa + ((g * 4 + c0) << 10) + kofs;
        wA[g * 2 + 1] = wsa + ((g * 4 + c1) << 10) + kofs;
    }
    unsigned hA = sptr(hst) + (unsigned)lane * (HSTR * 4) + kofs;
    float* myred = red + (wl * 32 + lane) * 7;   // partial banks stride 64*7
    float* hb[2] = { hb0, hb1 };

    for (int t = 0; t < LD; t++) {
        const float4* hg = (const float4*)hb[t & 1];
        float* hn_ = hb[(t & 1) ^ 1];
        #pragma unroll
        for (int i = 0; i < 3; i++) {
            int idx = tid + (i << 9);
            int row = idx >> 6, col = idx & 63;
            float4 v = __ldcg(hg + idx);
            *(float4*)(hst + row * HSTR + (col << 2)) = v;
        }
        float g_r0 = 0.f, g_z0 = 0.f, g_n0 = 0.f, g_r1 = 0.f, g_z1 = 0.f, g_n1 = 0.f;
        if (fin) {
            const float* gib = gi + ((size_t)t * DTn + lane) * G3;
            g_r0 = __ldg(gib + j0); g_z0 = __ldg(gib + Hn + j0); g_n0 = __ldg(gib + 2 * Hn + j0);
            g_r1 = __ldg(gib + j1); g_z1 = __ldg(gib + Hn + j1); g_n1 = __ldg(gib + 2 * Hn + j1);
        }
        __syncthreads();
        u64 ar0 = pk(br0, 0.f), az0 = pk(bz0, 0.f), an0 = pk(bn0, 0.f);
        u64 ar1 = pk(br1, 0.f), az1 = pk(bz1, 0.f), an1 = pk(bn1, 0.f);
        #pragma unroll
        for (int jj = 0; jj < 8; jj++) {
            unsigned off = jj << 4;
            u64 h01, h23, w01, w23;
            lds2(h01, h23, hA + off);
            lds2(w01, w23, wA[0] + off);
            ffma2(ar0, w01, h01); ffma2(ar0, w23, h23);
            lds2(w01, w23, wA[1] + off);
            ffma2(ar1, w01, h01); ffma2(ar1, w23, h23);
            lds2(w01, w23, wA[2] + off);
            ffma2(az0, w01, h01); ffma2(az0, w23, h23);
            lds2(w01, w23, wA[3] + off);
            ffma2(az1, w01, h01); ffma2(az1, w23, h23);
            lds2(w01, w23, wA[4] + off);
            ffma2(an0, w01, h01); ffma2(an0, w23, h23);
            lds2(w01, w23, wA[5] + off);
            ffma2(an1, w01, h01); ffma2(an1, w23, h23);
        }
        if (kq > 0) {
            float* rp = myred + (kq - 1) * (64 * 7);
            rp[0] = uns(ar0); rp[1] = uns(ar1);
            rp[2] = uns(az0); rp[3] = uns(az1);
            rp[4] = uns(an0); rp[5] = uns(an1);
        }
        __syncthreads();
        if (fin) {
            float sr0 = uns(ar0), sr1 = uns(ar1);
            float sz0 = uns(az0), sz1 = uns(az1);
            float sn0 = uns(an0), sn1 = uns(an1);
            #pragma unroll
            for (int p = 0; p < 7; p++) {
                float* rp = myred + p * (64 * 7);
                sr0 += rp[0]; sr1 += rp[1];
                sz0 += rp[2]; sz1 += rp[3];
                sn0 += rp[4]; sn1 += rp[5];
            }
            float r0 = sigm(g_r0 + sr0);
            float r1 = sigm(g_r1 + sr1);
            float z0 = sigm(g_z0 + sz0);
            float z1 = sigm(g_z1 + sz1);
            float n0 = tanhf(g_n0 + r0 * sn0);
            float n1 = tanhf(g_n1 + r1 * sn1);
            float ho0 = hst[lane * HSTR + j0];
            float ho1 = hst[lane * HSTR + j1];
            hn_[(lane << 8) + j0] = (1.0f - z0) * n0 + z0 * ho0;
            hn_[(lane << 8) + j1] = (1.0f - z1) * n1 + z1 * ho1;
        }
        bar_arrive(fl, cb, fbase + t + 1);
        bar_wait(fl, nbar, fbase + t + 1);
    }
}

// ---------------- term recurrence: 16 blocks x 16 cols; warp = 2 cols x 128 k ----------------
// wl = wid&7 (col pair), kq = wid>>3 (k-half)
__device__ void run_term(int cb, const float* __restrict__ Whh, const float* __restrict__ bhh,
                         unsigned* fl, unsigned fbase, float* ws, float* red, float* hst)
{
    int tid = threadIdx.x;
    int cbase = cb << 4;                     // 16 cols per block
    for (int idx = tid; idx < 48 * 256; idx += NTHR) {
        int rl = idx >> 8, j = idx & 255;
        int gate = rl >> 4, cc = rl & 15;
        ws[idx] = __ldg(Whh + (size_t)(gate * Hn + cbase + cc) * Hn + j);
    }
    int wid = tid >> 5, lane = tid & 31;
    int wl = wid & 7, kq = wid >> 3;         // kq 0..1
    int c0 = wl * 2, c1 = c0 + 1;
    int j0 = cbase + c0, j1 = cbase + c1;
    float br0 = 0.f, bz0 = 0.f, bn0 = 0.f, br1 = 0.f, bz1 = 0.f, bn1 = 0.f;
    if (kq == 0) {
        br0 = __ldg(bhh + j0); bz0 = __ldg(bhh + Hn + j0); bn0 = __ldg(bhh + 2 * Hn + j0);
        br1 = __ldg(bhh + j1); bz1 = __ldg(bhh + Hn + j1); bn1 = __ldg(bhh + 2 * Hn + j1);
    }
    unsigned wsa = sptr(ws);
    unsigned kofs = (unsigned)kq * 512;      // 128 floats
    unsigned wA[6];
    #pragma unroll
    for (int g = 0; g < 3; g++) {
        wA[g * 2 + 0] = wsa + ((g * 16 + c0) << 10) + kofs;
        wA[g * 2 + 1] = wsa + ((g * 16 + c1) << 10) + kofs;
    }
    unsigned h0A = sptr(hst) + (unsigned)lane * (HSTR * 4) + kofs;
    unsigned h1A = sptr(hst) + (unsigned)(lane + 32) * (HSTR * 4) + kofs;
    float* myred = red + (wl * 32 + lane) * 13;  // 256 slots, single partial bank

    for (int t = 0; t < LQ; t++) {
        const float4* hg = (const float4*)g_hq[t & 1];
        float* hn_ = g_hq[(t & 1) ^ 1];
        #pragma unroll
        for (int i = 0; i < 8; i++) {
            int idx = tid + (i << 9);
            int row = idx >> 6, col = idx & 63;
            float4 v = __ldcg(hg + idx);
            *(float4*)(hst + row * HSTR + (col << 2)) = v;
        }
        int q0 = lane, q1 = lane + 32;
        float gr00 = 0.f, gz00 = 0.f, gn00 = 0.f, gr01 = 0.f, gz01 = 0.f, gn01 = 0.f;
        float gr10 = 0.f, gz10 = 0.f, gn10 = 0.f, gr11 = 0.f, gz11 = 0.f, gn11 = 0.f;
        if (kq == 0) {
            const float* gA = g_gi_q + ((size_t)t * Qn + q0) * G3;
            const float* gB = g_gi_q + ((size_t)t * Qn + q1) * G3;
            gr00 = __ldg(gA + j0); gz00 = __ldg(gA + Hn + j0); gn00 = __ldg(gA + 2 * Hn + j0);
            gr01 = __ldg(gA + j1); gz01 = __ldg(gA + Hn + j1); gn01 = __ldg(gA + 2 * Hn + j1);
            gr10 = __ldg(gB + j0); gz10 = __ldg(gB + Hn + j0); gn10 = __ldg(gB + 2 * Hn + j0);
            gr11 = __ldg(gB + j1); gz11 = __ldg(gB + Hn + j1); gn11 = __ldg(gB + 2 * Hn + j1);
        }
        __syncthreads();
        u64 ar00 = pk(br0, 0.f), az00 = pk(bz0, 0.f), an00 = pk(bn0, 0.f);
        u64 ar01 = pk(br1, 0.f), az01 = pk(bz1, 0.f), an01 = pk(bn1, 0.f);
        u64 ar10 = pk(br0, 0.f), az10 = pk(bz0, 0.f), an10 = pk(bn0, 0.f);
        u64 ar11 = pk(br1, 0.f), az11 = pk(bz1, 0.f), an11 = pk(bn1, 0.f);
        #pragma unroll 4
        for (int jj = 0; jj < 32; jj++) {
            unsigned off = jj << 4;
            u64 h0a, h0b, h1a, h1b, w01, w23;
            lds2(h0a, h0b, h0A + off);
            lds2(h1a, h1b, h1A + off);
            lds2(w01, w23, wA[0] + off);
            ffma2(ar00, w01, h0a); ffma2(ar00, w23, h0b);
            ffma2(ar10, w01, h1a); ffma2(ar10, w23, h1b);
            lds2(w01, w23, wA[1] + off);
            ffma2(ar01, w01, h0a); ffma2(ar01, w23, h0b);
            ffma2(ar11, w01, h1a); ffma2(ar11, w23, h1b);
            lds2(w01, w23, wA[2] + off);
            ffma2(az00, w01, h0a); ffma2(az00, w23, h0b);
            ffma2(az10, w01, h1a); ffma2(az10, w23, h1b);
            lds2(w01, w23, wA[3] + off);
            ffma2(az01, w01, h0a); ffma2(az01, w23, h0b);
            ffma2(az11, w01, h1a); ffma2(az11, w23, h1b);
            lds2(w01, w23, wA[4] + off);
            ffma2(an00, w01, h0a); ffma2(an00, w23, h0b);
            ffma2(an10, w01, h1a); ffma2(an10, w23, h1b);
            lds2(w01, w23, wA[5] + off);
            ffma2(an01, w01, h0a); ffma2(an01, w23, h0b);
            ffma2(an11, w01, h1a); ffma2(an11, w23, h1b);
        }
        if (kq == 1) {
            myred[0]  = uns(ar00); myred[1]  = uns(ar01);
            myred[2]  = uns(az00); myred[3]  = uns(az01);
            myred[4]  = uns(an00); myred[5]  = uns(an01);
            myred[6]  = uns(ar10); myred[7]  = uns(ar11);
            myred[8]  = uns(az10); myred[9]  = uns(az11);
            myred[10] = uns(an10); myred[11] = uns(an11);
        }
        __syncthreads();
        if (kq == 0) {
            float r, z, n, ho;
            r = sigm(gr00 + uns(ar00) + myred[0]);
            z = sigm(gz00 + uns(az00) + myred[2]);
            n = tanhf(gn00 + r * (uns(an00) + myred[4]));
            ho = hst[q0 * HSTR + j0];
            hn_[(q0 << 8) + j0] = (1.0f - z) * n + z * ho;
            r = sigm(gr01 + uns(ar01) + myred[1]);
            z = sigm(gz01 + uns(az01) + myred[3]);
            n = tanhf(gn01 + r * (uns(an01) + myred[5]));
            ho = hst[q0 * HSTR + j1];
            hn_[(q0 << 8) + j1] = (1.0f - z) * n + z * ho;
            r = sigm(gr10 + uns(ar10) + myred[6]);
            z = sigm(gz10 + uns(az10) + myred[8]);
            n = tanhf(gn10 + r * (uns(an10) + myred[10]));
            ho = hst[q1 * HSTR + j0];
            hn_[(q1 << 8) + j0] = (1.0f - z) * n + z * ho;
            r = sigm(gr11 + uns(ar11) + myred[7]);
            z = sigm(gz11 + uns(az11) + myred[9]);
            n = tanhf(gn11 + r * (uns(an11) + myred[11]));
            ho = hst[q1 * HSTR + j1];
            hn_[(q1 << 8) + j1] = (1.0f - z) * n + z * ho;
        }
        bar_arrive(fl, cb, fbase + t + 1);
        bar_wait(fl, NB_T, fbase + t + 1);
    }
}

// ---------------- persistent kernel ----------------
__global__ void __launch_bounds__(NTHR, 1)
fmn_kernel(const int* __restrict__ q_tok, const int* __restrict__ p_tok, const int* __restrict__ n_tok,
           const float* __restrict__ term_emb, const float* __restrict__ term_Wih,
           const float* __restrict__ term_Whh, const float* __restrict__ term_bih,
           const float* __restrict__ term_bhh,
           const float* __restrict__ doc_emb,
           const float* __restrict__ dc_Wih, const float* __restrict__ dc_Whh,
           const float* __restrict__ dc_bih, const float* __restrict__ dc_bhh,
           const float* __restrict__ da_Wih, const float* __restrict__ da_Whh,
           const float* __restrict__ da_bih, const float* __restrict__ da_bhh,
           const float* __restrict__ pos_table, const float* __restrict__ posd_W,
           const float* __restrict__ posd_b,
           const float* __restrict__ qy_Wih, const float* __restrict__ qy_Whh,
           const float* __restrict__ qy_bih, const float* __restrict__ qy_bhh,
           float* __restrict__ out)
{
    __shared__ float ws[48 * 256];
    __shared__ float red[3584];
    extern __shared__ float dyn[];
    int bid = blockIdx.x;
    int tid = threadIdx.x;
    int half = tid >> 8;
    unsigned ball = rd_base(g_f_all, bid);

    if (bid < NB_DC) {                         // doc content GRU
        int gid = bid;
        unsigned bp0 = rd_base(g_f_p0c, gid);
        unsigned brr = rd_base(g_f_rc, gid);
        if (gid == 0)
            for (int i = tid; i < DTn * Hn; i += NTHR) g_hc[0][i] = 0.0f;
        if (gid < 32) transpose_w(gid, dc_Wih, g_wt_c, dyn);
        bar_arrive(g_f_p0c, gid, bp0 + 1); bar_wait(g_f_p0c, NB_DC, bp0 + 1);
        phase0_gemm(gid * 2 + half, NB_DC * 2, half, LD * DTn, 1, p_tok, n_tok,
                    doc_emb, g_wt_c, dc_bih, g_gi_c, dyn + half * 2048);
        bar_arrive(g_f_p0c, gid, bp0 + 2); bar_wait(g_f_p0c, NB_DC, bp0 + 2);
        run_doc(gid, dc_Whh, dc_bhh, g_gi_c, g_hc[0], g_hc[1], g_f_rc, NB_DC, brr, ws, red, dyn);
    } else if (bid < NB_DC + NB_DA) {          // doc attention GRU
        int gid = bid - NB_DC;
        unsigned bp0 = rd_base(g_f_p0a, gid);
        unsigned brr = rd_base(g_f_ra, gid);
        if (gid == 0)
            for (int i = tid; i < DTn * Hn; i += NTHR) g_ha[0][i] = 0.0f;
        if (gid < 32) transpose_w(gid, da_Wih, g_wt_a, dyn);
        bar_arrive(g_f_p0a, gid, bp0 + 1); bar_wait(g_f_p0a, NB_DA, bp0 + 1);
        phase0_gemm(gid * 2 + half, NB_DA * 2, half, LD * DTn, 1, p_tok, n_tok,
                    doc_emb, g_wt_a, da_bih, g_gi_a, dyn + half * 2048);
        bar_arrive(g_f_p0a, gid, bp0 + 2); bar_wait(g_f_p0a, NB_DA, bp0 + 2);
        run_doc(gid, da_Whh, da_bhh, g_gi_a, g_ha[0], g_ha[1], g_f_ra, NB_DA, brr, ws, red, dyn);
    } else {                                   // term GRU
        int gid = bid - NB_DC - NB_DA;         // 0..15
        unsigned bp0 = rd_base(g_f_p0t, gid);
        unsigned brr = rd_base(g_f_rt, gid);
        if (gid == 0)
            for (int i = tid; i < Qn * Hn; i += NTHR) g_hq[0][i] = 0.0f;
        transpose_w(gid * 2, term_Wih, g_wt_q, dyn);
        transpose_w(gid * 2 + 1, term_Wih, g_wt_q, dyn);
        bar_arrive(g_f_p0t, gid, bp0 + 1); bar_wait(g_f_p0t, NB_T, bp0 + 1);
        phase0_gemm(gid * 2 + half, NB_T * 2, half, LQ * Qn, 0, q_tok, (const int*)0,
                    term_emb, g_wt_q, term_bih, g_gi_q, dyn + half * 2048);
        bar_arrive(g_f_p0t, gid, bp0 + 2); bar_wait(g_f_p0t, NB_T, bp0 + 2);
        run_term(gid, term_Whh, term_bhh, g_f_rt, brr, ws, red, dyn);
    }

    bar_arrive(g_f_all, bid, ball + 1); bar_wait(g_f_all, NBLK, ball + 1);

    // ---- phase A: position dense (blocks 0..23) ----
    if (bid < DTn) {
        float* hrow = ws;
        if (tid < 256) hrow[tid] = __ldcg(&g_hc[0][bid * Hn + tid]);
        __syncthreads();
        if (tid < 256) {
            int dset = bid % DSET;
            float pe0 = __ldg(&pos_table[dset * 4 + 0]);
            float pe1 = __ldg(&pos_table[dset * 4 + 1]);
            float pe2 = __ldg(&pos_table[dset * 4 + 2]);
            float pe3 = __ldg(&pos_table[dset * 4 + 3]);
            int j = tid;
            const float* wrow = posd_W + (size_t)j * (Hn + 4);
            unsigned xsa = sptr(hrow);
            u64 acc = pk(0.0f, 0.0f);
            #pragma unroll 4
            for (int ii = 0; ii < 64; ii++) {
                u64 w01, w23, x01, x23;
                ldg2(w01, w23, wrow + (ii << 2));
                lds2(x01, x23, xsa + (ii << 4));
                ffma2(acc, w01, x01);
                ffma2(acc, w23, x23);
            }
            float a = uns(acc);
            a = fmaf(pe0, __ldg(wrow + 256), a);
            a = fmaf(pe1, __ldg(wrow + 257), a);
            a = fmaf(pe2, __ldg(wrow + 258), a);
            a = fmaf(pe3, __ldg(wrow + 259), a);
            a += __ldg(&posd_b[j]);
            g_attc[bid * Hn + j] = a;
        }
    } else if (bid >= 32 && bid < 96) {
        // ---- phase B: attention scores (q = bid-32) ----
        int q = bid - 32;
        float* eq = ws;
        if (tid < 256) eq[tid] = __ldcg(&g_hq[0][q * Hn + tid]);
        __syncthreads();
        if (tid < DTn) {
            const float4* ap = (const float4*)(g_ha[0] + tid * Hn);
            const float4* e4 = (const float4*)eq;
            float acc = 0.0f;
            #pragma unroll 4
            for (int ii = 0; ii < 64; ii++) {
                float4 a4 = __ldcg(ap + ii);
                float4 x4 = e4[ii];
                acc = fmaf(a4.x, x4.x, acc);
                acc = fmaf(a4.y, x4.y, acc);
                acc = fmaf(a4.z, x4.z, acc);
                acc = fmaf(a4.w, x4.w, acc);
            }
            g_scores[q * DTn + tid] = acc;
        }
    }

    bar_arrive(g_f_all, bid, ball + 2); bar_wait(g_f_all, NBLK, ball + 2);

    // ---- phase C: softmax + memory read + final GRU (blocks 0..63) ----
    if (bid < Qn) {
        int q = bid;
        float* sv = ws;
        float* wv = ws + 32;
        float* qs = ws + 64;
        if (tid < DTn) sv[tid] = __ldcg(&g_scores[q * DTn + tid]);
        __syncthreads();
        if (tid < 2) {
            int off = tid * DSET;
            float mx = -1e30f;
            for (int d2 = 0; d2 < DSET; d2++) mx = fmaxf(mx, sv[off + d2]);
            float s = 0.0f;
            for (int d2 = 0; d2 < DSET; d2++) {
                float e = __expf(sv[off + d2] - mx);
                wv[off + d2] = e;
                s += e;
            }
            float inv = 1.0f / s;
            for (int d2 = 0; d2 < DSET; d2++) wv[off + d2] *= inv;
        }
        __syncthreads();
        if (tid < 256) {
            int j = tid;
            float val = __ldcg(&g_hq[0][q * Hn + j]);
            #pragma unroll
            for (int d2 = 0; d2 < DSET; d2++)
                val = fmaf(wv[d2], __ldcg(&g_attc[d2 * Hn + j]), val);
            #pragma unroll
            for (int d2 = 0; d2 < DSET; d2++)
                val = fmaf(wv[DSET + d2], __ldcg(&g_attc[(DSET + d2) * Hn + j]), val);
            qs[j] = val;
        }
        __syncthreads();
        if (tid < 256) {
            int j = tid;
            u64 dr = pk(0.0f, 0.0f), dz = pk(0.0f, 0.0f), dn = pk(0.0f, 0.0f);
            unsigned qsa = sptr(qs);
            const float* wr = qy_Wih + (size_t)j * Hn;
            const float* wz = qy_Wih + (size_t)(Hn + j) * Hn;
            const float* wn = qy_Wih + (size_t)(2 * Hn + j) * Hn;
            #pragma unroll 4
            for (int ii = 0; ii < 64; ii++) {
                u64 x01, x23, w01, w23;
                lds2(x01, x23, qsa + (ii << 4));
                ldg2(w01, w23, wr + (ii << 2));
                ffma2(dr, w01, x01); ffma2(dr, w23, x23);
                ldg2(w01, w23, wz + (ii << 2));
                ffma2(dz, w01, x01); ffma2(dz, w23, x23);
                ldg2(w01, w23, wn + (ii << 2));
                ffma2(dn, w01, x01); ffma2(dn, w23, x23);
            }
            float r = sigm(uns(dr) + __ldg(&qy_bih[j]) + __ldg(&qy_bhh[j]));
            float z = sigm(uns(dz) + __ldg(&qy_bih[Hn + j]) + __ldg(&qy_bhh[Hn + j]));
            float n = tanhf(uns(dn) + __ldg(&qy_bih[2 * Hn + j]) + r * __ldg(&qy_bhh[2 * Hn + j]));
            out[q * Hn + j] = (1.0f - z) * n;
        }
    }
}

extern "C" void kernel_launch(void* const* d_in, const int* in_sizes, int n_in,
                              void* d_out, int out_size) {
    const int*   q_tok    = (const int*)d_in[0];
    const int*   p_tok    = (const int*)d_in[1];
    const int*   n_tok    = (const int*)d_in[2];
    const float* term_emb = (const float*)d_in[3];
    const float* term_Wih = (const float*)d_in[4];
    const float* term_Whh = (const float*)d_in[5];
    const float* term_bih = (const float*)d_in[6];
    const float* term_bhh = (const float*)d_in[7];
    const float* doc_emb  = (const float*)d_in[8];
    const float* dc_Wih   = (const float*)d_in[9];
    const float* dc_Whh   = (const float*)d_in[10];
    const float* dc_bih   = (const float*)d_in[11];
    const float* dc_bhh   = (const float*)d_in[12];
    const float* da_Wih   = (const float*)d_in[13];
    const float* da_Whh   = (const float*)d_in[14];
    const float* da_bih   = (const float*)d_in[15];
    const float* da_bhh   = (const float*)d_in[16];
    const float* pos_tab  = (const float*)d_in[17];
    const float* posd_W   = (const float*)d_in[18];
    const float* posd_b   = (const float*)d_in[19];
    const float* qy_Wih   = (const float*)d_in[20];
    const float* qy_Whh   = (const float*)d_in[21];
    const float* qy_bih   = (const float*)d_in[22];
    const float* qy_bhh   = (const float*)d_in[23];
    float* out = (float*)d_out;

    const int dyn_bytes = 64 * HSTR * 4;
    cudaFuncSetAttribute(fmn_kernel, cudaFuncAttributeMaxDynamicSharedMemorySize, dyn_bytes);
    fmn_kernel<<<NBLK, NTHR, dyn_bytes>>>(q_tok, p_tok, n_tok,
                            term_emb, term_Wih, term_Whh, term_bih, term_bhh,
                            doc_emb, dc_Wih, dc_Whh, dc_bih, dc_bhh,
                            da_Wih, da_Whh, da_bih, da_bhh,
                            pos_tab, posd_W, posd_b,
                            qy_Wih, qy_Whh, qy_bih, qy_bhh,
                            out);
}

// round 15
// speedup vs baseline: 1.1823x; 1.0515x over previous
#include <cuda_runtime.h>

typedef unsigned long long u64;

#define Qn   64
#define LQ   20
#define DSET 12
#define DTn  24
#define LD   50
#define Hn   256
#define G3   768
#define NBLK 144
#define NTHR 512

// ---------------- device scratch ----------------
__device__ float g_gi_q[LQ * Qn * G3];
__device__ float g_gi_c[LD * DTn * G3];
__device__ float g_gi_a[LD * DTn * G3];
__device__ float4 g_wt_c[64 * G3];      // k-major Wih (phase0)
__device__ float4 g_wt_a[64 * G3];
__device__ float4 g_wt_q[64 * G3];
__device__ float4 g_whh_c[64 * G3];     // k-major Whh (recurrence streaming)
__device__ float4 g_whh_a[64 * G3];
__device__ float4 g_whh_q[64 * G3];
__device__ float g_hq[Qn * Hn];
__device__ float g_hc[DTn * Hn];
__device__ float g_ha[DTn * Hn];
__device__ float g_attc[DTn * Hn];
__device__ float g_scores[Qn * DTn];
__device__ unsigned g_f_grp[3 * 48 * 32];
__device__ unsigned g_f_all[NBLK * 32];

// ---------------- helpers ----------------
__device__ __forceinline__ float sigm(float x) { return 1.0f / (1.0f + __expf(-x)); }
__device__ __forceinline__ u64 pk(float lo, float hi) {
    u64 r; asm("mov.b64 %0, {%1,%2};" : "=l"(r) : "f"(lo), "f"(hi)); return r;
}
__device__ __forceinline__ float uns(u64 v) {
    float lo, hi; asm("mov.b64 {%0,%1}, %2;" : "=f"(lo), "=f"(hi) : "l"(v));
    return lo + hi;
}
__device__ __forceinline__ void ffma2(u64& d, u64 a, u64 b) {
    asm("fma.rn.f32x2 %0, %1, %2, %0;" : "+l"(d) : "l"(a), "l"(b));
}
__device__ __forceinline__ unsigned sptr(const void* p) {
    return (unsigned)__cvta_generic_to_shared(p);
}
__device__ __forceinline__ void lds2(u64& a, u64& b, unsigned addr) {
    asm volatile("ld.shared.v2.u64 {%0,%1}, [%2];" : "=l"(a), "=l"(b) : "r"(addr));
}
__device__ __forceinline__ void ldg2(u64& a, u64& b, const float* p) {
    asm volatile("ld.global.nc.v2.u64 {%0,%1}, [%2];" : "=l"(a), "=l"(b) : "l"(p));
}
__device__ __forceinline__ void barh(int h) {
    asm volatile("bar.sync %0, %1;" :: "r"(1 + h), "r"(256) : "memory");
}

// ---- flag barrier ----
__device__ __forceinline__ void bar_arrive(unsigned* fl, int idx, unsigned gen) {
    __syncthreads();
    if (threadIdx.x == 0)
        asm volatile("st.release.gpu.global.u32 [%0], %1;"
                     :: "l"(fl + idx * 32), "r"(gen) : "memory");
}
__device__ __forceinline__ void bar_wait(unsigned* fl, int n, unsigned gen) {
    if (threadIdx.x < (unsigned)n) {
        unsigned cur;
        do {
            asm volatile("ld.acquire.gpu.global.u32 %0, [%1];"
                         : "=r"(cur) : "l"(fl + threadIdx.x * 32) : "memory");
        } while (cur < gen);
    }
    __syncthreads();
}
// long-wait version: sleep between polls (idle blocks only; last arrivals fast-path)
__device__ __forceinline__ void bar_wait_ns(unsigned* fl, int n, unsigned gen) {
    if (threadIdx.x < (unsigned)n) {
        unsigned cur;
        for (;;) {
            asm volatile("ld.acquire.gpu.global.u32 %0, [%1];"
                         : "=r"(cur) : "l"(fl + threadIdx.x * 32) : "memory");
            if (cur >= gen) break;
            __nanosleep(300);
        }
    }
    __syncthreads();
}
__device__ __forceinline__ unsigned rd_base(unsigned* fl, int idx) {
    return *(volatile unsigned*)(fl + idx * 32);
}

// ---------------- W transpose: 24 rows of W[768][256] -> Wt[64][768] float4 ----------------
__device__ void transpose_w(int gid, const float* __restrict__ W, float4* __restrict__ Wt,
                            float* sbuf)
{
    int tid = threadIdx.x;
    int r0 = gid * 24;
    for (int i = tid; i < 24 * 256; i += NTHR) {
        int rl = i >> 8, j = i & 255;
        sbuf[rl * 260 + j] = __ldg(W + (size_t)(r0 + rl) * Hn + j);
    }
    __syncthreads();
    for (int i = tid; i < 24 * 64; i += NTHR) {
        int rl = i % 24, kk = i / 24;
        float4 v = *(float4*)(sbuf + rl * 260 + (kk << 2));
        Wt[kk * G3 + r0 + rl] = v;
    }
    __syncthreads();
}

// ---------------- phase 0 (one 256-thread half = one virtual block) ----------------
__device__ void phase0_gemm(int vgid, int nv, int half, int R, int mode,
                            const int* __restrict__ tokA, const int* __restrict__ tokB,
                            const float* __restrict__ emb, const float4* __restrict__ Wt,
                            const float* __restrict__ bias, float* __restrict__ gi,
                            float* xs)
{
    int th = threadIdx.x & 255;
    int rpb = (R + nv - 1) / nv;
    int r0 = vgid * rpb;
    int r1 = min(R, r0 + rpb);
    unsigned xsa = sptr(xs);
    float b0 = __ldg(bias + th), b1 = __ldg(bias + th + 256), b2 = __ldg(bias + th + 512);

    for (int rt = r0; rt < r1; rt += 8) {
        int nr = min(8, r1 - rt);
        barh(half);
        for (int idx = th; idx < (nr << 8); idx += 256) {
            int rl = idx >> 8, j = idx & 255;
            int r = rt + rl;
            int tok;
            if (mode == 0) {
                int t = r >> 6, q = r & 63;
                tok = tokA[q * LQ + t];
            } else {
                int t = r / DTn, dt = r - t * DTn;
                tok = (dt < DSET) ? tokA[dt * LD + t] : tokB[(dt - DSET) * LD + t];
            }
            xs[(rl << 8) + j] = __ldg(emb + (size_t)tok * Hn + j);
        }
        barh(half);

        u64 acc[3][8];
        #pragma unroll
        for (int rl = 0; rl < 8; rl++) {
            acc[0][rl] = pk(b0, 0.0f);
            acc[1][rl] = pk(b1, 0.0f);
            acc[2][rl] = pk(b2, 0.0f);
        }
        #pragma unroll 2
        for (int jj = 0; jj < 64; jj++) {
            const float* wp = (const float*)(Wt + jj * G3 + th);
            u64 w0a, w0b, w1a, w1b, w2a, w2b;
            ldg2(w0a, w0b, wp);
            ldg2(w1a, w1b, wp + 1024);
            ldg2(w2a, w2b, wp + 2048);
            unsigned xo = xsa + (jj << 4);
            #pragma unroll
            for (int rlb = 0; rlb < 2; rlb++) {
                u64 x01[4], x23[4];
                #pragma unroll
                for (int rl = 0; rl < 4; rl++)
                    lds2(x01[rl], x23[rl], xo + ((rlb * 4 + rl) << 10));
                #pragma unroll
                for (int rl = 0; rl < 4; rl++) {
                    int ri = rlb * 4 + rl;
                    ffma2(acc[0][ri], w0a, x01[rl]); ffma2(acc[0][ri], w0b, x23[rl]);
                    ffma2(acc[1][ri], w1a, x01[rl]); ffma2(acc[1][ri], w1b, x23[rl]);
                    ffma2(acc[2][ri], w2a, x01[rl]); ffma2(acc[2][ri], w2b, x23[rl]);
                }
            }
        }
        for (int rl = 0; rl < nr; rl++) {
            float* gr = gi + (size_t)(rt + rl) * G3 + th;
            gr[0]   = uns(acc[0][rl]);
            gr[256] = uns(acc[1][rl]);
            gr[512] = uns(acc[2][rl]);
        }
    }
}

// ---------------- barrier-free recurrence: block owns 2 batch rows ----------------
// thread (j = tid&255, kh = tid>>8). Whh streamed k-major from L2; h in smem.
__device__ void run_rec(int gl, int steps, int B, const float4* __restrict__ wthh,
                        const float* __restrict__ bhh, const float* __restrict__ gi,
                        float* __restrict__ outH, float* hb, float* red)
{
    int tid = threadIdx.x;
    int j = tid & 255, kh = tid >> 8;
    int d0 = gl * 2;
    hb[tid] = 0.0f;                       // hb[0][2*256] zero-init
    const float* wb0 = (const float*)wthh + (j << 2) + (size_t)(kh * 32) * 3072;
    const float* wb1 = wb0 + 1024;
    const float* wb2 = wb0 + 2048;
    float bR = __ldg(bhh + j), bZ = __ldg(bhh + 256 + j), bN = __ldg(bhh + 512 + j);
    unsigned hbase = sptr(hb);
    unsigned khofs = (unsigned)kh * 512;  // 128 floats
    __syncthreads();

    for (int t = 0; t < steps; t++) {
        int cur = t & 1;
        unsigned hA = hbase + cur * 2048;
        float gr0 = 0.f, gz0 = 0.f, gn0 = 0.f, gr1 = 0.f, gz1 = 0.f, gn1 = 0.f;
        if (kh == 0) {
            const float* gA = gi + (size_t)(t * B + d0) * G3;
            gr0 = __ldg(gA + j); gz0 = __ldg(gA + 256 + j); gn0 = __ldg(gA + 512 + j);
            const float* gB = gA + G3;
            gr1 = __ldg(gB + j); gz1 = __ldg(gB + 256 + j); gn1 = __ldg(gB + 512 + j);
        }
        u64 a00 = 0, a01 = 0, a02 = 0, a10 = 0, a11 = 0, a12 = 0;
        #pragma unroll 8
        for (int kc = 0; kc < 32; kc++) {
            unsigned off = khofs + (kc << 4);
            u64 h0a, h0b, h1a, h1b, wa, wbv;
            lds2(h0a, h0b, hA + off);
            lds2(h1a, h1b, hA + 1024 + off);
            ldg2(wa, wbv, wb0 + (size_t)kc * 3072);
            ffma2(a00, wa, h0a); ffma2(a00, wbv, h0b);
            ffma2(a10, wa, h1a); ffma2(a10, wbv, h1b);
            ldg2(wa, wbv, wb1 + (size_t)kc * 3072);
            ffma2(a01, wa, h0a); ffma2(a01, wbv, h0b);
            ffma2(a11, wa, h1a); ffma2(a11, wbv, h1b);
            ldg2(wa, wbv, wb2 + (size_t)kc * 3072);
            ffma2(a02, wa, h0a); ffma2(a02, wbv, h0b);
            ffma2(a12, wa, h1a); ffma2(a12, wbv, h1b);
        }
        if (kh == 1) {
            float* rp = red + j * 6;
            rp[0] = uns(a00); rp[1] = uns(a01); rp[2] = uns(a02);
            rp[3] = uns(a10); rp[4] = uns(a11); rp[5] = uns(a12);
        }
        __syncthreads();
        if (kh == 0) {
            const float* rp = red + j * 6;
            float hr0 = uns(a00) + rp[0] + bR;
            float hz0 = uns(a01) + rp[1] + bZ;
            float hn0 = uns(a02) + rp[2] + bN;
            float hr1 = uns(a10) + rp[3] + bR;
            float hz1 = uns(a11) + rp[4] + bZ;
            float hn1 = uns(a12) + rp[5] + bN;
            float r0 = sigm(gr0 + hr0), z0 = sigm(gz0 + hz0);
            float n0 = tanhf(gn0 + r0 * hn0);
            float r1 = sigm(gr1 + hr1), z1 = sigm(gz1 + hz1);
            float n1 = tanhf(gn1 + r1 * hn1);
            float* hN = hb + (cur ^ 1) * 512;
            float ho0 = hb[cur * 512 + j];
            float ho1 = hb[cur * 512 + 256 + j];
            hN[j]       = (1.0f - z0) * n0 + z0 * ho0;
            hN[256 + j] = (1.0f - z1) * n1 + z1 * ho1;
        }
        __syncthreads();
    }
    int fb = steps & 1;
    outH[(size_t)d0 * 256 + tid] = hb[fb * 512 + tid];
}

// ---------------- persistent kernel ----------------
__global__ void __launch_bounds__(NTHR, 1)
fmn_kernel(const int* __restrict__ q_tok, const int* __restrict__ p_tok, const int* __restrict__ n_tok,
           const float* __restrict__ term_emb, const float* __restrict__ term_Wih,
           const float* __restrict__ term_Whh, const float* __restrict__ term_bih,
           const float* __restrict__ term_bhh,
           const float* __restrict__ doc_emb,
           const float* __restrict__ dc_Wih, const float* __restrict__ dc_Whh,
           const float* __restrict__ dc_bih, const float* __restrict__ dc_bhh,
           const float* __restrict__ da_Wih, const float* __restrict__ da_Whh,
           const float* __restrict__ da_bih, const float* __restrict__ da_bhh,
           const float* __restrict__ pos_table, const float* __restrict__ posd_W,
           const float* __restrict__ posd_b,
           const float* __restrict__ qy_Wih, const float* __restrict__ qy_Whh,
           const float* __restrict__ qy_bih, const float* __restrict__ qy_bhh,
           float* __restrict__ out)
{
    __shared__ float hb[2 * 512];
    __shared__ float red[256 * 6];
    extern __shared__ float dyn[];
    int bid = blockIdx.x;
    int tid = threadIdx.x;
    int half = tid >> 8;
    int grp = bid / 48, gl = bid % 48;
    unsigned* fl = g_f_grp + grp * (48 * 32);
    unsigned gb = rd_base(fl, gl);
    unsigned ball = rd_base(g_f_all, bid);

    // per-group bindings
    const int*   tokA; const int* tokB; const float* emb;
    const float* Wih; const float* Whh; const float* bih; const float* bhh;
    float4* wt; float4* whh_t; float* gi_; float* outH;
    int mode, R, recN, B, steps;
    if (grp == 0) {
        tokA = p_tok; tokB = n_tok; emb = doc_emb;
        Wih = dc_Wih; Whh = dc_Whh; bih = dc_bih; bhh = dc_bhh;
        wt = g_wt_c; whh_t = g_whh_c; gi_ = g_gi_c; outH = g_hc;
        mode = 1; R = LD * DTn; recN = 12; B = DTn; steps = LD;
    } else if (grp == 1) {
        tokA = p_tok; tokB = n_tok; emb = doc_emb;
        Wih = da_Wih; Whh = da_Whh; bih = da_bih; bhh = da_bhh;
        wt = g_wt_a; whh_t = g_whh_a; gi_ = g_gi_a; outH = g_ha;
        mode = 1; R = LD * DTn; recN = 12; B = DTn; steps = LD;
    } else {
        tokA = q_tok; tokB = (const int*)0; emb = term_emb;
        Wih = term_Wih; Whh = term_Whh; bih = term_bih; bhh = term_bhh;
        wt = g_wt_q; whh_t = g_whh_q; gi_ = g_gi_q; outH = g_hq;
        mode = 0; R = LQ * Qn; recN = 32; B = Qn; steps = LQ;
    }

    // transposes: units 0..31 Wih, 32..63 Whh; block gl does unit gl, and gl<16 also unit 48+gl
    if (gl < 32) transpose_w(gl, Wih, wt, dyn);
    else transpose_w(gl - 32, Whh, whh_t, dyn);
    if (gl < 16) transpose_w(gl + 16, Whh, whh_t, dyn);
    bar_arrive(fl, gl, gb + 1); bar_wait(fl, 48, gb + 1);

    phase0_gemm(gl * 2 + half, 96, half, R, mode, tokA, tokB, emb, wt, bih, gi_,
                dyn + half * 2048);
    bar_arrive(fl, gl, gb + 2); bar_wait(fl, 48, gb + 2);

    if (gl < recN)
        run_rec(gl, steps, B, whh_t, bhh, gi_, outH, hb, red);

    bar_arrive(g_f_all, bid, ball + 1); bar_wait_ns(g_f_all, NBLK, ball + 1);

    // ---- phase A: position dense (blocks 0..23) ----
    if (bid < DTn) {
        float* hrow = red;
        if (tid < 256) hrow[tid] = __ldcg(&g_hc[bid * Hn + tid]);
        __syncthreads();
        if (tid < 256) {
            int dset = bid % DSET;
            float pe0 = __ldg(&pos_table[dset * 4 + 0]);
            float pe1 = __ldg(&pos_table[dset * 4 + 1]);
            float pe2 = __ldg(&pos_table[dset * 4 + 2]);
            float pe3 = __ldg(&pos_table[dset * 4 + 3]);
            int j = tid;
            const float* wrow = posd_W + (size_t)j * (Hn + 4);
            unsigned xsa = sptr(hrow);
            u64 acc = pk(0.0f, 0.0f);
            #pragma unroll 4
            for (int ii = 0; ii < 64; ii++) {
                u64 w01, w23, x01, x23;
                ldg2(w01, w23, wrow + (ii << 2));
                lds2(x01, x23, xsa + (ii << 4));
                ffma2(acc, w01, x01);
                ffma2(acc, w23, x23);
            }
            float a = uns(acc);
            a = fmaf(pe0, __ldg(wrow + 256), a);
            a = fmaf(pe1, __ldg(wrow + 257), a);
            a = fmaf(pe2, __ldg(wrow + 258), a);
            a = fmaf(pe3, __ldg(wrow + 259), a);
            a += __ldg(&posd_b[j]);
            g_attc[bid * Hn + j] = a;
        }
    } else if (bid >= 32 && bid < 96) {
        // ---- phase B: attention scores (q = bid-32) ----
        int q = bid - 32;
        float* eq = red;
        if (tid < 256) eq[tid] = __ldcg(&g_hq[q * Hn + tid]);
        __syncthreads();
        if (tid < DTn) {
            const float4* ap = (const float4*)(g_ha + tid * Hn);
            const float4* e4 = (const float4*)eq;
            float acc = 0.0f;
            #pragma unroll 4
            for (int ii = 0; ii < 64; ii++) {
                float4 a4 = __ldcg(ap + ii);
                float4 x4 = e4[ii];
                acc = fmaf(a4.x, x4.x, acc);
                acc = fmaf(a4.y, x4.y, acc);
                acc = fmaf(a4.z, x4.z, acc);
                acc = fmaf(a4.w, x4.w, acc);
            }
            g_scores[q * DTn + tid] = acc;
        }
    }

    bar_arrive(g_f_all, bid, ball + 2); bar_wait(g_f_all, NBLK, ball + 2);

    // ---- phase C: softmax + memory read + final GRU (blocks 0..63) ----
    if (bid < Qn) {
        int q = bid;
        float* sv = red;
        float* wv = red + 32;
        float* qs = red + 64;
        if (tid < DTn) sv[tid] = __ldcg(&g_scores[q * DTn + tid]);
        __syncthreads();
        if (tid < 2) {
            int off = tid * DSET;
            float mx = -1e30f;
            for (int d2 = 0; d2 < DSET; d2++) mx = fmaxf(mx, sv[off + d2]);
            float s = 0.0f;
            for (int d2 = 0; d2 < DSET; d2++) {
                float e = __expf(sv[off + d2] - mx);
                wv[off + d2] = e;
                s += e;
            }
            float inv = 1.0f / s;
            for (int d2 = 0; d2 < DSET; d2++) wv[off + d2] *= inv;
        }
        __syncthreads();
        if (tid < 256) {
            int j = tid;
            float val = __ldcg(&g_hq[q * Hn + j]);
            #pragma unroll
            for (int d2 = 0; d2 < DSET; d2++)
                val = fmaf(wv[d2], __ldcg(&g_attc[d2 * Hn + j]), val);
            #pragma unroll
            for (int d2 = 0; d2 < DSET; d2++)
                val = fmaf(wv[DSET + d2], __ldcg(&g_attc[(DSET + d2) * Hn + j]), val);
            qs[j] = val;
        }
        __syncthreads();
        if (tid < 256) {
            int j = tid;
            u64 dr = pk(0.0f, 0.0f), dz = pk(0.0f, 0.0f), dn = pk(0.0f, 0.0f);
            unsigned qsa = sptr(qs);
            const float* wr = qy_Wih + (size_t)j * Hn;
            const float* wz = qy_Wih + (size_t)(Hn + j) * Hn;
            const float* wn = qy_Wih + (size_t)(2 * Hn + j) * Hn;
            #pragma unroll 4
            for (int ii = 0; ii < 64; ii++) {
                u64 x01, x23, w01, w23;
                lds2(x01, x23, qsa + (ii << 4));
                ldg2(w01, w23, wr + (ii << 2));
                ffma2(dr, w01, x01); ffma2(dr, w23, x23);
                ldg2(w01, w23, wz + (ii << 2));
                ffma2(dz, w01, x01); ffma2(dz, w23, x23);
                ldg2(w01, w23, wn + (ii << 2));
                ffma2(dn, w01, x01); ffma2(dn, w23, x23);
            }
            float r = sigm(uns(dr) + __ldg(&qy_bih[j]) + __ldg(&qy_bhh[j]));
            float z = sigm(uns(dz) + __ldg(&qy_bih[Hn + j]) + __ldg(&qy_bhh[Hn + j]));
            float n = tanhf(uns(dn) + __ldg(&qy_bih[2 * Hn + j]) + r * __ldg(&qy_bhh[2 * Hn + j]));
            out[q * Hn + j] = (1.0f - z) * n;
        }
    }
}

extern "C" void kernel_launch(void* const* d_in, const int* in_sizes, int n_in,
                              void* d_out, int out_size) {
    const int*   q_tok    = (const int*)d_in[0];
    const int*   p_tok    = (const int*)d_in[1];
    const int*   n_tok    = (const int*)d_in[2];
    const float* term_emb = (const float*)d_in[3];
    const float* term_Wih = (const float*)d_in[4];
    const float* term_Whh = (const float*)d_in[5];
    const float* term_bih = (const float*)d_in[6];
    const float* term_bhh = (const float*)d_in[7];
    const float* doc_emb  = (const float*)d_in[8];
    const float* dc_Wih   = (const float*)d_in[9];
    const float* dc_Whh   = (const float*)d_in[10];
    const float* dc_bih   = (const float*)d_in[11];
    const float* dc_bhh   = (const float*)d_in[12];
    const float* da_Wih   = (const float*)d_in[13];
    const float* da_Whh   = (const float*)d_in[14];
    const float* da_bih   = (const float*)d_in[15];
    const float* da_bhh   = (const float*)d_in[16];
    const float* pos_tab  = (const float*)d_in[17];
    const float* posd_W   = (const float*)d_in[18];
    const float* posd_b   = (const float*)d_in[19];
    const float* qy_Wih   = (const float*)d_in[20];
    const float* qy_Whh   = (const float*)d_in[21];
    const float* qy_bih   = (const float*)d_in[22];
    const float* qy_bhh   = (const float*)d_in[23];
    float* out = (float*)d_out;

    const int dyn_bytes = 25600;   // transpose sbuf (24*260*4=24960) / phase0 xs (2*8KB)
    cudaFuncSetAttribute(fmn_kernel, cudaFuncAttributeMaxDynamicSharedMemorySize, dyn_bytes);
    fmn_kernel<<<NBLK, NTHR, dyn_bytes>>>(q_tok, p_tok, n_tok,
                            term_emb, term_Wih, term_Whh, term_bih, term_bhh,
                            doc_emb, dc_Wih, dc_Whh, dc_bih, dc_bhh,
                            da_Wih, da_Whh, da_bih, da_bhh,
                            pos_tab, posd_W, posd_b,
                            qy_Wih, qy_Whh, qy_bih, qy_bhh,
                            out);
}

// round 16
// speedup vs baseline: 1.2757x; 1.0790x over previous
#include <cuda_runtime.h>

typedef unsigned long long u64;

#define Qn   64
#define LQ   20
#define DSET 12
#define DTn  24
#define LD   50
#define Hn   256
#define G3   768
#define HSTR 260
#define NB_DOC 52   // real blocks on each doc phase0 (32 main + 20 helpers) -> 104 virtual
#define NB_TRM 40   // real blocks on term phase0 (32 main + 8 helpers) -> 80 virtual
#define NBLK 144
#define NTHR 512

// ---------------- device scratch ----------------
__device__ float g_gi_q[LQ * Qn * G3];
__device__ float g_gi_c[LD * DTn * G3];
__device__ float g_gi_a[LD * DTn * G3];
__device__ float4 g_wt_c[64 * G3];
__device__ float4 g_wt_a[64 * G3];
__device__ float4 g_wt_q[64 * G3];
__device__ float g_hq[2][Qn * Hn];
__device__ float g_hc[2][DTn * Hn];
__device__ float g_ha[2][DTn * Hn];
__device__ float g_attc[DTn * Hn];
__device__ float g_scores[Qn * DTn];
__device__ unsigned g_f_p0c[NB_DOC * 32];
__device__ unsigned g_f_p0a[NB_DOC * 32];
__device__ unsigned g_f_p0t[NB_TRM * 32];
__device__ unsigned g_f_rc[32 * 32];
__device__ unsigned g_f_ra[32 * 32];
__device__ unsigned g_f_rt[32 * 32];
__device__ unsigned g_f_all[NBLK * 32];

// ---------------- helpers ----------------
__device__ __forceinline__ float sigm(float x) { return 1.0f / (1.0f + __expf(-x)); }
__device__ __forceinline__ u64 pk(float lo, float hi) {
    u64 r; asm("mov.b64 %0, {%1,%2};" : "=l"(r) : "f"(lo), "f"(hi)); return r;
}
__device__ __forceinline__ float uns(u64 v) {
    float lo, hi; asm("mov.b64 {%0,%1}, %2;" : "=f"(lo), "=f"(hi) : "l"(v));
    return lo + hi;
}
__device__ __forceinline__ void ffma2(u64& d, u64 a, u64 b) {
    asm("fma.rn.f32x2 %0, %1, %2, %0;" : "+l"(d) : "l"(a), "l"(b));
}
__device__ __forceinline__ unsigned sptr(const void* p) {
    return (unsigned)__cvta_generic_to_shared(p);
}
__device__ __forceinline__ void lds2(u64& a, u64& b, unsigned addr) {
    asm volatile("ld.shared.v2.u64 {%0,%1}, [%2];" : "=l"(a), "=l"(b) : "r"(addr));
}
__device__ __forceinline__ void ldg2(u64& a, u64& b, const float* p) {
    asm volatile("ld.global.nc.v2.u64 {%0,%1}, [%2];" : "=l"(a), "=l"(b) : "l"(p));
}
// named barrier over one 256-thread half (id 1 or 2)
__device__ __forceinline__ void barh(int h) {
    asm volatile("bar.sync %0, %1;" :: "r"(1 + h), "r"(256) : "memory");
}

// ---- flag barrier ----
__device__ __forceinline__ void bar_arrive(unsigned* fl, int idx, unsigned gen) {
    __syncthreads();
    if (threadIdx.x == 0)
        asm volatile("st.release.gpu.global.u32 [%0], %1;"
                     :: "l"(fl + idx * 32), "r"(gen) : "memory");
}
__device__ __forceinline__ void bar_wait(unsigned* fl, int n, unsigned gen) {
    if (threadIdx.x < (unsigned)n) {
        unsigned cur;
        do {
            asm volatile("ld.acquire.gpu.global.u32 %0, [%1];"
                         : "=r"(cur) : "l"(fl + threadIdx.x * 32) : "memory");
        } while (cur < gen);
    }
    __syncthreads();
}
// long-wait: fast-path poll, then sleep between polls (keeps idle blocks off the L2)
__device__ __forceinline__ void bar_wait_ns(unsigned* fl, int n, unsigned gen) {
    if (threadIdx.x < (unsigned)n) {
        unsigned cur;
        asm volatile("ld.acquire.gpu.global.u32 %0, [%1];"
                     : "=r"(cur) : "l"(fl + threadIdx.x * 32) : "memory");
        while (cur < gen) {
            __nanosleep(400);
            asm volatile("ld.acquire.gpu.global.u32 %0, [%1];"
                         : "=r"(cur) : "l"(fl + threadIdx.x * 32) : "memory");
        }
    }
    __syncthreads();
}
__device__ __forceinline__ unsigned rd_base(unsigned* fl, int idx) {
    return *(volatile unsigned*)(fl + idx * 32);
}

// ---------------- W transpose (512 threads) ----------------
__device__ void transpose_w(int gid, const float* __restrict__ W, float4* __restrict__ Wt,
                            float* sbuf)
{
    int tid = threadIdx.x;
    int r0 = gid * 24;
    for (int i = tid; i < 24 * 256; i += NTHR) {
        int rl = i >> 8, j = i & 255;
        sbuf[rl * 260 + j] = __ldg(W + (size_t)(r0 + rl) * Hn + j);
    }
    __syncthreads();
    for (int i = tid; i < 24 * 64; i += NTHR) {
        int rl = i % 24, kk = i / 24;
        float4 v = *(float4*)(sbuf + rl * 260 + (kk << 2));
        Wt[kk * G3 + r0 + rl] = v;
    }
    __syncthreads();
}

// ---------------- phase 0 (one 256-thread half = one virtual block) ----------------
__device__ void phase0_gemm(int vgid, int nv, int half, int R, int mode,
                            const int* __restrict__ tokA, const int* __restrict__ tokB,
                            const float* __restrict__ emb, const float4* __restrict__ Wt,
                            const float* __restrict__ bias, float* __restrict__ gi,
                            float* xs)
{
    int th = threadIdx.x & 255;
    int rpb = (R + nv - 1) / nv;
    int r0 = vgid * rpb;
    int r1 = min(R, r0 + rpb);
    unsigned xsa = sptr(xs);
    float b0 = __ldg(bias + th), b1 = __ldg(bias + th + 256), b2 = __ldg(bias + th + 512);

    for (int rt = r0; rt < r1; rt += 8) {
        int nr = min(8, r1 - rt);
        barh(half);
        for (int idx = th; idx < (nr << 8); idx += 256) {
            int rl = idx >> 8, j = idx & 255;
            int r = rt + rl;
            int tok;
            if (mode == 0) {
                int t = r >> 6, q = r & 63;
                tok = tokA[q * LQ + t];
            } else {
                int t = r / DTn, dt = r - t * DTn;
                tok = (dt < DSET) ? tokA[dt * LD + t] : tokB[(dt - DSET) * LD + t];
            }
            xs[(rl << 8) + j] = __ldg(emb + (size_t)tok * Hn + j);
        }
        barh(half);

        u64 acc[3][8];
        #pragma unroll
        for (int rl = 0; rl < 8; rl++) {
            acc[0][rl] = pk(b0, 0.0f);
            acc[1][rl] = pk(b1, 0.0f);
            acc[2][rl] = pk(b2, 0.0f);
        }
        #pragma unroll 2
        for (int jj = 0; jj < 64; jj++) {
            const float* wp = (const float*)(Wt + jj * G3 + th);
            u64 w0a, w0b, w1a, w1b, w2a, w2b;
            ldg2(w0a, w0b, wp);
            ldg2(w1a, w1b, wp + 1024);
            ldg2(w2a, w2b, wp + 2048);
            unsigned xo = xsa + (jj << 4);
            #pragma unroll
            for (int rlb = 0; rlb < 2; rlb++) {
                u64 x01[4], x23[4];
                #pragma unroll
                for (int rl = 0; rl < 4; rl++)
                    lds2(x01[rl], x23[rl], xo + ((rlb * 4 + rl) << 10));
                #pragma unroll
                for (int rl = 0; rl < 4; rl++) {
                    int ri = rlb * 4 + rl;
                    ffma2(acc[0][ri], w0a, x01[rl]); ffma2(acc[0][ri], w0b, x23[rl]);
                    ffma2(acc[1][ri], w1a, x01[rl]); ffma2(acc[1][ri], w1b, x23[rl]);
                    ffma2(acc[2][ri], w2a, x01[rl]); ffma2(acc[2][ri], w2b, x23[rl]);
                }
            }
        }
        for (int rl = 0; rl < nr; rl++) {
            float* gr = gi + (size_t)(rt + rl) * G3 + th;
            gr[0]   = uns(acc[0][rl]);
            gr[256] = uns(acc[1][rl]);
            gr[512] = uns(acc[2][rl]);
        }
    }
}

// ---------------- doc recurrence: 16 warps, k-quarter split ----------------
__device__ void run_doc(int cb, const float* __restrict__ Whh, const float* __restrict__ bhh,
                        const float* __restrict__ gi, float* hb0, float* hb1,
                        unsigned* fl, unsigned fbase, float* ws, float* red, float* hst)
{
    int tid = threadIdx.x;
    int cbase = cb << 3;
    for (int idx = tid; idx < 6144; idx += NTHR) {
        int rl = idx >> 8, j = idx & 255;
        int gate = rl >> 3, cc = rl & 7;
        ws[idx] = __ldg(Whh + (size_t)(gate * Hn + cbase + cc) * Hn + j);
    }
    int wid = tid >> 5, lane = tid & 31;
    int kq = wid >> 2, wl = wid & 3;
    int c0 = wl * 2, c1 = c0 + 1;
    int j0 = cbase + c0, j1 = cbase + c1;
    bool fin = (kq == 0) && (lane < DTn);
    float br0 = 0.f, bz0 = 0.f, bn0 = 0.f, br1 = 0.f, bz1 = 0.f, bn1 = 0.f;
    if (kq == 0) {
        br0 = __ldg(bhh + j0); bz0 = __ldg(bhh + Hn + j0); bn0 = __ldg(bhh + 2 * Hn + j0);
        br1 = __ldg(bhh + j1); bz1 = __ldg(bhh + Hn + j1); bn1 = __ldg(bhh + 2 * Hn + j1);
    }
    unsigned wsa = sptr(ws);
    unsigned kofs = (unsigned)kq * 256;    // 64 floats
    unsigned wA[6];
    #pragma unroll
    for (int g = 0; g < 3; g++) {
        wA[g * 2 + 0] = wsa + ((g * 8 + c0) << 10) + kofs;
        wA[g * 2 + 1] = wsa + ((g * 8 + c1) << 10) + kofs;
    }
    unsigned hA = sptr(hst) + (unsigned)lane * (HSTR * 4) + kofs;
    float* myred = red + (wl * 32 + lane) * 7;
    float* hb[2] = { hb0, hb1 };

    for (int t = 0; t < LD; t++) {
        const float4* hg = (const float4*)hb[t & 1];
        float* hn_ = hb[(t & 1) ^ 1];
        #pragma unroll
        for (int i = 0; i < 3; i++) {
            int idx = tid + (i << 9);          // < 1536 float4
            int row = idx >> 6, col = idx & 63;
            float4 v = __ldcg(hg + idx);
            *(float4*)(hst + row * HSTR + (col << 2)) = v;
        }
        float g_r0 = 0.f, g_z0 = 0.f, g_n0 = 0.f, g_r1 = 0.f, g_z1 = 0.f, g_n1 = 0.f;
        if (fin) {
            const float* gib = gi + ((size_t)t * DTn + lane) * G3;
            g_r0 = __ldg(gib + j0); g_z0 = __ldg(gib + Hn + j0); g_n0 = __ldg(gib + 2 * Hn + j0);
            g_r1 = __ldg(gib + j1); g_z1 = __ldg(gib + Hn + j1); g_n1 = __ldg(gib + 2 * Hn + j1);
        }
        __syncthreads();
        u64 ar0 = pk(br0, 0.f), az0 = pk(bz0, 0.f), an0 = pk(bn0, 0.f);
        u64 ar1 = pk(br1, 0.f), az1 = pk(bz1, 0.f), an1 = pk(bn1, 0.f);
        #pragma unroll 4
        for (int jj = 0; jj < 16; jj++) {
            unsigned off = jj << 4;
            u64 h01, h23, w01, w23;
            lds2(h01, h23, hA + off);
            lds2(w01, w23, wA[0] + off);
            ffma2(ar0, w01, h01); ffma2(ar0, w23, h23);
            lds2(w01, w23, wA[1] + off);
            ffma2(ar1, w01, h01); ffma2(ar1, w23, h23);
            lds2(w01, w23, wA[2] + off);
            ffma2(az0, w01, h01); ffma2(az0, w23, h23);
            lds2(w01, w23, wA[3] + off);
            ffma2(az1, w01, h01); ffma2(az1, w23, h23);
            lds2(w01, w23, wA[4] + off);
            ffma2(an0, w01, h01); ffma2(an0, w23, h23);
            lds2(w01, w23, wA[5] + off);
            ffma2(an1, w01, h01); ffma2(an1, w23, h23);
        }
        if (kq > 0) {
            float* rp = myred + (kq - 1) * (128 * 7);
            rp[0] = uns(ar0); rp[1] = uns(ar1);
            rp[2] = uns(az0); rp[3] = uns(az1);
            rp[4] = uns(an0); rp[5] = uns(an1);
        }
        __syncthreads();
        if (fin) {
            float sr0 = uns(ar0), sr1 = uns(ar1);
            float sz0 = uns(az0), sz1 = uns(az1);
            float sn0 = uns(an0), sn1 = uns(an1);
            #pragma unroll
            for (int p = 0; p < 3; p++) {
                float* rp = myred + p * (128 * 7);
                sr0 += rp[0]; sr1 += rp[1];
                sz0 += rp[2]; sz1 += rp[3];
                sn0 += rp[4]; sn1 += rp[5];
            }
            float r0 = sigm(g_r0 + sr0);
            float r1 = sigm(g_r1 + sr1);
            float z0 = sigm(g_z0 + sz0);
            float z1 = sigm(g_z1 + sz1);
            float n0 = tanhf(g_n0 + r0 * sn0);
            float n1 = tanhf(g_n1 + r1 * sn1);
            float ho0 = hst[lane * HSTR + j0];
            float ho1 = hst[lane * HSTR + j1];
            hn_[(lane << 8) + j0] = (1.0f - z0) * n0 + z0 * ho0;
            hn_[(lane << 8) + j1] = (1.0f - z1) * n1 + z1 * ho1;
        }
        bar_arrive(fl, cb, fbase + t + 1);
        bar_wait(fl, 32, fbase + t + 1);
    }
}

// ---------------- term recurrence: 16 warps, k-quarter split, 2 q-halves ----------------
__device__ void run_term(int cb, const float* __restrict__ Whh, const float* __restrict__ bhh,
                         unsigned* fl, unsigned fbase, float* ws, float* red, float* hst)
{
    int tid = threadIdx.x;
    int cbase = cb << 3;
    for (int idx = tid; idx < 6144; idx += NTHR) {
        int rl = idx >> 8, j = idx & 255;
        int gate = rl >> 3, cc = rl & 7;
        ws[idx] = __ldg(Whh + (size_t)(gate * Hn + cbase + cc) * Hn + j);
    }
    int wid = tid >> 5, lane = tid & 31;
    int kq = wid >> 2, wl = wid & 3;
    int c0 = wl * 2, c1 = c0 + 1;
    int j0 = cbase + c0, j1 = cbase + c1;
    float br0 = 0.f, bz0 = 0.f, bn0 = 0.f, br1 = 0.f, bz1 = 0.f, bn1 = 0.f;
    if (kq == 0) {
        br0 = __ldg(bhh + j0); bz0 = __ldg(bhh + Hn + j0); bn0 = __ldg(bhh + 2 * Hn + j0);
        br1 = __ldg(bhh + j1); bz1 = __ldg(bhh + Hn + j1); bn1 = __ldg(bhh + 2 * Hn + j1);
    }
    unsigned wsa = sptr(ws);
    unsigned kofs = (unsigned)kq * 256;
    unsigned wA[6];
    #pragma unroll
    for (int g = 0; g < 3; g++) {
        wA[g * 2 + 0] = wsa + ((g * 8 + c0) << 10) + kofs;
        wA[g * 2 + 1] = wsa + ((g * 8 + c1) << 10) + kofs;
    }
    unsigned h0A = sptr(hst) + (unsigned)lane * (HSTR * 4) + kofs;
    unsigned h1A = sptr(hst) + (unsigned)(lane + 32) * (HSTR * 4) + kofs;
    float* myred = red + (wl * 32 + lane) * 13;

    for (int t = 0; t < LQ; t++) {
        const float4* hg = (const float4*)g_hq[t & 1];
        float* hn_ = g_hq[(t & 1) ^ 1];
        #pragma unroll
        for (int i = 0; i < 8; i++) {
            int idx = tid + (i << 9);          // < 4096 float4
            int row = idx >> 6, col = idx & 63;
            float4 v = __ldcg(hg + idx);
            *(float4*)(hst + row * HSTR + (col << 2)) = v;
        }
        int q0 = lane, q1 = lane + 32;
        float gr00 = 0.f, gz00 = 0.f, gn00 = 0.f, gr01 = 0.f, gz01 = 0.f, gn01 = 0.f;
        float gr10 = 0.f, gz10 = 0.f, gn10 = 0.f, gr11 = 0.f, gz11 = 0.f, gn11 = 0.f;
        if (kq == 0) {
            const float* gA = g_gi_q + ((size_t)t * Qn + q0) * G3;
            const float* gB = g_gi_q + ((size_t)t * Qn + q1) * G3;
            gr00 = __ldg(gA + j0); gz00 = __ldg(gA + Hn + j0); gn00 = __ldg(gA + 2 * Hn + j0);
            gr01 = __ldg(gA + j1); gz01 = __ldg(gA + Hn + j1); gn01 = __ldg(gA + 2 * Hn + j1);
            gr10 = __ldg(gB + j0); gz10 = __ldg(gB + Hn + j0); gn10 = __ldg(gB + 2 * Hn + j0);
            gr11 = __ldg(gB + j1); gz11 = __ldg(gB + Hn + j1); gn11 = __ldg(gB + 2 * Hn + j1);
        }
        __syncthreads();
        u64 ar00 = pk(br0, 0.f), az00 = pk(bz0, 0.f), an00 = pk(bn0, 0.f);
        u64 ar01 = pk(br1, 0.f), az01 = pk(bz1, 0.f), an01 = pk(bn1, 0.f);
        u64 ar10 = pk(br0, 0.f), az10 = pk(bz0, 0.f), an10 = pk(bn0, 0.f);
        u64 ar11 = pk(br1, 0.f), az11 = pk(bz1, 0.f), an11 = pk(bn1, 0.f);
        #pragma unroll 4
        for (int jj = 0; jj < 16; jj++) {
            unsigned off = jj << 4;
            u64 h0a, h0b, h1a, h1b, w01, w23;
            lds2(h0a, h0b, h0A + off);
            lds2(h1a, h1b, h1A + off);
            lds2(w01, w23, wA[0] + off);
            ffma2(ar00, w01, h0a); ffma2(ar00, w23, h0b);
            ffma2(ar10, w01, h1a); ffma2(ar10, w23, h1b);
            lds2(w01, w23, wA[1] + off);
            ffma2(ar01, w01, h0a); ffma2(ar01, w23, h0b);
            ffma2(ar11, w01, h1a); ffma2(ar11, w23, h1b);
            lds2(w01, w23, wA[2] + off);
            ffma2(az00, w01, h0a); ffma2(az00, w23, h0b);
            ffma2(az10, w01, h1a); ffma2(az10, w23, h1b);
            lds2(w01, w23, wA[3] + off);
            ffma2(az01, w01, h0a); ffma2(az01, w23, h0b);
            ffma2(az11, w01, h1a); ffma2(az11, w23, h1b);
            lds2(w01, w23, wA[4] + off);
            ffma2(an00, w01, h0a); ffma2(an00, w23, h0b);
            ffma2(an10, w01, h1a); ffma2(an10, w23, h1b);
            lds2(w01, w23, wA[5] + off);
            ffma2(an01, w01, h0a); ffma2(an01, w23, h0b);
            ffma2(an11, w01, h1a); ffma2(an11, w23, h1b);
        }
        if (kq > 0) {
            float* rp = myred + (kq - 1) * (128 * 13);
            rp[0]  = uns(ar00); rp[1]  = uns(ar01);
            rp[2]  = uns(az00); rp[3]  = uns(az01);
            rp[4]  = uns(an00); rp[5]  = uns(an01);
            rp[6]  = uns(ar10); rp[7]  = uns(ar11);
            rp[8]  = uns(az10); rp[9]  = uns(az11);
            rp[10] = uns(an10); rp[11] = uns(an11);
        }
        __syncthreads();
        if (kq == 0) {
            float s[12];
            s[0] = uns(ar00); s[1] = uns(ar01); s[2] = uns(az00); s[3] = uns(az01);
            s[4] = uns(an00); s[5] = uns(an01); s[6] = uns(ar10); s[7] = uns(ar11);
            s[8] = uns(az10); s[9] = uns(az11); s[10] = uns(an10); s[11] = uns(an11);
            #pragma unroll
            for (int p = 0; p < 3; p++) {
                float* rp = myred + p * (128 * 13);
                #pragma unroll
                for (int v = 0; v < 12; v++) s[v] += rp[v];
            }
            float r, z, n, ho;
            r = sigm(gr00 + s[0]);
            z = sigm(gz00 + s[2]);
            n = tanhf(gn00 + r * s[4]);
            ho = hst[q0 * HSTR + j0];
            hn_[(q0 << 8) + j0] = (1.0f - z) * n + z * ho;
            r = sigm(gr01 + s[1]);
            z = sigm(gz01 + s[3]);
            n = tanhf(gn01 + r * s[5]);
            ho = hst[q0 * HSTR + j1];
            hn_[(q0 << 8) + j1] = (1.0f - z) * n + z * ho;
            r = sigm(gr10 + s[6]);
            z = sigm(gz10 + s[8]);
            n = tanhf(gn10 + r * s[10]);
            ho = hst[q1 * HSTR + j0];
            hn_[(q1 << 8) + j0] = (1.0f - z) * n + z * ho;
            r = sigm(gr11 + s[7]);
            z = sigm(gz11 + s[9]);
            n = tanhf(gn11 + r * s[11]);
            ho = hst[q1 * HSTR + j1];
            hn_[(q1 << 8) + j1] = (1.0f - z) * n + z * ho;
        }
        bar_arrive(fl, cb, fbase + t + 1);
        bar_wait(fl, 32, fbase + t + 1);
    }
}

// ---------------- persistent kernel ----------------
__global__ void __launch_bounds__(NTHR, 1)
fmn_kernel(const int* __restrict__ q_tok, const int* __restrict__ p_tok, const int* __restrict__ n_tok,
           const float* __restrict__ term_emb, const float* __restrict__ term_Wih,
           const float* __restrict__ term_Whh, const float* __restrict__ term_bih,
           const float* __restrict__ term_bhh,
           const float* __restrict__ doc_emb,
           const float* __restrict__ dc_Wih, const float* __restrict__ dc_Whh,
           const float* __restrict__ dc_bih, const float* __restrict__ dc_bhh,
           const float* __restrict__ da_Wih, const float* __restrict__ da_Whh,
           const float* __restrict__ da_bih, const float* __restrict__ da_bhh,
           const float* __restrict__ pos_table, const float* __restrict__ posd_W,
           const float* __restrict__ posd_b,
           const float* __restrict__ qy_Wih, const float* __restrict__ qy_Whh,
           const float* __restrict__ qy_bih, const float* __restrict__ qy_bhh,
           float* __restrict__ out)
{
    __shared__ float ws[24 * 256];
    __shared__ float red[3 * 128 * 13];
    extern __shared__ float dyn[];
    int bid = blockIdx.x;
    int tid = threadIdx.x;
    int half = tid >> 8;                   // 0/1: phase0 virtual half
    unsigned ball = rd_base(g_f_all, bid);

    if (bid < 32) {
        int gid = bid;
        unsigned bp0 = rd_base(g_f_p0c, gid);
        unsigned brr = rd_base(g_f_rc, gid);
        if (gid == 0)
            for (int i = tid; i < DTn * Hn; i += NTHR) g_hc[0][i] = 0.0f;
        transpose_w(gid, dc_Wih, g_wt_c, dyn);
        bar_arrive(g_f_p0c, gid, bp0 + 1); bar_wait(g_f_p0c, NB_DOC, bp0 + 1);
        phase0_gemm(gid * 2 + half, NB_DOC * 2, half, LD * DTn, 1, p_tok, n_tok,
                    doc_emb, g_wt_c, dc_bih, g_gi_c, dyn + half * 2048);
        bar_arrive(g_f_p0c, gid, bp0 + 2); bar_wait(g_f_p0c, NB_DOC, bp0 + 2);
        run_doc(gid, dc_Whh, dc_bhh, g_gi_c, g_hc[0], g_hc[1], g_f_rc, brr, ws, red, dyn);
    } else if (bid < 64) {
        int gid = bid - 32;
        unsigned bp0 = rd_base(g_f_p0a, gid);
        unsigned brr = rd_base(g_f_ra, gid);
        if (gid == 0)
            for (int i = tid; i < DTn * Hn; i += NTHR) g_ha[0][i] = 0.0f;
        transpose_w(gid, da_Wih, g_wt_a, dyn);
        bar_arrive(g_f_p0a, gid, bp0 + 1); bar_wait(g_f_p0a, NB_DOC, bp0 + 1);
        phase0_gemm(gid * 2 + half, NB_DOC * 2, half, LD * DTn, 1, p_tok, n_tok,
                    doc_emb, g_wt_a, da_bih, g_gi_a, dyn + half * 2048);
        bar_arrive(g_f_p0a, gid, bp0 + 2); bar_wait(g_f_p0a, NB_DOC, bp0 + 2);
        run_doc(gid, da_Whh, da_bhh, g_gi_a, g_ha[0], g_ha[1], g_f_ra, brr, ws, red, dyn);
    } else if (bid < 96) {
        int gid = bid - 64;
        unsigned bp0 = rd_base(g_f_p0t, gid);
        unsigned brr = rd_base(g_f_rt, gid);
        if (gid == 0)
            for (int i = tid; i < Qn * Hn; i += NTHR) g_hq[0][i] = 0.0f;
        transpose_w(gid, term_Wih, g_wt_q, dyn);
        bar_arrive(g_f_p0t, gid, bp0 + 1); bar_wait(g_f_p0t, NB_TRM, bp0 + 1);
        phase0_gemm(gid * 2 + half, NB_TRM * 2, half, LQ * Qn, 0, q_tok, (const int*)0,
                    term_emb, g_wt_q, term_bih, g_gi_q, dyn + half * 2048);
        bar_arrive(g_f_p0t, gid, bp0 + 2); bar_wait(g_f_p0t, NB_TRM, bp0 + 2);
        run_term(gid, term_Whh, term_bhh, g_f_rt, brr, ws, red, dyn);
    } else if (bid < 116) {
        int gid = bid - 96 + 32;
        unsigned bp0 = rd_base(g_f_p0c, gid);
        bar_arrive(g_f_p0c, gid, bp0 + 1); bar_wait(g_f_p0c, NB_DOC, bp0 + 1);
        phase0_gemm(gid * 2 + half, NB_DOC * 2, half, LD * DTn, 1, p_tok, n_tok,
                    doc_emb, g_wt_c, dc_bih, g_gi_c, dyn + half * 2048);
        bar_arrive(g_f_p0c, gid, bp0 + 2);
    } else if (bid < 136) {
        int gid = bid - 116 + 32;
        unsigned bp0 = rd_base(g_f_p0a, gid);
        bar_arrive(g_f_p0a, gid, bp0 + 1); bar_wait(g_f_p0a, NB_DOC, bp0 + 1);
        phase0_gemm(gid * 2 + half, NB_DOC * 2, half, LD * DTn, 1, p_tok, n_tok,
                    doc_emb, g_wt_a, da_bih, g_gi_a, dyn + half * 2048);
        bar_arrive(g_f_p0a, gid, bp0 + 2);
    } else {
        int gid = bid - 136 + 32;
        unsigned bp0 = rd_base(g_f_p0t, gid);
        bar_arrive(g_f_p0t, gid, bp0 + 1); bar_wait(g_f_p0t, NB_TRM, bp0 + 1);
        phase0_gemm(gid * 2 + half, NB_TRM * 2, half, LQ * Qn, 0, q_tok, (const int*)0,
                    term_emb, g_wt_q, term_bih, g_gi_q, dyn + half * 2048);
        bar_arrive(g_f_p0t, gid, bp0 + 2);
    }

    // long barrier: idle/early blocks back off so chain-barrier L2 traffic is clean
    bar_arrive(g_f_all, bid, ball + 1); bar_wait_ns(g_f_all, NBLK, ball + 1);

    // ---- phase A: position dense (blocks 0..23; threads 0..255 active) ----
    if (bid < DTn) {
        float* hrow = ws;
        if (tid < 256) hrow[tid] = __ldcg(&g_hc[0][bid * Hn + tid]);
        __syncthreads();
        if (tid < 256) {
            int dset = bid % DSET;
            float pe0 = __ldg(&pos_table[dset * 4 + 0]);
            float pe1 = __ldg(&pos_table[dset * 4 + 1]);
            float pe2 = __ldg(&pos_table[dset * 4 + 2]);
            float pe3 = __ldg(&pos_table[dset * 4 + 3]);
            int j = tid;
            const float* wrow = posd_W + (size_t)j * (Hn + 4);
            unsigned xsa = sptr(hrow);
            u64 acc = pk(0.0f, 0.0f);
            #pragma unroll 4
            for (int ii = 0; ii < 64; ii++) {
                u64 w01, w23, x01, x23;
                ldg2(w01, w23, wrow + (ii << 2));
                lds2(x01, x23, xsa + (ii << 4));
                ffma2(acc, w01, x01);
                ffma2(acc, w23, x23);
            }
            float a = uns(acc);
            a = fmaf(pe0, __ldg(wrow + 256), a);
            a = fmaf(pe1, __ldg(wrow + 257), a);
            a = fmaf(pe2, __ldg(wrow + 258), a);
            a = fmaf(pe3, __ldg(wrow + 259), a);
            a += __ldg(&posd_b[j]);
            g_attc[bid * Hn + j] = a;
        }
    } else if (bid >= 32 && bid < 96) {
        // ---- phase B: attention scores ----
        int q = bid - 32;
        float* eq = ws;
        if (tid < 256) eq[tid] = __ldcg(&g_hq[0][q * Hn + tid]);
        __syncthreads();
        if (tid < DTn) {
            const float4* ap = (const float4*)(g_ha[0] + tid * Hn);
            const float4* e4 = (const float4*)eq;
            float acc = 0.0f;
            #pragma unroll 4
            for (int ii = 0; ii < 64; ii++) {
                float4 a4 = __ldcg(ap + ii);
                float4 x4 = e4[ii];
                acc = fmaf(a4.x, x4.x, acc);
                acc = fmaf(a4.y, x4.y, acc);
                acc = fmaf(a4.z, x4.z, acc);
                acc = fmaf(a4.w, x4.w, acc);
            }
            g_scores[q * DTn + tid] = acc;
        }
    }

    bar_arrive(g_f_all, bid, ball + 2); bar_wait_ns(g_f_all, NBLK, ball + 2);

    // ---- phase C: softmax + memory read + final GRU (blocks 0..63) ----
    if (bid < Qn) {
        int q = bid;
        float* sv = ws;
        float* wv = ws + 32;
        float* qs = ws + 64;
        if (tid < DTn) sv[tid] = __ldcg(&g_scores[q * DTn + tid]);
        __syncthreads();
        if (tid < 2) {
            int off = tid * DSET;
            float mx = -1e30f;
            for (int d2 = 0; d2 < DSET; d2++) mx = fmaxf(mx, sv[off + d2]);
            float s = 0.0f;
            for (int d2 = 0; d2 < DSET; d2++) {
                float e = __expf(sv[off + d2] - mx);
                wv[off + d2] = e;
                s += e;
            }
            float inv = 1.0f / s;
            for (int d2 = 0; d2 < DSET; d2++) wv[off + d2] *= inv;
        }
        __syncthreads();
        if (tid < 256) {
            int j = tid;
            float val = __ldcg(&g_hq[0][q * Hn + j]);
            #pragma unroll
            for (int d2 = 0; d2 < DSET; d2++)
                val = fmaf(wv[d2], __ldcg(&g_attc[d2 * Hn + j]), val);
            #pragma unroll
            for (int d2 = 0; d2 < DSET; d2++)
                val = fmaf(wv[DSET + d2], __ldcg(&g_attc[(DSET + d2) * Hn + j]), val);
            qs[j] = val;
        }
        __syncthreads();
        if (tid < 256) {
            int j = tid;
            u64 dr = pk(0.0f, 0.0f), dz = pk(0.0f, 0.0f), dn = pk(0.0f, 0.0f);
            unsigned qsa = sptr(qs);
            const float* wr = qy_Wih + (size_t)j * Hn;
            const float* wz = qy_Wih + (size_t)(Hn + j) * Hn;
            const float* wn = qy_Wih + (size_t)(2 * Hn + j) * Hn;
            #pragma unroll 4
            for (int ii = 0; ii < 64; ii++) {
                u64 x01, x23, w01, w23;
                lds2(x01, x23, qsa + (ii << 4));
                ldg2(w01, w23, wr + (ii << 2));
                ffma2(dr, w01, x01); ffma2(dr, w23, x23);
                ldg2(w01, w23, wz + (ii << 2));
                ffma2(dz, w01, x01); ffma2(dz, w23, x23);
                ldg2(w01, w23, wn + (ii << 2));
                ffma2(dn, w01, x01); ffma2(dn, w23, x23);
            }
            float r = sigm(uns(dr) + __ldg(&qy_bih[j]) + __ldg(&qy_bhh[j]));
            float z = sigm(uns(dz) + __ldg(&qy_bih[Hn + j]) + __ldg(&qy_bhh[Hn + j]));
            float n = tanhf(uns(dn) + __ldg(&qy_bih[2 * Hn + j]) + r * __ldg(&qy_bhh[2 * Hn + j]));
            out[q * Hn + j] = (1.0f - z) * n;
        }
    }
}

extern "C" void kernel_launch(void* const* d_in, const int* in_sizes, int n_in,
                              void* d_out, int out_size) {
    const int*   q_tok    = (const int*)d_in[0];
    const int*   p_tok    = (const int*)d_in[1];
    const int*   n_tok    = (const int*)d_in[2];
    const float* term_emb = (const float*)d_in[3];
    const float* term_Wih = (const float*)d_in[4];
    const float* term_Whh = (const float*)d_in[5];
    const float* term_bih = (const float*)d_in[6];
    const float* term_bhh = (const float*)d_in[7];
    const float* doc_emb  = (const float*)d_in[8];
    const float* dc_Wih   = (const float*)d_in[9];
    const float* dc_Whh   = (const float*)d_in[10];
    const float* dc_bih   = (const float*)d_in[11];
    const float* dc_bhh   = (const float*)d_in[12];
    const float* da_Wih   = (const float*)d_in[13];
    const float* da_Whh   = (const float*)d_in[14];
    const float* da_bih   = (const float*)d_in[15];
    const float* da_bhh   = (const float*)d_in[16];
    const float* pos_tab  = (const float*)d_in[17];
    const float* posd_W   = (const float*)d_in[18];
    const float* posd_b   = (const float*)d_in[19];
    const float* qy_Wih   = (const float*)d_in[20];
    const float* qy_Whh   = (const float*)d_in[21];
    const float* qy_bih   = (const float*)d_in[22];
    const float* qy_bhh   = (const float*)d_in[23];
    float* out = (float*)d_out;

    const int dyn_bytes = 64 * HSTR * 4;   // 66560: term h stage / transpose buf / 2x phase0 xs
    cudaFuncSetAttribute(fmn_kernel, cudaFuncAttributeMaxDynamicSharedMemorySize, dyn_bytes);
    fmn_kernel<<<NBLK, NTHR, dyn_bytes>>>(q_tok, p_tok, n_tok,
                            term_emb, term_Wih, term_Whh, term_bih, term_bhh,
                            doc_emb, dc_Wih, dc_Whh, dc_bih, dc_bhh,
                            da_Wih, da_Whh, da_bih, da_bhh,
                            pos_tab, posd_W, posd_b,
                            qy_Wih, qy_Whh, qy_bih, qy_bhh,
                            out);
}

// round 17
// speedup vs baseline: 1.3078x; 1.0251x over previous
#include <cuda_runtime.h>

typedef unsigned long long u64;

#define Qn   64
#define LQ   20
#define DSET 12
#define DTn  24
#define LD   50
#define Hn   256
#define G3   768
#define HSTR 260
#define NB_DOC 52   // 32 mains (chain) + 20 helpers
#define NB_TRM 40   // 32 mains + 8 helpers
#define NBLK 144
#define NTHR 512

// ---------------- device scratch ----------------
__device__ float g_gi_q[LQ * Qn * G3];
__device__ float g_gi_c[LD * DTn * G3];
__device__ float g_gi_a[LD * DTn * G3];
__device__ float4 g_wt_c[64 * G3];
__device__ float4 g_wt_a[64 * G3];
__device__ float4 g_wt_q[64 * G3];
__device__ float g_hq[2][Qn * Hn];
__device__ float g_hc[2][DTn * Hn];
__device__ float g_ha[2][DTn * Hn];
__device__ float g_attc[DTn * Hn];
__device__ float g_scores[Qn * DTn];
__device__ unsigned g_f_p0c[NB_DOC * 32];
__device__ unsigned g_f_p0a[NB_DOC * 32];
__device__ unsigned g_f_p0t[NB_TRM * 32];
__device__ unsigned g_f_rc[32 * 32];
__device__ unsigned g_f_ra[32 * 32];
__device__ unsigned g_f_rt[32 * 32];
__device__ unsigned g_f_all[NBLK * 32];

// ---------------- helpers ----------------
__device__ __forceinline__ float sigm(float x) { return 1.0f / (1.0f + __expf(-x)); }
__device__ __forceinline__ u64 pk(float lo, float hi) {
    u64 r; asm("mov.b64 %0, {%1,%2};" : "=l"(r) : "f"(lo), "f"(hi)); return r;
}
__device__ __forceinline__ float uns(u64 v) {
    float lo, hi; asm("mov.b64 {%0,%1}, %2;" : "=f"(lo), "=f"(hi) : "l"(v));
    return lo + hi;
}
__device__ __forceinline__ void ffma2(u64& d, u64 a, u64 b) {
    asm("fma.rn.f32x2 %0, %1, %2, %0;" : "+l"(d) : "l"(a), "l"(b));
}
__device__ __forceinline__ unsigned sptr(const void* p) {
    return (unsigned)__cvta_generic_to_shared(p);
}
__device__ __forceinline__ void lds2(u64& a, u64& b, unsigned addr) {
    asm volatile("ld.shared.v2.u64 {%0,%1}, [%2];" : "=l"(a), "=l"(b) : "r"(addr));
}
__device__ __forceinline__ void ldg2(u64& a, u64& b, const float* p) {
    asm volatile("ld.global.nc.v2.u64 {%0,%1}, [%2];" : "=l"(a), "=l"(b) : "l"(p));
}
__device__ __forceinline__ void barh(int h) {
    asm volatile("bar.sync %0, %1;" :: "r"(1 + h), "r"(256) : "memory");
}

// ---- flag barrier ----
__device__ __forceinline__ void bar_arrive(unsigned* fl, int idx, unsigned gen) {
    __syncthreads();
    if (threadIdx.x == 0)
        asm volatile("st.release.gpu.global.u32 [%0], %1;"
                     :: "l"(fl + idx * 32), "r"(gen) : "memory");
}
__device__ __forceinline__ void bar_wait(unsigned* fl, int n, unsigned gen) {
    if (threadIdx.x < (unsigned)n) {
        unsigned cur;
        do {
            asm volatile("ld.acquire.gpu.global.u32 %0, [%1];"
                         : "=r"(cur) : "l"(fl + threadIdx.x * 32) : "memory");
        } while (cur < gen);
    }
    __syncthreads();
}
__device__ __forceinline__ void bar_wait_ns(unsigned* fl, int n, unsigned gen) {
    if (threadIdx.x < (unsigned)n) {
        unsigned cur;
        asm volatile("ld.acquire.gpu.global.u32 %0, [%1];"
                     : "=r"(cur) : "l"(fl + threadIdx.x * 32) : "memory");
        while (cur < gen) {
            __nanosleep(400);
            asm volatile("ld.acquire.gpu.global.u32 %0, [%1];"
                         : "=r"(cur) : "l"(fl + threadIdx.x * 32) : "memory");
        }
    }
    __syncthreads();
}
// poll one flag (callers: exactly the threads consuming the guarded data)
__device__ __forceinline__ void poll_flag(const unsigned* fp, unsigned gen) {
    unsigned cur;
    do {
        asm volatile("ld.acquire.gpu.global.u32 %0, [%1];"
                     : "=r"(cur) : "l"(fp) : "memory");
    } while (cur < gen);
}
__device__ __forceinline__ unsigned rd_base(unsigned* fl, int idx) {
    return *(volatile unsigned*)(fl + idx * 32);
}

// ---------------- W transpose (512 threads) ----------------
__device__ void transpose_w(int gid, const float* __restrict__ W, float4* __restrict__ Wt,
                            float* sbuf)
{
    int tid = threadIdx.x;
    int r0 = gid * 24;
    for (int i = tid; i < 24 * 256; i += NTHR) {
        int rl = i >> 8, j = i & 255;
        sbuf[rl * 260 + j] = __ldg(W + (size_t)(r0 + rl) * Hn + j);
    }
    __syncthreads();
    for (int i = tid; i < 24 * 64; i += NTHR) {
        int rl = i % 24, kk = i / 24;
        float4 v = *(float4*)(sbuf + rl * 260 + (kk << 2));
        Wt[kk * G3 + r0 + rl] = v;
    }
    __syncthreads();
}

// ---------------- phase 0 over explicit row range [r0, r1) ----------------
__device__ void phase0_gemm(int r0, int r1, int half, int mode,
                            const int* __restrict__ tokA, const int* __restrict__ tokB,
                            const float* __restrict__ emb, const float4* __restrict__ Wt,
                            const float* __restrict__ bias, float* __restrict__ gi,
                            float* xs)
{
    int th = threadIdx.x & 255;
    unsigned xsa = sptr(xs);
    float b0 = __ldg(bias + th), b1 = __ldg(bias + th + 256), b2 = __ldg(bias + th + 512);

    for (int rt = r0; rt < r1; rt += 8) {
        int nr = min(8, r1 - rt);
        barh(half);
        for (int idx = th; idx < (nr << 8); idx += 256) {
            int rl = idx >> 8, j = idx & 255;
            int r = rt + rl;
            int tok;
            if (mode == 0) {
                int t = r >> 6, q = r & 63;
                tok = tokA[q * LQ + t];
            } else {
                int t = r / DTn, dt = r - t * DTn;
                tok = (dt < DSET) ? tokA[dt * LD + t] : tokB[(dt - DSET) * LD + t];
            }
            xs[(rl << 8) + j] = __ldg(emb + (size_t)tok * Hn + j);
        }
        barh(half);

        u64 acc[3][8];
        #pragma unroll
        for (int rl = 0; rl < 8; rl++) {
            acc[0][rl] = pk(b0, 0.0f);
            acc[1][rl] = pk(b1, 0.0f);
            acc[2][rl] = pk(b2, 0.0f);
        }
        #pragma unroll 2
        for (int jj = 0; jj < 64; jj++) {
            const float* wp = (const float*)(Wt + jj * G3 + th);
            u64 w0a, w0b, w1a, w1b, w2a, w2b;
            ldg2(w0a, w0b, wp);
            ldg2(w1a, w1b, wp + 1024);
            ldg2(w2a, w2b, wp + 2048);
            unsigned xo = xsa + (jj << 4);
            #pragma unroll
            for (int rlb = 0; rlb < 2; rlb++) {
                u64 x01[4], x23[4];
                #pragma unroll
                for (int rl = 0; rl < 4; rl++)
                    lds2(x01[rl], x23[rl], xo + ((rlb * 4 + rl) << 10));
                #pragma unroll
                for (int rl = 0; rl < 4; rl++) {
                    int ri = rlb * 4 + rl;
                    ffma2(acc[0][ri], w0a, x01[rl]); ffma2(acc[0][ri], w0b, x23[rl]);
                    ffma2(acc[1][ri], w1a, x01[rl]); ffma2(acc[1][ri], w1b, x23[rl]);
                    ffma2(acc[2][ri], w2a, x01[rl]); ffma2(acc[2][ri], w2b, x23[rl]);
                }
            }
        }
        for (int rl = 0; rl < nr; rl++) {
            float* gr = gi + (size_t)(rt + rl) * G3 + th;
            gr[0]   = uns(acc[0][rl]);
            gr[256] = uns(acc[1][rl]);
            gr[512] = uns(acc[2][rl]);
        }
    }
}

// ---------------- doc recurrence: 16 warps, k-quarter split ----------------
__device__ void run_doc(int cb, const float* __restrict__ Whh, const float* __restrict__ bhh,
                        const float* __restrict__ gi, float* hb0, float* hb1,
                        unsigned* fl, unsigned fbase, float* ws, float* red, float* hst,
                        unsigned* flp0, unsigned bp0)
{
    int tid = threadIdx.x;
    int cbase = cb << 3;
    for (int idx = tid; idx < 6144; idx += NTHR) {
        int rl = idx >> 8, j = idx & 255;
        int gate = rl >> 3, cc = rl & 7;
        ws[idx] = __ldg(Whh + (size_t)(gate * Hn + cbase + cc) * Hn + j);
    }
    int wid = tid >> 5, lane = tid & 31;
    int kq = wid >> 2, wl = wid & 3;
    int c0 = wl * 2, c1 = c0 + 1;
    int j0 = cbase + c0, j1 = cbase + c1;
    bool fin = (kq == 0) && (lane < DTn);
    float br0 = 0.f, bz0 = 0.f, bn0 = 0.f, br1 = 0.f, bz1 = 0.f, bn1 = 0.f;
    if (kq == 0) {
        br0 = __ldg(bhh + j0); bz0 = __ldg(bhh + Hn + j0); bn0 = __ldg(bhh + 2 * Hn + j0);
        br1 = __ldg(bhh + j1); bz1 = __ldg(bhh + Hn + j1); bn1 = __ldg(bhh + 2 * Hn + j1);
    }
    unsigned wsa = sptr(ws);
    unsigned kofs = (unsigned)kq * 256;
    unsigned wA[6];
    #pragma unroll
    for (int g = 0; g < 3; g++) {
        wA[g * 2 + 0] = wsa + ((g * 8 + c0) << 10) + kofs;
        wA[g * 2 + 1] = wsa + ((g * 8 + c1) << 10) + kofs;
    }
    unsigned hA = sptr(hst) + (unsigned)lane * (HSTR * 4) + kofs;
    float* myred = red + (wl * 32 + lane) * 7;
    float* hb[2] = { hb0, hb1 };

    for (int t = 0; t < LD; t++) {
        const float4* hg = (const float4*)hb[t & 1];
        float* hn_ = hb[(t & 1) ^ 1];
        #pragma unroll
        for (int i = 0; i < 3; i++) {
            int idx = tid + (i << 9);
            int row = idx >> 6, col = idx & 63;
            float4 v = __ldcg(hg + idx);
            *(float4*)(hst + row * HSTR + (col << 2)) = v;
        }
        float g_r0 = 0.f, g_z0 = 0.f, g_n0 = 0.f, g_r1 = 0.f, g_z1 = 0.f, g_n1 = 0.f;
        if (fin) {
            // steps >=16 use helper-produced gi; helper block (32 + (hv-1)/2) owns it
            if (t >= 16) {
                int hv = (24 * (t + 1) - 384 + 20) / 21;
                poll_flag(flp0 + (32 + ((hv - 1) >> 1)) * 32, bp0 + 2);
            }
            const float* gib = gi + ((size_t)t * DTn + lane) * G3;
            g_r0 = __ldg(gib + j0); g_z0 = __ldg(gib + Hn + j0); g_n0 = __ldg(gib + 2 * Hn + j0);
            g_r1 = __ldg(gib + j1); g_z1 = __ldg(gib + Hn + j1); g_n1 = __ldg(gib + 2 * Hn + j1);
        }
        __syncthreads();
        u64 ar0 = pk(br0, 0.f), az0 = pk(bz0, 0.f), an0 = pk(bn0, 0.f);
        u64 ar1 = pk(br1, 0.f), az1 = pk(bz1, 0.f), an1 = pk(bn1, 0.f);
        #pragma unroll 4
        for (int jj = 0; jj < 16; jj++) {
            unsigned off = jj << 4;
            u64 h01, h23, w01, w23;
            lds2(h01, h23, hA + off);
            lds2(w01, w23, wA[0] + off);
            ffma2(ar0, w01, h01); ffma2(ar0, w23, h23);
            lds2(w01, w23, wA[1] + off);
            ffma2(ar1, w01, h01); ffma2(ar1, w23, h23);
            lds2(w01, w23, wA[2] + off);
            ffma2(az0, w01, h01); ffma2(az0, w23, h23);
            lds2(w01, w23, wA[3] + off);
            ffma2(az1, w01, h01); ffma2(az1, w23, h23);
            lds2(w01, w23, wA[4] + off);
            ffma2(an0, w01, h01); ffma2(an0, w23, h23);
            lds2(w01, w23, wA[5] + off);
            ffma2(an1, w01, h01); ffma2(an1, w23, h23);
        }
        if (kq > 0) {
            float* rp = myred + (kq - 1) * (128 * 7);
            rp[0] = uns(ar0); rp[1] = uns(ar1);
            rp[2] = uns(az0); rp[3] = uns(az1);
            rp[4] = uns(an0); rp[5] = uns(an1);
        }
        __syncthreads();
        if (fin) {
            float sr0 = uns(ar0), sr1 = uns(ar1);
            float sz0 = uns(az0), sz1 = uns(az1);
            float sn0 = uns(an0), sn1 = uns(an1);
            #pragma unroll
            for (int p = 0; p < 3; p++) {
                float* rp = myred + p * (128 * 7);
                sr0 += rp[0]; sr1 += rp[1];
                sz0 += rp[2]; sz1 += rp[3];
                sn0 += rp[4]; sn1 += rp[5];
            }
            float r0 = sigm(g_r0 + sr0);
            float r1 = sigm(g_r1 + sr1);
            float z0 = sigm(g_z0 + sz0);
            float z1 = sigm(g_z1 + sz1);
            float n0 = tanhf(g_n0 + r0 * sn0);
            float n1 = tanhf(g_n1 + r1 * sn1);
            float ho0 = hst[lane * HSTR + j0];
            float ho1 = hst[lane * HSTR + j1];
            hn_[(lane << 8) + j0] = (1.0f - z0) * n0 + z0 * ho0;
            hn_[(lane << 8) + j1] = (1.0f - z1) * n1 + z1 * ho1;
        }
        bar_arrive(fl, cb, fbase + t + 1);
        bar_wait(fl, 32, fbase + t + 1);
    }
}

// ---------------- term recurrence: 16 warps, k-quarter split, 2 q-halves ----------------
__device__ void run_term(int cb, const float* __restrict__ Whh, const float* __restrict__ bhh,
                         unsigned* fl, unsigned fbase, float* ws, float* red, float* hst,
                         unsigned* flp0, unsigned bp0)
{
    int tid = threadIdx.x;
    int cbase = cb << 3;
    for (int idx = tid; idx < 6144; idx += NTHR) {
        int rl = idx >> 8, j = idx & 255;
        int gate = rl >> 3, cc = rl & 7;
        ws[idx] = __ldg(Whh + (size_t)(gate * Hn + cbase + cc) * Hn + j);
    }
    int wid = tid >> 5, lane = tid & 31;
    int kq = wid >> 2, wl = wid & 3;
    int c0 = wl * 2, c1 = c0 + 1;
    int j0 = cbase + c0, j1 = cbase + c1;
    float br0 = 0.f, bz0 = 0.f, bn0 = 0.f, br1 = 0.f, bz1 = 0.f, bn1 = 0.f;
    if (kq == 0) {
        br0 = __ldg(bhh + j0); bz0 = __ldg(bhh + Hn + j0); bn0 = __ldg(bhh + 2 * Hn + j0);
        br1 = __ldg(bhh + j1); bz1 = __ldg(bhh + Hn + j1); bn1 = __ldg(bhh + 2 * Hn + j1);
    }
    unsigned wsa = sptr(ws);
    unsigned kofs = (unsigned)kq * 256;
    unsigned wA[6];
    #pragma unroll
    for (int g = 0; g < 3; g++) {
        wA[g * 2 + 0] = wsa + ((g * 8 + c0) << 10) + kofs;
        wA[g * 2 + 1] = wsa + ((g * 8 + c1) << 10) + kofs;
    }
    unsigned h0A = sptr(hst) + (unsigned)lane * (HSTR * 4) + kofs;
    unsigned h1A = sptr(hst) + (unsigned)(lane + 32) * (HSTR * 4) + kofs;
    float* myred = red + (wl * 32 + lane) * 13;

    for (int t = 0; t < LQ; t++) {
        const float4* hg = (const float4*)g_hq[t & 1];
        float* hn_ = g_hq[(t & 1) ^ 1];
        #pragma unroll
        for (int i = 0; i < 8; i++) {
            int idx = tid + (i << 9);
            int row = idx >> 6, col = idx & 63;
            float4 v = __ldcg(hg + idx);
            *(float4*)(hst + row * HSTR + (col << 2)) = v;
        }
        int q0 = lane, q1 = lane + 32;
        float gr00 = 0.f, gz00 = 0.f, gn00 = 0.f, gr01 = 0.f, gz01 = 0.f, gn01 = 0.f;
        float gr10 = 0.f, gz10 = 0.f, gn10 = 0.f, gr11 = 0.f, gz11 = 0.f, gn11 = 0.f;
        if (kq == 0) {
            if (t >= 8) {
                int hv = (64 * (t + 1) - 512 + 47) / 48;
                poll_flag(flp0 + (32 + ((hv - 1) >> 1)) * 32, bp0 + 2);
            }
            const float* gA = g_gi_q + ((size_t)t * Qn + q0) * G3;
            const float* gB = g_gi_q + ((size_t)t * Qn + q1) * G3;
            gr00 = __ldg(gA + j0); gz00 = __ldg(gA + Hn + j0); gn00 = __ldg(gA + 2 * Hn + j0);
            gr01 = __ldg(gA + j1); gz01 = __ldg(gA + Hn + j1); gn01 = __ldg(gA + 2 * Hn + j1);
            gr10 = __ldg(gB + j0); gz10 = __ldg(gB + Hn + j0); gn10 = __ldg(gB + 2 * Hn + j0);
            gr11 = __ldg(gB + j1); gz11 = __ldg(gB + Hn + j1); gn11 = __ldg(gB + 2 * Hn + j1);
        }
        __syncthreads();
        u64 ar00 = pk(br0, 0.f), az00 = pk(bz0, 0.f), an00 = pk(bn0, 0.f);
        u64 ar01 = pk(br1, 0.f), az01 = pk(bz1, 0.f), an01 = pk(bn1, 0.f);
        u64 ar10 = pk(br0, 0.f), az10 = pk(bz0, 0.f), an10 = pk(bn0, 0.f);
        u64 ar11 = pk(br1, 0.f), az11 = pk(bz1, 0.f), an11 = pk(bn1, 0.f);
        #pragma unroll 4
        for (int jj = 0; jj < 16; jj++) {
            unsigned off = jj << 4;
            u64 h0a, h0b, h1a, h1b, w01, w23;
            lds2(h0a, h0b, h0A + off);
            lds2(h1a, h1b, h1A + off);
            lds2(w01, w23, wA[0] + off);
            ffma2(ar00, w01, h0a); ffma2(ar00, w23, h0b);
            ffma2(ar10, w01, h1a); ffma2(ar10, w23, h1b);
            lds2(w01, w23, wA[1] + off);
            ffma2(ar01, w01, h0a); ffma2(ar01, w23, h0b);
            ffma2(ar11, w01, h1a); ffma2(ar11, w23, h1b);
            lds2(w01, w23, wA[2] + off);
            ffma2(az00, w01, h0a); ffma2(az00, w23, h0b);
            ffma2(az10, w01, h1a); ffma2(az10, w23, h1b);
            lds2(w01, w23, wA[3] + off);
            ffma2(az01, w01, h0a); ffma2(az01, w23, h0b);
            ffma2(az11, w01, h1a); ffma2(az11, w23, h1b);
            lds2(w01, w23, wA[4] + off);
            ffma2(an00, w01, h0a); ffma2(an00, w23, h0b);
            ffma2(an10, w01, h1a); ffma2(an10, w23, h1b);
            lds2(w01, w23, wA[5] + off);
            ffma2(an01, w01, h0a); ffma2(an01, w23, h0b);
            ffma2(an11, w01, h1a); ffma2(an11, w23, h1b);
        }
        if (kq > 0) {
            float* rp = myred + (kq - 1) * (128 * 13);
            rp[0]  = uns(ar00); rp[1]  = uns(ar01);
            rp[2]  = uns(az00); rp[3]  = uns(az01);
            rp[4]  = uns(an00); rp[5]  = uns(an01);
            rp[6]  = uns(ar10); rp[7]  = uns(ar11);
            rp[8]  = uns(az10); rp[9]  = uns(az11);
            rp[10] = uns(an10); rp[11] = uns(an11);
        }
        __syncthreads();
        if (kq == 0) {
            float s[12];
            s[0] = uns(ar00); s[1] = uns(ar01); s[2] = uns(az00); s[3] = uns(az01);
            s[4] = uns(an00); s[5] = uns(an01); s[6] = uns(ar10); s[7] = uns(ar11);
            s[8] = uns(az10); s[9] = uns(az11); s[10] = uns(an10); s[11] = uns(an11);
            #pragma unroll
            for (int p = 0; p < 3; p++) {
                float* rp = myred + p * (128 * 13);
                #pragma unroll
                for (int v = 0; v < 12; v++) s[v] += rp[v];
            }
            float r, z, n, ho;
            r = sigm(gr00 + s[0]);
            z = sigm(gz00 + s[2]);
            n = tanhf(gn00 + r * s[4]);
            ho = hst[q0 * HSTR + j0];
            hn_[(q0 << 8) + j0] = (1.0f - z) * n + z * ho;
            r = sigm(gr01 + s[1]);
            z = sigm(gz01 + s[3]);
            n = tanhf(gn01 + r * s[5]);
            ho = hst[q0 * HSTR + j1];
            hn_[(q0 << 8) + j1] = (1.0f - z) * n + z * ho;
            r = sigm(gr10 + s[6]);
            z = sigm(gz10 + s[8]);
            n = tanhf(gn10 + r * s[10]);
            ho = hst[q1 * HSTR + j0];
            hn_[(q1 << 8) + j0] = (1.0f - z) * n + z * ho;
            r = sigm(gr11 + s[7]);
            z = sigm(gz11 + s[9]);
            n = tanhf(gn11 + r * s[11]);
            ho = hst[q1 * HSTR + j1];
            hn_[(q1 << 8) + j1] = (1.0f - z) * n + z * ho;
        }
        bar_arrive(fl, cb, fbase + t + 1);
        bar_wait(fl, 32, fbase + t + 1);
    }
}

// ---------------- persistent kernel ----------------
__global__ void __launch_bounds__(NTHR, 1)
fmn_kernel(const int* __restrict__ q_tok, const int* __restrict__ p_tok, const int* __restrict__ n_tok,
           const float* __restrict__ term_emb, const float* __restrict__ term_Wih,
           const float* __restrict__ term_Whh, const float* __restrict__ term_bih,
           const float* __restrict__ term_bhh,
           const float* __restrict__ doc_emb,
           const float* __restrict__ dc_Wih, const float* __restrict__ dc_Whh,
           const float* __restrict__ dc_bih, const float* __restrict__ dc_bhh,
           const float* __restrict__ da_Wih, const float* __restrict__ da_Whh,
           const float* __restrict__ da_bih, const float* __restrict__ da_bhh,
           const float* __restrict__ pos_table, const float* __restrict__ posd_W,
           const float* __restrict__ posd_b,
           const float* __restrict__ qy_Wih, const float* __restrict__ qy_Whh,
           const float* __restrict__ qy_bih, const float* __restrict__ qy_bhh,
           float* __restrict__ out)
{
    __shared__ float ws[24 * 256];
    __shared__ float red[3 * 128 * 13];
    extern __shared__ float dyn[];
    int bid = blockIdx.x;
    int tid = threadIdx.x;
    int half = tid >> 8;
    unsigned ball = rd_base(g_f_all, bid);

    if (bid < 32) {                        // doc-c main: phase0 steps 0..15, then chain
        int gid = bid;
        unsigned bp0 = rd_base(g_f_p0c, gid);
        unsigned brr = rd_base(g_f_rc, gid);
        if (gid == 0)
            for (int i = tid; i < DTn * Hn; i += NTHR) g_hc[0][i] = 0.0f;
        transpose_w(gid, dc_Wih, g_wt_c, dyn);
        bar_arrive(g_f_p0c, gid, bp0 + 1); bar_wait(g_f_p0c, 32, bp0 + 1);
        int r0 = (gid * 2 + half) * 6;
        phase0_gemm(r0, r0 + 6, half, 1, p_tok, n_tok, doc_emb, g_wt_c, dc_bih, g_gi_c,
                    dyn + half * 2048);
        bar_arrive(g_f_p0c, gid, bp0 + 2); bar_wait(g_f_p0c, 32, bp0 + 2);
        run_doc(gid, dc_Whh, dc_bhh, g_gi_c, g_hc[0], g_hc[1], g_f_rc, brr, ws, red, dyn,
                g_f_p0c, bp0);
    } else if (bid < 64) {                 // doc-a main
        int gid = bid - 32;
        unsigned bp0 = rd_base(g_f_p0a, gid);
        unsigned brr = rd_base(g_f_ra, gid);
        if (gid == 0)
            for (int i = tid; i < DTn * Hn; i += NTHR) g_ha[0][i] = 0.0f;
        transpose_w(gid, da_Wih, g_wt_a, dyn);
        bar_arrive(g_f_p0a, gid, bp0 + 1); bar_wait(g_f_p0a, 32, bp0 + 1);
        int r0 = (gid * 2 + half) * 6;
        phase0_gemm(r0, r0 + 6, half, 1, p_tok, n_tok, doc_emb, g_wt_a, da_bih, g_gi_a,
                    dyn + half * 2048);
        bar_arrive(g_f_p0a, gid, bp0 + 2); bar_wait(g_f_p0a, 32, bp0 + 2);
        run_doc(gid, da_Whh, da_bhh, g_gi_a, g_ha[0], g_ha[1], g_f_ra, brr, ws, red, dyn,
                g_f_p0a, bp0);
    } else if (bid < 96) {                 // term main: phase0 steps 0..7, then chain
        int gid = bid - 64;
        unsigned bp0 = rd_base(g_f_p0t, gid);
        unsigned brr = rd_base(g_f_rt, gid);
        if (gid == 0)
            for (int i = tid; i < Qn * Hn; i += NTHR) g_hq[0][i] = 0.0f;
        transpose_w(gid, term_Wih, g_wt_q, dyn);
        bar_arrive(g_f_p0t, gid, bp0 + 1); bar_wait(g_f_p0t, 32, bp0 + 1);
        int r0 = (gid * 2 + half) * 8;
        phase0_gemm(r0, r0 + 8, half, 0, q_tok, (const int*)0, term_emb, g_wt_q, term_bih,
                    g_gi_q, dyn + half * 2048);
        bar_arrive(g_f_p0t, gid, bp0 + 2); bar_wait(g_f_p0t, 32, bp0 + 2);
        run_term(gid, term_Whh, term_bhh, g_f_rt, brr, ws, red, dyn, g_f_p0t, bp0);
    } else if (bid < 116) {                // doc-c helper: rows 384.. (steps 16..49)
        int gid = bid - 96 + 32;
        unsigned bp0 = rd_base(g_f_p0c, gid);
        bar_arrive(g_f_p0c, gid, bp0 + 1); bar_wait(g_f_p0c, 32, bp0 + 1);
        int hv = (gid - 32) * 2 + half;
        int r0 = 384 + hv * 21;
        int r1 = min(LD * DTn, r0 + 21);
        phase0_gemm(r0, r1, half, 1, p_tok, n_tok, doc_emb, g_wt_c, dc_bih, g_gi_c,
                    dyn + half * 2048);
        bar_arrive(g_f_p0c, gid, bp0 + 2);
    } else if (bid < 136) {                // doc-a helper
        int gid = bid - 116 + 32;
        unsigned bp0 = rd_base(g_f_p0a, gid);
        bar_arrive(g_f_p0a, gid, bp0 + 1); bar_wait(g_f_p0a, 32, bp0 + 1);
        int hv = (gid - 32) * 2 + half;
        int r0 = 384 + hv * 21;
        int r1 = min(LD * DTn, r0 + 21);
        phase0_gemm(r0, r1, half, 1, p_tok, n_tok, doc_emb, g_wt_a, da_bih, g_gi_a,
                    dyn + half * 2048);
        bar_arrive(g_f_p0a, gid, bp0 + 2);
    } else {                               // term helper: rows 512.. (steps 8..19)
        int gid = bid - 136 + 32;
        unsigned bp0 = rd_base(g_f_p0t, gid);
        bar_arrive(g_f_p0t, gid, bp0 + 1); bar_wait(g_f_p0t, 32, bp0 + 1);
        int hv = (gid - 32) * 2 + half;
        int r0 = 512 + hv * 48;
        phase0_gemm(r0, r0 + 48, half, 0, q_tok, (const int*)0, term_emb, g_wt_q, term_bih,
                    g_gi_q, dyn + half * 2048);
        bar_arrive(g_f_p0t, gid, bp0 + 2);
    }

    bar_arrive(g_f_all, bid, ball + 1); bar_wait_ns(g_f_all, NBLK, ball + 1);

    // ---- phase A: position dense (blocks 0..23) ----
    if (bid < DTn) {
        float* hrow = ws;
        if (tid < 256) hrow[tid] = __ldcg(&g_hc[0][bid * Hn + tid]);
        __syncthreads();
        if (tid < 256) {
            int dset = bid % DSET;
            float pe0 = __ldg(&pos_table[dset * 4 + 0]);
            float pe1 = __ldg(&pos_table[dset * 4 + 1]);
            float pe2 = __ldg(&pos_table[dset * 4 + 2]);
            float pe3 = __ldg(&pos_table[dset * 4 + 3]);
            int j = tid;
            const float* wrow = posd_W + (size_t)j * (Hn + 4);
            unsigned xsa = sptr(hrow);
            u64 acc = pk(0.0f, 0.0f);
            #pragma unroll 4
            for (int ii = 0; ii < 64; ii++) {
                u64 w01, w23, x01, x23;
                ldg2(w01, w23, wrow + (ii << 2));
                lds2(x01, x23, xsa + (ii << 4));
                ffma2(acc, w01, x01);
                ffma2(acc, w23, x23);
            }
            float a = uns(acc);
            a = fmaf(pe0, __ldg(wrow + 256), a);
            a = fmaf(pe1, __ldg(wrow + 257), a);
            a = fmaf(pe2, __ldg(wrow + 258), a);
            a = fmaf(pe3, __ldg(wrow + 259), a);
            a += __ldg(&posd_b[j]);
            g_attc[bid * Hn + j] = a;
        }
    } else if (bid >= 32 && bid < 96) {
        // ---- phase B: attention scores ----
        int q = bid - 32;
        float* eq = ws;
        if (tid < 256) eq[tid] = __ldcg(&g_hq[0][q * Hn + tid]);
        __syncthreads();
        if (tid < DTn) {
            const float4* ap = (const float4*)(g_ha[0] + tid * Hn);
            const float4* e4 = (const float4*)eq;
            float acc = 0.0f;
            #pragma unroll 4
            for (int ii = 0; ii < 64; ii++) {
                float4 a4 = __ldcg(ap + ii);
                float4 x4 = e4[ii];
                acc = fmaf(a4.x, x4.x, acc);
                acc = fmaf(a4.y, x4.y, acc);
                acc = fmaf(a4.z, x4.z, acc);
                acc = fmaf(a4.w, x4.w, acc);
            }
            g_scores[q * DTn + tid] = acc;
        }
    }

    bar_arrive(g_f_all, bid, ball + 2); bar_wait_ns(g_f_all, NBLK, ball + 2);

    // ---- phase C: softmax + memory read + final GRU (blocks 0..63) ----
    if (bid < Qn) {
        int q = bid;
        float* sv = ws;
        float* wv = ws + 32;
        float* qs = ws + 64;
        if (tid < DTn) sv[tid] = __ldcg(&g_scores[q * DTn + tid]);
        __syncthreads();
        if (tid < 2) {
            int off = tid * DSET;
            float mx = -1e30f;
            for (int d2 = 0; d2 < DSET; d2++) mx = fmaxf(mx, sv[off + d2]);
            float s = 0.0f;
            for (int d2 = 0; d2 < DSET; d2++) {
                float e = __expf(sv[off + d2] - mx);
                wv[off + d2] = e;
                s += e;
            }
            float inv = 1.0f / s;
            for (int d2 = 0; d2 < DSET; d2++) wv[off + d2] *= inv;
        }
        __syncthreads();
        if (tid < 256) {
            int j = tid;
            float val = __ldcg(&g_hq[0][q * Hn + j]);
            #pragma unroll
            for (int d2 = 0; d2 < DSET; d2++)
                val = fmaf(wv[d2], __ldcg(&g_attc[d2 * Hn + j]), val);
            #pragma unroll
            for (int d2 = 0; d2 < DSET; d2++)
                val = fmaf(wv[DSET + d2], __ldcg(&g_attc[(DSET + d2) * Hn + j]), val);
            qs[j] = val;
        }
        __syncthreads();
        if (tid < 256) {
            int j = tid;
            u64 dr = pk(0.0f, 0.0f), dz = pk(0.0f, 0.0f), dn = pk(0.0f, 0.0f);
            unsigned qsa = sptr(qs);
            const float* wr = qy_Wih + (size_t)j * Hn;
            const float* wz = qy_Wih + (size_t)(Hn + j) * Hn;
            const float* wn = qy_Wih + (size_t)(2 * Hn + j) * Hn;
            #pragma unroll 4
            for (int ii = 0; ii < 64; ii++) {
                u64 x01, x23, w01, w23;
                lds2(x01, x23, qsa + (ii << 4));
                ldg2(w01, w23, wr + (ii << 2));
                ffma2(dr, w01, x01); ffma2(dr, w23, x23);
                ldg2(w01, w23, wz + (ii << 2));
                ffma2(dz, w01, x01); ffma2(dz, w23, x23);
                ldg2(w01, w23, wn + (ii << 2));
                ffma2(dn, w01, x01); ffma2(dn, w23, x23);
            }
            float r = sigm(uns(dr) + __ldg(&qy_bih[j]) + __ldg(&qy_bhh[j]));
            float z = sigm(uns(dz) + __ldg(&qy_bih[Hn + j]) + __ldg(&qy_bhh[Hn + j]));
            float n = tanhf(uns(dn) + __ldg(&qy_bih[2 * Hn + j]) + r * __ldg(&qy_bhh[2 * Hn + j]));
            out[q * Hn + j] = (1.0f - z) * n;
        }
    }
}

extern "C" void kernel_launch(void* const* d_in, const int* in_sizes, int n_in,
                              void* d_out, int out_size) {
    const int*   q_tok    = (const int*)d_in[0];
    const int*   p_tok    = (const int*)d_in[1];
    const int*   n_tok    = (const int*)d_in[2];
    const float* term_emb = (const float*)d_in[3];
    const float* term_Wih = (const float*)d_in[4];
    const float* term_Whh = (const float*)d_in[5];
    const float* term_bih = (const float*)d_in[6];
    const float* term_bhh = (const float*)d_in[7];
    const float* doc_emb  = (const float*)d_in[8];
    const float* dc_Wih   = (const float*)d_in[9];
    const float* dc_Whh   = (const float*)d_in[10];
    const float* dc_bih   = (const float*)d_in[11];
    const float* dc_bhh   = (const float*)d_in[12];
    const float* da_Wih   = (const float*)d_in[13];
    const float* da_Whh   = (const float*)d_in[14];
    const float* da_bih   = (const float*)d_in[15];
    const float* da_bhh   = (const float*)d_in[16];
    const float* pos_tab  = (const float*)d_in[17];
    const float* posd_W   = (const float*)d_in[18];
    const float* posd_b   = (const float*)d_in[19];
    const float* qy_Wih   = (const float*)d_in[20];
    const float* qy_Whh   = (const float*)d_in[21];
    const float* qy_bih   = (const float*)d_in[22];
    const float* qy_bhh   = (const float*)d_in[23];
    float* out = (float*)d_out;

    const int dyn_bytes = 64 * HSTR * 4;
    cudaFuncSetAttribute(fmn_kernel, cudaFuncAttributeMaxDynamicSharedMemorySize, dyn_bytes);
    fmn_kernel<<<NBLK, NTHR, dyn_bytes>>>(q_tok, p_tok, n_tok,
                            term_emb, term_Wih, term_Whh, term_bih, term_bhh,
                            doc_emb, dc_Wih, dc_Whh, dc_bih, dc_bhh,
                            da_Wih, da_Whh, da_bih, da_bhh,
                            pos_tab, posd_W, posd_b,
                            qy_Wih, qy_Whh, qy_bih, qy_bhh,
                            out);
}